// round 3
// baseline (speedup 1.0000x reference)
#include <cuda_runtime.h>
#include <math.h>

// ---------------------------------------------------------------------------
// Problem constants
// ---------------------------------------------------------------------------
#define BATCH 2
#define SEQ   2048
#define DMODEL 1024
#define NHEAD 16
#define HDIM  64
#define THD   (NHEAD * HDIM)          // 1024
#define MROWS (BATCH * SEQ)           // 4096
#define QK_COLS (2 * THD)             // 2048
#define GN_EPS 1e-5f

// ---------------------------------------------------------------------------
// Scratch (device globals; no allocations allowed)
// ---------------------------------------------------------------------------
__device__ float g_Q[MROWS * QK_COLS];     // 4096 x 2048
__device__ float g_K[MROWS * QK_COLS];     // 4096 x 2048
__device__ float g_V[MROWS * THD];         // 4096 x 1024
__device__ float g_Vt[BATCH * NHEAD * HDIM * SEQ];   // [bh][d][s]
__device__ float g_AttO[MROWS * THD];      // 4096 x 1024 (post-GN attention out)
__device__ float g_cosT[SEQ * 32];
__device__ float g_sinT[SEQ * 32];

// ---------------------------------------------------------------------------
// Helpers
// ---------------------------------------------------------------------------
__device__ __forceinline__ unsigned f2tf(float x) {
    unsigned u;
    asm("cvt.rna.tf32.f32 %0, %1;" : "=r"(u) : "f"(x));
    return u;
}

__device__ __forceinline__ void ldsm4(unsigned &r0, unsigned &r1, unsigned &r2, unsigned &r3, unsigned addr) {
    asm volatile("ldmatrix.sync.aligned.m8n8.x4.shared.b16 {%0,%1,%2,%3}, [%4];"
        : "=r"(r0), "=r"(r1), "=r"(r2), "=r"(r3) : "r"(addr));
}

__device__ __forceinline__ void mma8(float* c, const unsigned* a, unsigned b0, unsigned b1) {
    asm volatile(
        "mma.sync.aligned.m16n8k8.row.col.f32.tf32.tf32.f32 "
        "{%0,%1,%2,%3},{%4,%5,%6,%7},{%8,%9},{%0,%1,%2,%3};"
        : "+f"(c[0]), "+f"(c[1]), "+f"(c[2]), "+f"(c[3])
        : "r"(a[0]), "r"(a[1]), "r"(a[2]), "r"(a[3]), "r"(b0), "r"(b1));
}

__device__ __forceinline__ void cp16(unsigned saddr, const void* g) {
    asm volatile("cp.async.cg.shared.global [%0], [%1], 16;" :: "r"(saddr), "l"(g));
}

// ---------------------------------------------------------------------------
// RoPE tables
// ---------------------------------------------------------------------------
__global__ void rope_tables_kernel(float* __restrict__ cosT, float* __restrict__ sinT) {
    int i = blockIdx.x * blockDim.x + threadIdx.x;
    if (i >= SEQ * 32) return;
    int t = i >> 5;
    int j = i & 31;
    double invf = pow(10000.0, -(double)(2 * j) / 64.0);
    float f = (float)t * (float)invf;
    cosT[i] = (float)cos((double)f);
    sinT[i] = (float)sin((double)f);
}

// ---------------------------------------------------------------------------
// In-place RoPE on Q and K; rounds results to tf32 (rna) for unbiased HMMA.
// ---------------------------------------------------------------------------
__global__ void rope_kernel(float* __restrict__ Q, float* __restrict__ K,
                            const float* __restrict__ cosT, const float* __restrict__ sinT) {
    int idx = blockIdx.x * blockDim.x + threadIdx.x;
    if (idx >= MROWS * 1024) return;
    int m  = idx >> 10;
    int p  = idx & 1023;
    int ch = p >> 5;
    int dl = p & 31;
    int s  = m & (SEQ - 1);
    float c  = cosT[s * 32 + dl];
    float sn = sinT[s * 32 + dl];
    int base = m * QK_COLS + ch * HDIM + dl;
    float qlo = Q[base], qhi = Q[base + 32];
    Q[base]      = __uint_as_float(f2tf(qlo * c - qhi * sn));
    Q[base + 32] = __uint_as_float(f2tf(qhi * c + qlo * sn));
    float klo = K[base], khi = K[base + 32];
    K[base]      = __uint_as_float(f2tf(klo * c - khi * sn));
    K[base + 32] = __uint_as_float(f2tf(khi * c + klo * sn));
}

// ---------------------------------------------------------------------------
// V transpose: g_V [b*S+s][h*64+d] -> g_Vt [(b*16+h)*64+d][s], tf32-rounded.
// ---------------------------------------------------------------------------
__global__ void vtrans_kernel(const float* __restrict__ V, float* __restrict__ Vt) {
    __shared__ float t[32][33];
    int bh = blockIdx.z;
    int b = bh >> 4, h = bh & 15;
    int s0 = blockIdx.x * 32, d0 = blockIdx.y * 32;
    int tx = threadIdx.x, ty = threadIdx.y;
#pragma unroll
    for (int j = 0; j < 32; j += 8)
        t[ty + j][tx] = V[(size_t)(b * SEQ + s0 + ty + j) * THD + h * HDIM + d0 + tx];
    __syncthreads();
#pragma unroll
    for (int j = 0; j < 32; j += 8)
        Vt[(size_t)(bh * HDIM + d0 + ty + j) * SEQ + s0 + tx] =
            __uint_as_float(f2tf(t[tx][ty + j]));
}

// ---------------------------------------------------------------------------
// SGEMM: C[M,N] = A[M,K] * B[K,N] (fp32 FFMA path, unchanged)
// ---------------------------------------------------------------------------
__global__ __launch_bounds__(256) void sgemm_kernel(
    const float* __restrict__ A, const float* __restrict__ B, float* __restrict__ C,
    int M, int N, int K)
{
    __shared__ float As[16][132];
    __shared__ float Bs[16][132];

    const int tid = threadIdx.x;
    const int tx = tid & 15;
    const int ty = tid >> 4;
    const int bx = blockIdx.x;
    const int by = blockIdx.y;

    float acc[8][8];
#pragma unroll
    for (int i = 0; i < 8; i++)
#pragma unroll
        for (int j = 0; j < 8; j++) acc[i][j] = 0.f;

    const int nTiles = K >> 4;
    for (int kt = 0; kt < nTiles; kt++) {
#pragma unroll
        for (int q = 0; q < 2; q++) {
            int fi = tid + q * 256;
            int ar = fi >> 2;
            int ac4 = fi & 3;
            float4 av = *(const float4*)&A[(size_t)(by * 128 + ar) * K + kt * 16 + ac4 * 4];
            As[ac4 * 4 + 0][ar] = av.x;
            As[ac4 * 4 + 1][ar] = av.y;
            As[ac4 * 4 + 2][ar] = av.z;
            As[ac4 * 4 + 3][ar] = av.w;
        }
#pragma unroll
        for (int q = 0; q < 2; q++) {
            int fi = tid + q * 256;
            int br = fi >> 5;
            int bc4 = fi & 31;
            float4 bv = *(const float4*)&B[(size_t)(kt * 16 + br) * N + bx * 128 + bc4 * 4];
            *(float4*)&Bs[br][bc4 * 4] = bv;
        }
        __syncthreads();

#pragma unroll
        for (int kk = 0; kk < 16; kk++) {
            float a[8], b[8];
            float4 a0 = *(float4*)&As[kk][ty * 8];
            float4 a1 = *(float4*)&As[kk][ty * 8 + 4];
            float4 b0 = *(float4*)&Bs[kk][tx * 8];
            float4 b1 = *(float4*)&Bs[kk][tx * 8 + 4];
            a[0]=a0.x; a[1]=a0.y; a[2]=a0.z; a[3]=a0.w; a[4]=a1.x; a[5]=a1.y; a[6]=a1.z; a[7]=a1.w;
            b[0]=b0.x; b[1]=b0.y; b[2]=b0.z; b[3]=b0.w; b[4]=b1.x; b[5]=b1.y; b[6]=b1.z; b[7]=b1.w;
#pragma unroll
            for (int i = 0; i < 8; i++)
#pragma unroll
                for (int j = 0; j < 8; j++) acc[i][j] = fmaf(a[i], b[j], acc[i][j]);
        }
        __syncthreads();
    }

#pragma unroll
    for (int i = 0; i < 8; i++) {
        size_t row = (size_t)(by * 128 + ty * 8 + i);
        float4 c0 = make_float4(acc[i][0], acc[i][1], acc[i][2], acc[i][3]);
        float4 c1 = make_float4(acc[i][4], acc[i][5], acc[i][6], acc[i][7]);
        *(float4*)&C[row * N + bx * 128 + tx * 8]     = c0;
        *(float4*)&C[row * N + bx * 128 + tx * 8 + 4] = c1;
    }
}

// ---------------------------------------------------------------------------
// Tensor-core differential flash attention + fused group-norm epilogue.
// Grid: (S/64, B*H). Block: 128 threads (4 warps x 16 q rows).
// mma.sync m16n8k8 tf32 for both QK^T and PV; P round-trips via smem.
// ---------------------------------------------------------------------------
#define ATS 68
#define ATT_SMEM (6 * 64 * ATS * 4)

__global__ __launch_bounds__(128) void attn_tc_kernel(
    const float* __restrict__ Q, const float* __restrict__ K, const float* __restrict__ Vt,
    const float* __restrict__ lq1, const float* __restrict__ lk1,
    const float* __restrict__ lq2, const float* __restrict__ lk2,
    const float* __restrict__ lam_init_p,
    const float* __restrict__ gnw, const float* __restrict__ gnb,
    float* __restrict__ Out)
{
    extern __shared__ float sm[];
    float* Q1s = sm;
    float* Q2s = Q1s + 64 * ATS;
    float* K1s = Q2s + 64 * ATS;
    float* K2s = K1s + 64 * ATS;
    float* Vts = K2s + 64 * ATS;
    float* Ps  = Vts + 64 * ATS;

    const int tid = threadIdx.x;
    const int wid = tid >> 5;
    const int lane = tid & 31;
    const int g = lane >> 2;
    const int tig = lane & 3;
    const int bh = blockIdx.y;
    const int b = bh >> 4;
    const int h = bh & 15;
    const int q0 = blockIdx.x * 64;
    const int rowg0 = b * SEQ;
    const float scale = 0.125f;

    const unsigned smQ1 = (unsigned)__cvta_generic_to_shared(Q1s);
    const unsigned smQ2 = (unsigned)__cvta_generic_to_shared(Q2s);
    const unsigned smK1 = (unsigned)__cvta_generic_to_shared(K1s);
    const unsigned smK2 = (unsigned)__cvta_generic_to_shared(K2s);
    const unsigned smVt = (unsigned)__cvta_generic_to_shared(Vts);
    const unsigned smPs = (unsigned)__cvta_generic_to_shared(Ps);

    // async Q tile loads (64 rows x 64 cols, both components)
#pragma unroll
    for (int q = 0; q < 8; q++) {
        int fi = tid + q * 128;
        int r = fi >> 4, c4 = fi & 15;
        const float* gq = &Q[(size_t)(rowg0 + q0 + r) * QK_COLS + h * HDIM + c4 * 4];
        cp16(smQ1 + (r * ATS + c4 * 4) * 4, gq);
        cp16(smQ2 + (r * ATS + c4 * 4) * 4, gq + THD);
    }
    asm volatile("cp.async.commit_group;");

    float O1[8][4], O2[8][4];
#pragma unroll
    for (int i = 0; i < 8; i++)
#pragma unroll
        for (int j = 0; j < 4; j++) { O1[i][j] = 0.f; O2[i][j] = 0.f; }
    float m1[2] = {-1e30f, -1e30f}, m2[2] = {-1e30f, -1e30f};
    float l1[2] = {0.f, 0.f},       l2[2] = {0.f, 0.f};

    // per-lane ldmatrix base addresses (bytes)
    const unsigned aoffA = ((wid * 16 + (lane & 15)) * ATS + ((lane >> 4) << 2)) * 4;
    const unsigned aQ1 = smQ1 + aoffA;
    const unsigned aQ2 = smQ2 + aoffA;
    const unsigned aPs = smPs + aoffA;
    const unsigned boffB = ((lane & 7) * ATS + ((lane >> 3) << 2)) * 4;
    const unsigned bK1 = smK1 + boffB;
    const unsigned bK2 = smK2 + boffB;
    const unsigned bVt = smVt + boffB;

    for (int kt = 0; kt < SEQ / 64; kt++) {
        const int k0 = kt * 64;
        __syncthreads();   // previous tile fully consumed
#pragma unroll
        for (int q = 0; q < 8; q++) {
            int fi = tid + q * 128;
            int r = fi >> 4, c4 = fi & 15;
            const float* gk = &K[(size_t)(rowg0 + k0 + r) * QK_COLS + h * HDIM + c4 * 4];
            cp16(smK1 + (r * ATS + c4 * 4) * 4, gk);
            cp16(smK2 + (r * ATS + c4 * 4) * 4, gk + THD);
            const float* gv = &Vt[(size_t)(bh * HDIM + r) * SEQ + k0 + c4 * 4];
            cp16(smVt + (r * ATS + c4 * 4) * 4, gv);
        }
        asm volatile("cp.async.commit_group;");
        asm volatile("cp.async.wait_group 0;");
        __syncthreads();

#pragma unroll
        for (int br = 0; br < 2; br++) {
            const unsigned aQ = br ? aQ2 : aQ1;
            const unsigned bK = br ? bK2 : bK1;
            float (*O)[4] = br ? O2 : O1;
            float* mm = br ? m2 : m1;
            float* ll = br ? l2 : l1;

            float S[8][4];
#pragma unroll
            for (int i = 0; i < 8; i++)
#pragma unroll
                for (int j = 0; j < 4; j++) S[i][j] = 0.f;

            // S = Q_w (16x64) @ K^T (64x64)
#pragma unroll
            for (int p = 0; p < 4; p++) {
                unsigned A0[4], A1[4];
                ldsm4(A0[0], A0[1], A0[2], A0[3], aQ + p * 64);
                ldsm4(A1[0], A1[1], A1[2], A1[3], aQ + p * 64 + 32);
#pragma unroll
                for (int nf = 0; nf < 8; nf++) {
                    unsigned Bf[4];
                    ldsm4(Bf[0], Bf[1], Bf[2], Bf[3], bK + nf * (8 * ATS * 4) + p * 64);
                    mma8(S[nf], A0, Bf[0], Bf[1]);
                    mma8(S[nf], A1, Bf[2], Bf[3]);
                }
            }

            // online softmax (rows g and g+8 of this warp's 16-row block)
            float mx0 = -1e30f, mx1 = -1e30f;
#pragma unroll
            for (int nf = 0; nf < 8; nf++) {
                mx0 = fmaxf(mx0, fmaxf(S[nf][0], S[nf][1]));
                mx1 = fmaxf(mx1, fmaxf(S[nf][2], S[nf][3]));
            }
            mx0 = fmaxf(mx0, __shfl_xor_sync(0xffffffffu, mx0, 1));
            mx0 = fmaxf(mx0, __shfl_xor_sync(0xffffffffu, mx0, 2));
            mx1 = fmaxf(mx1, __shfl_xor_sync(0xffffffffu, mx1, 1));
            mx1 = fmaxf(mx1, __shfl_xor_sync(0xffffffffu, mx1, 2));
            float mn0 = fmaxf(mm[0], mx0 * scale);
            float mn1 = fmaxf(mm[1], mx1 * scale);
            float c0 = __expf(mm[0] - mn0);
            float c1 = __expf(mm[1] - mn1);
            float s0 = 0.f, s1 = 0.f;
            const int prow0 = (wid * 16 + g) * ATS + 2 * tig;
#pragma unroll
            for (int nf = 0; nf < 8; nf++) {
                float p00 = __expf(S[nf][0] * scale - mn0);
                float p01 = __expf(S[nf][1] * scale - mn0);
                float p10 = __expf(S[nf][2] * scale - mn1);
                float p11 = __expf(S[nf][3] * scale - mn1);
                s0 += p00 + p01;
                s1 += p10 + p11;
                float2 v0 = make_float2(__uint_as_float(f2tf(p00)), __uint_as_float(f2tf(p01)));
                float2 v1 = make_float2(__uint_as_float(f2tf(p10)), __uint_as_float(f2tf(p11)));
                *(float2*)&Ps[prow0 + nf * 8] = v0;
                *(float2*)&Ps[prow0 + 8 * ATS + nf * 8] = v1;
            }
            s0 += __shfl_xor_sync(0xffffffffu, s0, 1);
            s0 += __shfl_xor_sync(0xffffffffu, s0, 2);
            s1 += __shfl_xor_sync(0xffffffffu, s1, 1);
            s1 += __shfl_xor_sync(0xffffffffu, s1, 2);
            ll[0] = ll[0] * c0 + s0;
            ll[1] = ll[1] * c1 + s1;
            mm[0] = mn0;
            mm[1] = mn1;
#pragma unroll
            for (int nf = 0; nf < 8; nf++) {
                O[nf][0] *= c0; O[nf][1] *= c0;
                O[nf][2] *= c1; O[nf][3] *= c1;
            }
            __syncwarp();

            // O += P (16x64) @ V (64x64)
#pragma unroll
            for (int p = 0; p < 4; p++) {
                unsigned A0[4], A1[4];
                ldsm4(A0[0], A0[1], A0[2], A0[3], aPs + p * 64);
                ldsm4(A1[0], A1[1], A1[2], A1[3], aPs + p * 64 + 32);
#pragma unroll
                for (int df = 0; df < 8; df++) {
                    unsigned Bf[4];
                    ldsm4(Bf[0], Bf[1], Bf[2], Bf[3], bVt + df * (8 * ATS * 4) + p * 64);
                    mma8(O[df], A0, Bf[0], Bf[1]);
                    mma8(O[df], A1, Bf[2], Bf[3]);
                }
            }
            __syncwarp();   // Ps consumed; next branch may overwrite
        }
    }

    // ======= epilogue: diff + group-norm + scale =======
    const float lam_init = lam_init_p[0];
    const float lam = __expf(lq1[h] * lk1[h]) - __expf(lq2[h] * lk2[h]) + lam_init;
    const float osc = 1.0f - lam_init;

#pragma unroll
    for (int r = 0; r < 2; r++) {
        float inv1 = 1.0f / l1[r];
        float inv2 = lam / l2[r];
        float v[16];
        float s = 0.f, sq = 0.f;
#pragma unroll
        for (int nf = 0; nf < 8; nf++) {
            float a0 = O1[nf][2 * r + 0] * inv1 - O2[nf][2 * r + 0] * inv2;
            float a1 = O1[nf][2 * r + 1] * inv1 - O2[nf][2 * r + 1] * inv2;
            v[2 * nf] = a0; v[2 * nf + 1] = a1;
            s += a0 + a1;
            sq += a0 * a0 + a1 * a1;
        }
        s  += __shfl_xor_sync(0xffffffffu, s, 1);
        s  += __shfl_xor_sync(0xffffffffu, s, 2);
        sq += __shfl_xor_sync(0xffffffffu, sq, 1);
        sq += __shfl_xor_sync(0xffffffffu, sq, 2);
        float mean = s * (1.0f / 64.0f);
        float var = sq * (1.0f / 64.0f) - mean * mean;
        float istd = rsqrtf(var + GN_EPS);
        size_t row = (size_t)(rowg0 + q0 + wid * 16 + g + 8 * r);
#pragma unroll
        for (int nf = 0; nf < 8; nf++) {
            int col = h * HDIM + nf * 8 + 2 * tig;
            float gw0 = gnw[col], gw1 = gnw[col + 1];
            float gb0 = gnb[col], gb1 = gnb[col + 1];
            float2 o = make_float2(((v[2 * nf]     - mean) * istd * gw0 + gb0) * osc,
                                   ((v[2 * nf + 1] - mean) * istd * gw1 + gb1) * osc);
            *(float2*)&Out[row * THD + col] = o;
        }
    }
}

// ---------------------------------------------------------------------------
// kernel_launch
// ---------------------------------------------------------------------------
extern "C" void kernel_launch(void* const* d_in, const int* in_sizes, int n_in,
                              void* d_out, int out_size)
{
    const float* x   = (const float*)d_in[0];
    const float* Wq  = (const float*)d_in[1];
    const float* Wk  = (const float*)d_in[2];
    const float* Wv  = (const float*)d_in[3];
    const float* Wo  = (const float*)d_in[4];
    const float* lq1 = (const float*)d_in[5];
    const float* lk1 = (const float*)d_in[6];
    const float* lq2 = (const float*)d_in[7];
    const float* lk2 = (const float*)d_in[8];
    const float* lam = (const float*)d_in[9];
    const float* gnw = (const float*)d_in[10];
    const float* gnb = (const float*)d_in[11];
    float* out = (float*)d_out;

    float *Q, *K, *V, *Vt, *A, *cosT, *sinT;
    cudaGetSymbolAddress((void**)&Q, g_Q);
    cudaGetSymbolAddress((void**)&K, g_K);
    cudaGetSymbolAddress((void**)&V, g_V);
    cudaGetSymbolAddress((void**)&Vt, g_Vt);
    cudaGetSymbolAddress((void**)&A, g_AttO);
    cudaGetSymbolAddress((void**)&cosT, g_cosT);
    cudaGetSymbolAddress((void**)&sinT, g_sinT);

    cudaFuncSetAttribute(attn_tc_kernel, cudaFuncAttributeMaxDynamicSharedMemorySize, ATT_SMEM);

    // RoPE tables
    rope_tables_kernel<<<(SEQ * 32 + 255) / 256, 256>>>(cosT, sinT);

    // Projections (fp32)
    sgemm_kernel<<<dim3(QK_COLS / 128, MROWS / 128), 256>>>(x, Wq, Q, MROWS, QK_COLS, DMODEL);
    sgemm_kernel<<<dim3(QK_COLS / 128, MROWS / 128), 256>>>(x, Wk, K, MROWS, QK_COLS, DMODEL);
    sgemm_kernel<<<dim3(THD / 128, MROWS / 128), 256>>>(x, Wv, V, MROWS, THD, DMODEL);

    // RoPE (in place, tf32-rounded outputs)
    rope_kernel<<<(MROWS * 1024) / 256, 256>>>(Q, K, cosT, sinT);

    // V transpose -> [bh][d][s], tf32-rounded
    vtrans_kernel<<<dim3(SEQ / 32, HDIM / 32, BATCH * NHEAD), dim3(32, 8)>>>(V, Vt);

    // Tensor-core differential attention + GN
    attn_tc_kernel<<<dim3(SEQ / 64, BATCH * NHEAD), 128, ATT_SMEM>>>(
        Q, K, Vt, lq1, lk1, lq2, lk2, lam, gnw, gnb, A);

    // Output projection (fp32)
    sgemm_kernel<<<dim3(DMODEL / 128, MROWS / 128), 256>>>(A, Wo, out, MROWS, DMODEL, DMODEL);
}

// round 4
// speedup vs baseline: 1.8295x; 1.8295x over previous
#include <cuda_runtime.h>
#include <cuda_bf16.h>
#include <math.h>

#define BATCH 2
#define SEQ   2048
#define DMODEL 1024
#define NHEAD 16
#define HDIM  64
#define THD   (NHEAD * HDIM)
#define MROWS (BATCH * SEQ)
#define QK_COLS (2 * THD)
#define GN_EPS 1e-5f

// ---------------- scratch ----------------
__device__ float g_Q[MROWS * QK_COLS];
__device__ float g_K[MROWS * QK_COLS];
__device__ float g_V[MROWS * THD];
__device__ float g_Vt[BATCH * NHEAD * HDIM * SEQ];
__device__ float g_cosT[SEQ * 32];
__device__ float g_sinT[SEQ * 32];
__device__ __nv_bfloat16 g_xh[MROWS * DMODEL],  g_xl[MROWS * DMODEL];
__device__ __nv_bfloat16 g_Wqh[DMODEL * QK_COLS], g_Wql[DMODEL * QK_COLS];
__device__ __nv_bfloat16 g_Wkh[DMODEL * QK_COLS], g_Wkl[DMODEL * QK_COLS];
__device__ __nv_bfloat16 g_Wvh[DMODEL * THD],   g_Wvl[DMODEL * THD];
__device__ __nv_bfloat16 g_Woh[THD * DMODEL],   g_Wol[THD * DMODEL];
__device__ __nv_bfloat16 g_Ah[MROWS * THD],     g_Al[MROWS * THD];

// ---------------- helpers ----------------
__device__ __forceinline__ unsigned f2tf(float x) {
    unsigned u; asm("cvt.rna.tf32.f32 %0, %1;" : "=r"(u) : "f"(x)); return u;
}
__device__ __forceinline__ void ldsm4(unsigned &r0, unsigned &r1, unsigned &r2, unsigned &r3, unsigned a) {
    asm volatile("ldmatrix.sync.aligned.m8n8.x4.shared.b16 {%0,%1,%2,%3}, [%4];"
        : "=r"(r0), "=r"(r1), "=r"(r2), "=r"(r3) : "r"(a));
}
__device__ __forceinline__ void ldsmT4(unsigned &r0, unsigned &r1, unsigned &r2, unsigned &r3, unsigned a) {
    asm volatile("ldmatrix.sync.aligned.m8n8.x4.trans.shared.b16 {%0,%1,%2,%3}, [%4];"
        : "=r"(r0), "=r"(r1), "=r"(r2), "=r"(r3) : "r"(a));
}
__device__ __forceinline__ void mma8(float* c, const unsigned* a, unsigned b0, unsigned b1) {
    asm volatile("mma.sync.aligned.m16n8k8.row.col.f32.tf32.tf32.f32 "
        "{%0,%1,%2,%3},{%4,%5,%6,%7},{%8,%9},{%0,%1,%2,%3};"
        : "+f"(c[0]), "+f"(c[1]), "+f"(c[2]), "+f"(c[3])
        : "r"(a[0]), "r"(a[1]), "r"(a[2]), "r"(a[3]), "r"(b0), "r"(b1));
}
__device__ __forceinline__ void mma16(float* c, const unsigned* a, unsigned b0, unsigned b1) {
    asm volatile("mma.sync.aligned.m16n8k16.row.col.f32.bf16.bf16.f32 "
        "{%0,%1,%2,%3},{%4,%5,%6,%7},{%8,%9},{%0,%1,%2,%3};"
        : "+f"(c[0]), "+f"(c[1]), "+f"(c[2]), "+f"(c[3])
        : "r"(a[0]), "r"(a[1]), "r"(a[2]), "r"(a[3]), "r"(b0), "r"(b1));
}
__device__ __forceinline__ void cp16(unsigned s, const void* g) {
    asm volatile("cp.async.cg.shared.global [%0], [%1], 16;" :: "r"(s), "l"(g));
}
__device__ __forceinline__ void cpcommit() { asm volatile("cp.async.commit_group;"); }

// ---------------- small kernels ----------------
__global__ void conv_split_kernel(const float* __restrict__ s, __nv_bfloat16* __restrict__ h,
                                  __nv_bfloat16* __restrict__ l, int n) {
    int i = blockIdx.x * blockDim.x + threadIdx.x;
    if (i >= n) return;
    float v = s[i];
    __nv_bfloat16 hv = __float2bfloat16_rn(v);
    h[i] = hv;
    l[i] = __float2bfloat16_rn(v - __bfloat162float(hv));
}

__global__ void rope_tables_kernel(float* __restrict__ cosT, float* __restrict__ sinT) {
    int i = blockIdx.x * blockDim.x + threadIdx.x;
    if (i >= SEQ * 32) return;
    int t = i >> 5, j = i & 31;
    double invf = pow(10000.0, -(double)(2 * j) / 64.0);
    float f = (float)t * (float)invf;
    cosT[i] = (float)cos((double)f);
    sinT[i] = (float)sin((double)f);
}

__global__ void rope_kernel(float* __restrict__ Q, float* __restrict__ K,
                            const float* __restrict__ cosT, const float* __restrict__ sinT) {
    int idx = blockIdx.x * blockDim.x + threadIdx.x;
    if (idx >= MROWS * 1024) return;
    int m = idx >> 10, p = idx & 1023;
    int ch = p >> 5, dl = p & 31;
    int s = m & (SEQ - 1);
    float c = cosT[s * 32 + dl], sn = sinT[s * 32 + dl];
    int base = m * QK_COLS + ch * HDIM + dl;
    float qlo = Q[base], qhi = Q[base + 32];
    Q[base]      = __uint_as_float(f2tf(qlo * c - qhi * sn));
    Q[base + 32] = __uint_as_float(f2tf(qhi * c + qlo * sn));
    float klo = K[base], khi = K[base + 32];
    K[base]      = __uint_as_float(f2tf(klo * c - khi * sn));
    K[base + 32] = __uint_as_float(f2tf(khi * c + klo * sn));
}

__global__ void vtrans_kernel(const float* __restrict__ V, float* __restrict__ Vt) {
    __shared__ float t[32][33];
    int bh = blockIdx.z, b = bh >> 4, h = bh & 15;
    int s0 = blockIdx.x * 32, d0 = blockIdx.y * 32;
    int tx = threadIdx.x, ty = threadIdx.y;
#pragma unroll
    for (int j = 0; j < 32; j += 8)
        t[ty + j][tx] = V[(size_t)(b * SEQ + s0 + ty + j) * THD + h * HDIM + d0 + tx];
    __syncthreads();
#pragma unroll
    for (int j = 0; j < 32; j += 8)
        Vt[(size_t)(bh * HDIM + d0 + ty + j) * SEQ + s0 + tx] = __uint_as_float(f2tf(t[tx][ty + j]));
}

// ---------------- bf16x3 tensor-core GEMM ----------------
// C[M,N] f32 = (Ah+Al)[M,K] @ (Bh+Bl)[K,N].  BM=128 BN=128 BK=32, 256 thr.
#define GA_ST 40
#define GB_ST 136
#define O_AH 0
#define O_AL (128 * GA_ST)
#define O_BH (2 * 128 * GA_ST)
#define O_BL (O_BH + 32 * GB_ST)
#define STG_EL (O_BH + 2 * 32 * GB_ST)
#define GEMM_SMEM (2 * STG_EL * 2)

__global__ __launch_bounds__(256) void gemm_bf3_kernel(
    const __nv_bfloat16* __restrict__ Ah, const __nv_bfloat16* __restrict__ Al,
    const __nv_bfloat16* __restrict__ Bh, const __nv_bfloat16* __restrict__ Bl,
    float* __restrict__ C, int M, int N, int K)
{
    extern __shared__ __nv_bfloat16 smb[];
    const unsigned smB = (unsigned)__cvta_generic_to_shared(smb);
    const int tid = threadIdx.x, wid = tid >> 5, lane = tid & 31;
    const int wm = wid & 3, wn = wid >> 2;
    const int g = lane >> 2, t = lane & 3;
    const int bm0 = blockIdx.y * 128, bn0 = blockIdx.x * 128;

    float acc[2][8][4];
#pragma unroll
    for (int i = 0; i < 2; i++)
#pragma unroll
        for (int j = 0; j < 8; j++)
#pragma unroll
            for (int c = 0; c < 4; c++) acc[i][j][c] = 0.f;

    auto load_stage = [&](int kt, int stg) {
        const int k0 = kt * 32;
        const unsigned sb = smB + stg * (STG_EL * 2);
#pragma unroll
        for (int q = 0; q < 4; q++) {
            int fi = tid + q * 256;
            int u = fi >> 9, idx = fi & 511;
            int r = idx >> 2, c = (idx & 3) * 8;
            cp16(sb + ((u ? O_AL : O_AH) + r * GA_ST + c) * 2,
                 (u ? Al : Ah) + (size_t)(bm0 + r) * K + k0 + c);
        }
#pragma unroll
        for (int q = 0; q < 4; q++) {
            int fi = tid + q * 256;
            int u = fi >> 9, idx = fi & 511;
            int r = idx >> 4, c = (idx & 15) * 8;
            cp16(sb + ((u ? O_BL : O_BH) + r * GB_ST + c) * 2,
                 (u ? Bl : Bh) + (size_t)(k0 + r) * N + bn0 + c);
        }
    };
    load_stage(0, 0);
    cpcommit();

    // fragment address components
    const unsigned aoff = ((lane & 15) * GA_ST + (lane >> 4) * 8) * 2;
    const unsigned boff = (((((lane >> 3) & 1) * 8) + (lane & 7)) * GB_ST + (lane >> 4) * 8) * 2;
    const int NT = K >> 5;

    for (int kt = 0; kt < NT; kt++) {
        if (kt + 1 < NT) { load_stage(kt + 1, (kt + 1) & 1); cpcommit();
            asm volatile("cp.async.wait_group 1;"); }
        else { asm volatile("cp.async.wait_group 0;"); }
        __syncthreads();
        const unsigned sb = smB + (kt & 1) * (STG_EL * 2);

#pragma unroll
        for (int ks = 0; ks < 2; ks++) {
            unsigned AH[2][4], AL[2][4];
#pragma unroll
            for (int mf = 0; mf < 2; mf++) {
                unsigned a = sb + (wm * 32 + mf * 16) * GA_ST * 2 + aoff + ks * 32;
                ldsm4(AH[mf][0], AH[mf][1], AH[mf][2], AH[mf][3], a + O_AH * 2);
                ldsm4(AL[mf][0], AL[mf][1], AL[mf][2], AL[mf][3], a + O_AL * 2);
            }
#pragma unroll
            for (int np = 0; np < 4; np++) {
                unsigned bofs = sb + boff + ks * 16 * GB_ST * 2 + (wn * 64 + np * 16) * 2;
                unsigned TH[4], TL[4];
                ldsmT4(TH[0], TH[1], TH[2], TH[3], bofs + O_BH * 2);
                ldsmT4(TL[0], TL[1], TL[2], TL[3], bofs + O_BL * 2);
#pragma unroll
                for (int hh = 0; hh < 2; hh++) {
                    int nf = np * 2 + hh;
#pragma unroll
                    for (int mf = 0; mf < 2; mf++) {
                        mma16(acc[mf][nf], AH[mf], TH[2 * hh], TH[2 * hh + 1]);
                        mma16(acc[mf][nf], AH[mf], TL[2 * hh], TL[2 * hh + 1]);
                        mma16(acc[mf][nf], AL[mf], TH[2 * hh], TH[2 * hh + 1]);
                    }
                }
            }
        }
        __syncthreads();
    }

#pragma unroll
    for (int mf = 0; mf < 2; mf++) {
        size_t r0 = (size_t)(bm0 + wm * 32 + mf * 16 + g);
#pragma unroll
        for (int nf = 0; nf < 8; nf++) {
            int c = bn0 + wn * 64 + nf * 8 + 2 * t;
            *(float2*)&C[r0 * N + c]       = make_float2(acc[mf][nf][0], acc[mf][nf][1]);
            *(float2*)&C[(r0 + 8) * N + c] = make_float2(acc[mf][nf][2], acc[mf][nf][3]);
        }
    }
}

// ---------------- differential flash attention v3 ----------------
// 128-row q tile, 8 warps: warps 0-3 branch1, 4-7 branch2 (same rows).
// tf32 mma; P built via shuffles; K/V double-buffered; GN epilogue -> bf16 hi/lo.
#define ATS 68
#define QBUF (128 * ATS)
#define STG  (64 * ATS)
#define STAGE0 (2 * QBUF)
#define STAGE_STRIDE (3 * STG)
#define ATT_SMEM ((STAGE0 + 2 * STAGE_STRIDE) * 4)
#define NKT (SEQ / 64)

__global__ __launch_bounds__(256) void attn_v3_kernel(
    const float* __restrict__ Q, const float* __restrict__ K, const float* __restrict__ Vt,
    const float* __restrict__ lq1, const float* __restrict__ lk1,
    const float* __restrict__ lq2, const float* __restrict__ lk2,
    const float* __restrict__ lam_init_p,
    const float* __restrict__ gnw, const float* __restrict__ gnb,
    __nv_bfloat16* __restrict__ OutH, __nv_bfloat16* __restrict__ OutL)
{
    extern __shared__ float sm[];
    const unsigned smBase = (unsigned)__cvta_generic_to_shared(sm);
    const int tid = threadIdx.x, wid = tid >> 5, lane = tid & 31;
    const int br = wid >> 2, mblk = wid & 3;
    const int g = lane >> 2, t = lane & 3;
    const int bh = blockIdx.y, b = bh >> 4, h = bh & 15;
    const int q0 = blockIdx.x * 128;
    const int rowg0 = b * SEQ;
    const float scale = 0.125f;
    const int c1base = h * HDIM;

#pragma unroll
    for (int q = 0; q < 8; q++) {
        int fi = tid + q * 256;
        int r = fi >> 4, c4 = fi & 15;
        const float* gq = &Q[(size_t)(rowg0 + q0 + r) * QK_COLS + c1base + c4 * 4];
        cp16(smBase + (r * ATS + c4 * 4) * 4, gq);
        cp16(smBase + (QBUF + r * ATS + c4 * 4) * 4, gq + THD);
    }
    auto load_stage = [&](int kt, int stg) {
        const int k0 = kt * 64;
        const int base = STAGE0 + stg * STAGE_STRIDE;
#pragma unroll
        for (int q = 0; q < 4; q++) {
            int fi = tid + q * 256;
            int r = fi >> 4, c4 = fi & 15;
            const float* gk = &K[(size_t)(rowg0 + k0 + r) * QK_COLS + c1base + c4 * 4];
            cp16(smBase + (base + r * ATS + c4 * 4) * 4, gk);
            cp16(smBase + (base + STG + r * ATS + c4 * 4) * 4, gk + THD);
            cp16(smBase + (base + 2 * STG + r * ATS + c4 * 4) * 4,
                 &Vt[(size_t)(bh * HDIM + r) * SEQ + k0 + c4 * 4]);
        }
    };
    load_stage(0, 0);
    cpcommit();

    const unsigned aoff = ((lane & 15) * ATS + ((lane >> 4) << 2)) * 4;
    const unsigned aQw = smBase + (br ? QBUF * 4 : 0) + (mblk * 32) * ATS * 4 + aoff;
    const unsigned boff = ((lane & 7) * ATS + ((lane >> 3) << 2)) * 4;

    float O[2][8][4];
#pragma unroll
    for (int mf = 0; mf < 2; mf++)
#pragma unroll
        for (int df = 0; df < 8; df++)
#pragma unroll
            for (int c = 0; c < 4; c++) O[mf][df][c] = 0.f;
    float mmx[2][2] = {{-1e30f, -1e30f}, {-1e30f, -1e30f}};
    float lsum[2][2] = {{0.f, 0.f}, {0.f, 0.f}};
    const int src1 = (lane & ~3) | (t >> 1);
    const int src2 = src1 + 2;

    for (int kt = 0; kt < NKT; kt++) {
        if (kt + 1 < NKT) { load_stage(kt + 1, (kt + 1) & 1); cpcommit();
            asm volatile("cp.async.wait_group 1;"); }
        else { asm volatile("cp.async.wait_group 0;"); }
        __syncthreads();

        const unsigned stb = smBase + (STAGE0 + (kt & 1) * STAGE_STRIDE) * 4;
        const unsigned kB = stb + (br ? STG * 4 : 0) + boff;
        const unsigned vB = stb + 2 * STG * 4 + boff;

        float S[2][8][4];
#pragma unroll
        for (int mf = 0; mf < 2; mf++)
#pragma unroll
            for (int nf = 0; nf < 8; nf++)
#pragma unroll
                for (int c = 0; c < 4; c++) S[mf][nf][c] = 0.f;

#pragma unroll
        for (int p = 0; p < 4; p++) {
            unsigned A0[2][4], A1[2][4];
#pragma unroll
            for (int mf = 0; mf < 2; mf++) {
                ldsm4(A0[mf][0], A0[mf][1], A0[mf][2], A0[mf][3], aQw + mf * 16 * ATS * 4 + p * 64);
                ldsm4(A1[mf][0], A1[mf][1], A1[mf][2], A1[mf][3], aQw + mf * 16 * ATS * 4 + p * 64 + 32);
            }
#pragma unroll
            for (int nf = 0; nf < 8; nf++) {
                unsigned Bf[4];
                ldsm4(Bf[0], Bf[1], Bf[2], Bf[3], kB + nf * (8 * ATS * 4) + p * 64);
#pragma unroll
                for (int mf = 0; mf < 2; mf++) {
                    mma8(S[mf][nf], A0[mf], Bf[0], Bf[1]);
                    mma8(S[mf][nf], A1[mf], Bf[2], Bf[3]);
                }
            }
        }

#pragma unroll
        for (int mf = 0; mf < 2; mf++) {
            float mx0 = -1e30f, mx1 = -1e30f;
#pragma unroll
            for (int nf = 0; nf < 8; nf++) {
                mx0 = fmaxf(mx0, fmaxf(S[mf][nf][0], S[mf][nf][1]));
                mx1 = fmaxf(mx1, fmaxf(S[mf][nf][2], S[mf][nf][3]));
            }
            mx0 = fmaxf(mx0, __shfl_xor_sync(0xffffffffu, mx0, 1));
            mx0 = fmaxf(mx0, __shfl_xor_sync(0xffffffffu, mx0, 2));
            mx1 = fmaxf(mx1, __shfl_xor_sync(0xffffffffu, mx1, 1));
            mx1 = fmaxf(mx1, __shfl_xor_sync(0xffffffffu, mx1, 2));
            float mn0 = fmaxf(mmx[mf][0], mx0 * scale);
            float mn1 = fmaxf(mmx[mf][1], mx1 * scale);
            float c0 = __expf(mmx[mf][0] - mn0);
            float c1 = __expf(mmx[mf][1] - mn1);
            float s0 = 0.f, s1 = 0.f;
#pragma unroll
            for (int nf = 0; nf < 8; nf++) {
                float p00 = __expf(S[mf][nf][0] * scale - mn0);
                float p01 = __expf(S[mf][nf][1] * scale - mn0);
                float p10 = __expf(S[mf][nf][2] * scale - mn1);
                float p11 = __expf(S[mf][nf][3] * scale - mn1);
                S[mf][nf][0] = p00; S[mf][nf][1] = p01;
                S[mf][nf][2] = p10; S[mf][nf][3] = p11;
                s0 += p00 + p01; s1 += p10 + p11;
            }
            s0 += __shfl_xor_sync(0xffffffffu, s0, 1);
            s0 += __shfl_xor_sync(0xffffffffu, s0, 2);
            s1 += __shfl_xor_sync(0xffffffffu, s1, 1);
            s1 += __shfl_xor_sync(0xffffffffu, s1, 2);
            lsum[mf][0] = lsum[mf][0] * c0 + s0;
            lsum[mf][1] = lsum[mf][1] * c1 + s1;
            mmx[mf][0] = mn0; mmx[mf][1] = mn1;
#pragma unroll
            for (int df = 0; df < 8; df++) {
                O[mf][df][0] *= c0; O[mf][df][1] *= c0;
                O[mf][df][2] *= c1; O[mf][df][3] *= c1;
            }
        }

#pragma unroll
        for (int p = 0; p < 4; p++) {
            unsigned PA[2][2][4];
#pragma unroll
            for (int mf = 0; mf < 2; mf++)
#pragma unroll
                for (int jj = 0; jj < 2; jj++) {
                    int j = 2 * p + jj;
                    unsigned q0r = f2tf(S[mf][j][0]);
                    unsigned q1r = f2tf(S[mf][j][1]);
                    unsigned q2r = f2tf(S[mf][j][2]);
                    unsigned q3r = f2tf(S[mf][j][3]);
                    unsigned x00 = __shfl_sync(0xffffffffu, q0r, src1);
                    unsigned x01 = __shfl_sync(0xffffffffu, q1r, src1);
                    unsigned x20 = __shfl_sync(0xffffffffu, q2r, src1);
                    unsigned x21 = __shfl_sync(0xffffffffu, q3r, src1);
                    unsigned y00 = __shfl_sync(0xffffffffu, q0r, src2);
                    unsigned y01 = __shfl_sync(0xffffffffu, q1r, src2);
                    unsigned y20 = __shfl_sync(0xffffffffu, q2r, src2);
                    unsigned y21 = __shfl_sync(0xffffffffu, q3r, src2);
                    PA[mf][jj][0] = (t & 1) ? x01 : x00;
                    PA[mf][jj][1] = (t & 1) ? x21 : x20;
                    PA[mf][jj][2] = (t & 1) ? y01 : y00;
                    PA[mf][jj][3] = (t & 1) ? y21 : y20;
                }
#pragma unroll
            for (int df = 0; df < 8; df++) {
                unsigned Bf[4];
                ldsm4(Bf[0], Bf[1], Bf[2], Bf[3], vB + df * (8 * ATS * 4) + p * 64);
#pragma unroll
                for (int mf = 0; mf < 2; mf++) {
                    mma8(O[mf][df], PA[mf][0], Bf[0], Bf[1]);
                    mma8(O[mf][df], PA[mf][1], Bf[2], Bf[3]);
                }
            }
        }
        __syncthreads();
    }

    // epilogue: branch exchange + diff + GN + bf16 hi/lo out
    const float lam_init = lam_init_p[0];
    const float lam = __expf(lq1[h] * lk1[h]) - __expf(lq2[h] * lk2[h]) + lam_init;
    const float osc = 1.0f - lam_init;
    float* Ex = sm + STAGE0;

    if (br == 1) {
#pragma unroll
        for (int mf = 0; mf < 2; mf++) {
            float inv0 = lam / lsum[mf][0];
            float inv1 = lam / lsum[mf][1];
            int row0 = mblk * 32 + mf * 16 + g;
#pragma unroll
            for (int df = 0; df < 8; df++) {
                int col = df * 8 + 2 * t;
                *(float2*)&Ex[row0 * ATS + col] = make_float2(O[mf][df][0] * inv0, O[mf][df][1] * inv0);
                *(float2*)&Ex[(row0 + 8) * ATS + col] = make_float2(O[mf][df][2] * inv1, O[mf][df][3] * inv1);
            }
        }
    }
    __syncthreads();
    if (br == 0) {
#pragma unroll
        for (int mf = 0; mf < 2; mf++) {
#pragma unroll
            for (int half = 0; half < 2; half++) {
                float inv1 = 1.0f / lsum[mf][half];
                int lrow = mblk * 32 + mf * 16 + g + 8 * half;
                float v[16];
                float s = 0.f, sq = 0.f;
#pragma unroll
                for (int df = 0; df < 8; df++) {
                    float2 e = *(float2*)&Ex[lrow * ATS + df * 8 + 2 * t];
                    float a0 = O[mf][df][half * 2 + 0] * inv1 - e.x;
                    float a1 = O[mf][df][half * 2 + 1] * inv1 - e.y;
                    v[2 * df] = a0; v[2 * df + 1] = a1;
                    s += a0 + a1; sq += a0 * a0 + a1 * a1;
                }
                s  += __shfl_xor_sync(0xffffffffu, s, 1);
                s  += __shfl_xor_sync(0xffffffffu, s, 2);
                sq += __shfl_xor_sync(0xffffffffu, sq, 1);
                sq += __shfl_xor_sync(0xffffffffu, sq, 2);
                float mean = s * (1.0f / 64.0f);
                float var = sq * (1.0f / 64.0f) - mean * mean;
                float istd = rsqrtf(var + GN_EPS);
                size_t grow = (size_t)(rowg0 + q0 + lrow);
#pragma unroll
                for (int df = 0; df < 8; df++) {
                    int col = h * HDIM + df * 8 + 2 * t;
                    float2 gw = *(const float2*)&gnw[col];
                    float2 gb = *(const float2*)&gnb[col];
                    float o0 = ((v[2 * df]     - mean) * istd * gw.x + gb.x) * osc;
                    float o1 = ((v[2 * df + 1] - mean) * istd * gw.y + gb.y) * osc;
                    __nv_bfloat16 h0 = __float2bfloat16_rn(o0);
                    __nv_bfloat16 h1 = __float2bfloat16_rn(o1);
                    __nv_bfloat162 ph; ph.x = h0; ph.y = h1;
                    __nv_bfloat162 pl;
                    pl.x = __float2bfloat16_rn(o0 - __bfloat162float(h0));
                    pl.y = __float2bfloat16_rn(o1 - __bfloat162float(h1));
                    *(__nv_bfloat162*)&OutH[grow * THD + col] = ph;
                    *(__nv_bfloat162*)&OutL[grow * THD + col] = pl;
                }
            }
        }
    }
}

// ---------------- kernel_launch ----------------
extern "C" void kernel_launch(void* const* d_in, const int* in_sizes, int n_in,
                              void* d_out, int out_size)
{
    const float* x   = (const float*)d_in[0];
    const float* Wq  = (const float*)d_in[1];
    const float* Wk  = (const float*)d_in[2];
    const float* Wv  = (const float*)d_in[3];
    const float* Wo  = (const float*)d_in[4];
    const float* lq1 = (const float*)d_in[5];
    const float* lk1 = (const float*)d_in[6];
    const float* lq2 = (const float*)d_in[7];
    const float* lk2 = (const float*)d_in[8];
    const float* lam = (const float*)d_in[9];
    const float* gnw = (const float*)d_in[10];
    const float* gnb = (const float*)d_in[11];
    float* out = (float*)d_out;

    float *Q, *K, *V, *Vt, *cosT, *sinT;
    __nv_bfloat16 *xh, *xl, *Wqh, *Wql, *Wkh, *Wkl, *Wvh, *Wvl, *Woh, *Wol, *Ah, *Al;
    cudaGetSymbolAddress((void**)&Q, g_Q);
    cudaGetSymbolAddress((void**)&K, g_K);
    cudaGetSymbolAddress((void**)&V, g_V);
    cudaGetSymbolAddress((void**)&Vt, g_Vt);
    cudaGetSymbolAddress((void**)&cosT, g_cosT);
    cudaGetSymbolAddress((void**)&sinT, g_sinT);
    cudaGetSymbolAddress((void**)&xh, g_xh);
    cudaGetSymbolAddress((void**)&xl, g_xl);
    cudaGetSymbolAddress((void**)&Wqh, g_Wqh);
    cudaGetSymbolAddress((void**)&Wql, g_Wql);
    cudaGetSymbolAddress((void**)&Wkh, g_Wkh);
    cudaGetSymbolAddress((void**)&Wkl, g_Wkl);
    cudaGetSymbolAddress((void**)&Wvh, g_Wvh);
    cudaGetSymbolAddress((void**)&Wvl, g_Wvl);
    cudaGetSymbolAddress((void**)&Woh, g_Woh);
    cudaGetSymbolAddress((void**)&Wol, g_Wol);
    cudaGetSymbolAddress((void**)&Ah, g_Ah);
    cudaGetSymbolAddress((void**)&Al, g_Al);

    cudaFuncSetAttribute(attn_v3_kernel, cudaFuncAttributeMaxDynamicSharedMemorySize, ATT_SMEM);
    cudaFuncSetAttribute(gemm_bf3_kernel, cudaFuncAttributeMaxDynamicSharedMemorySize, GEMM_SMEM);

    rope_tables_kernel<<<(SEQ * 32 + 255) / 256, 256>>>(cosT, sinT);

    conv_split_kernel<<<(MROWS * DMODEL + 255) / 256, 256>>>(x, xh, xl, MROWS * DMODEL);
    conv_split_kernel<<<(DMODEL * QK_COLS + 255) / 256, 256>>>(Wq, Wqh, Wql, DMODEL * QK_COLS);
    conv_split_kernel<<<(DMODEL * QK_COLS + 255) / 256, 256>>>(Wk, Wkh, Wkl, DMODEL * QK_COLS);
    conv_split_kernel<<<(DMODEL * THD + 255) / 256, 256>>>(Wv, Wvh, Wvl, DMODEL * THD);
    conv_split_kernel<<<(THD * DMODEL + 255) / 256, 256>>>(Wo, Woh, Wol, THD * DMODEL);

    gemm_bf3_kernel<<<dim3(QK_COLS / 128, MROWS / 128), 256, GEMM_SMEM>>>(
        xh, xl, Wqh, Wql, Q, MROWS, QK_COLS, DMODEL);
    gemm_bf3_kernel<<<dim3(QK_COLS / 128, MROWS / 128), 256, GEMM_SMEM>>>(
        xh, xl, Wkh, Wkl, K, MROWS, QK_COLS, DMODEL);
    gemm_bf3_kernel<<<dim3(THD / 128, MROWS / 128), 256, GEMM_SMEM>>>(
        xh, xl, Wvh, Wvl, V, MROWS, THD, DMODEL);

    rope_kernel<<<(MROWS * 1024) / 256, 256>>>(Q, K, cosT, sinT);
    vtrans_kernel<<<dim3(SEQ / 32, HDIM / 32, BATCH * NHEAD), dim3(32, 8)>>>(V, Vt);

    attn_v3_kernel<<<dim3(SEQ / 128, BATCH * NHEAD), 256, ATT_SMEM>>>(
        Q, K, Vt, lq1, lk1, lq2, lk2, lam, gnw, gnb, Ah, Al);

    gemm_bf3_kernel<<<dim3(DMODEL / 128, MROWS / 128), 256, GEMM_SMEM>>>(
        Ah, Al, Woh, Wol, out, MROWS, DMODEL, THD);
}

// round 8
// speedup vs baseline: 2.3903x; 1.3065x over previous
#include <cuda_runtime.h>
#include <cuda_bf16.h>
#include <cuda_fp16.h>
#include <cstdint>
#include <math.h>

#define BATCH 2
#define SEQ   2048
#define DMODEL 1024
#define NHEAD 16
#define HDIM  64
#define THD   (NHEAD * HDIM)
#define MROWS (BATCH * SEQ)
#define QK_COLS (2 * THD)
#define GN_EPS 1e-5f

// ---------------- scratch ----------------
__device__ float g_Q[MROWS * QK_COLS];
__device__ float g_K[MROWS * QK_COLS];
__device__ float g_V[MROWS * THD];
__device__ __half g_Qh[MROWS * QK_COLS];
__device__ __half g_Kh[MROWS * QK_COLS];
__device__ __half g_Vth[BATCH * NHEAD * HDIM * SEQ];   // [bh][d][s]
__device__ float g_cosT[SEQ * 32];
__device__ float g_sinT[SEQ * 32];
__device__ __nv_bfloat16 g_xh[MROWS * DMODEL],  g_xl[MROWS * DMODEL];
__device__ __nv_bfloat16 g_Wqh[DMODEL * QK_COLS], g_Wql[DMODEL * QK_COLS];
__device__ __nv_bfloat16 g_Wkh[DMODEL * QK_COLS], g_Wkl[DMODEL * QK_COLS];
__device__ __nv_bfloat16 g_Wvh[DMODEL * THD],   g_Wvl[DMODEL * THD];
__device__ __nv_bfloat16 g_Woh[THD * DMODEL],   g_Wol[THD * DMODEL];
__device__ __nv_bfloat16 g_Ah[MROWS * THD],     g_Al[MROWS * THD];

// ---------------- helpers ----------------
__device__ __forceinline__ void ldsm4(unsigned &r0, unsigned &r1, unsigned &r2, unsigned &r3, unsigned a) {
    asm volatile("ldmatrix.sync.aligned.m8n8.x4.shared.b16 {%0,%1,%2,%3}, [%4];"
        : "=r"(r0), "=r"(r1), "=r"(r2), "=r"(r3) : "r"(a));
}
__device__ __forceinline__ void ldsmT4(unsigned &r0, unsigned &r1, unsigned &r2, unsigned &r3, unsigned a) {
    asm volatile("ldmatrix.sync.aligned.m8n8.x4.trans.shared.b16 {%0,%1,%2,%3}, [%4];"
        : "=r"(r0), "=r"(r1), "=r"(r2), "=r"(r3) : "r"(a));
}
__device__ __forceinline__ void mma16bf(float* c, const unsigned* a, unsigned b0, unsigned b1) {
    asm volatile("mma.sync.aligned.m16n8k16.row.col.f32.bf16.bf16.f32 "
        "{%0,%1,%2,%3},{%4,%5,%6,%7},{%8,%9},{%0,%1,%2,%3};"
        : "+f"(c[0]), "+f"(c[1]), "+f"(c[2]), "+f"(c[3])
        : "r"(a[0]), "r"(a[1]), "r"(a[2]), "r"(a[3]), "r"(b0), "r"(b1));
}
__device__ __forceinline__ void mma16h(float* c, const unsigned* a, unsigned b0, unsigned b1) {
    asm volatile("mma.sync.aligned.m16n8k16.row.col.f32.f16.f16.f32 "
        "{%0,%1,%2,%3},{%4,%5,%6,%7},{%8,%9},{%0,%1,%2,%3};"
        : "+f"(c[0]), "+f"(c[1]), "+f"(c[2]), "+f"(c[3])
        : "r"(a[0]), "r"(a[1]), "r"(a[2]), "r"(a[3]), "r"(b0), "r"(b1));
}
__device__ __forceinline__ void cp16(unsigned s, const void* g) {
    asm volatile("cp.async.cg.shared.global [%0], [%1], 16;" :: "r"(s), "l"(g));
}
__device__ __forceinline__ void cpcommit() { asm volatile("cp.async.commit_group;"); }
__device__ __forceinline__ unsigned pack2(float a, float b) {
    __half2 h = __floats2half2_rn(a, b);
    return *(unsigned*)&h;
}

// ---------------- small kernels ----------------
__global__ void conv_split_kernel(const float* __restrict__ s, __nv_bfloat16* __restrict__ h,
                                  __nv_bfloat16* __restrict__ l, int n) {
    int i = blockIdx.x * blockDim.x + threadIdx.x;
    if (i >= n) return;
    float v = s[i];
    __nv_bfloat16 hv = __float2bfloat16_rn(v);
    h[i] = hv;
    l[i] = __float2bfloat16_rn(v - __bfloat162float(hv));
}

__global__ void rope_tables_kernel(float* __restrict__ cosT, float* __restrict__ sinT) {
    int i = blockIdx.x * blockDim.x + threadIdx.x;
    if (i >= SEQ * 32) return;
    int t = i >> 5, j = i & 31;
    double invf = pow(10000.0, -(double)(2 * j) / 64.0);
    float f = (float)t * (float)invf;
    cosT[i] = (float)cos((double)f);
    sinT[i] = (float)sin((double)f);
}

// f32 Q,K -> RoPE -> fp16 Qh,Kh
__global__ void rope_kernel(const float* __restrict__ Q, const float* __restrict__ K,
                            __half* __restrict__ Qh, __half* __restrict__ Kh,
                            const float* __restrict__ cosT, const float* __restrict__ sinT) {
    int idx = blockIdx.x * blockDim.x + threadIdx.x;
    if (idx >= MROWS * 1024) return;
    int m = idx >> 10, p = idx & 1023;
    int ch = p >> 5, dl = p & 31;
    int s = m & (SEQ - 1);
    float c = cosT[s * 32 + dl], sn = sinT[s * 32 + dl];
    int base = m * QK_COLS + ch * HDIM + dl;
    float qlo = Q[base], qhi = Q[base + 32];
    Qh[base]      = __float2half_rn(qlo * c - qhi * sn);
    Qh[base + 32] = __float2half_rn(qhi * c + qlo * sn);
    float klo = K[base], khi = K[base + 32];
    Kh[base]      = __float2half_rn(klo * c - khi * sn);
    Kh[base + 32] = __float2half_rn(khi * c + klo * sn);
}

// f32 V -> fp16 Vt [bh][d][s]
__global__ void vtrans_kernel(const float* __restrict__ V, __half* __restrict__ Vt) {
    __shared__ float t[32][33];
    int bh = blockIdx.z, b = bh >> 4, h = bh & 15;
    int s0 = blockIdx.x * 32, d0 = blockIdx.y * 32;
    int tx = threadIdx.x, ty = threadIdx.y;
#pragma unroll
    for (int j = 0; j < 32; j += 8)
        t[ty + j][tx] = V[(size_t)(b * SEQ + s0 + ty + j) * THD + h * HDIM + d0 + tx];
    __syncthreads();
#pragma unroll
    for (int j = 0; j < 32; j += 8)
        Vt[(size_t)(bh * HDIM + d0 + ty + j) * SEQ + s0 + tx] = __float2half_rn(t[tx][ty + j]);
}

// ---------------- bf16x3 mma.sync GEMM (round-4, passing) ----------------
#define GA_ST 40
#define GB_ST 136
#define O_AH 0
#define O_AL (128 * GA_ST)
#define O_BH (2 * 128 * GA_ST)
#define O_BL (O_BH + 32 * GB_ST)
#define STG_EL (O_BH + 2 * 32 * GB_ST)
#define GEMM_SMEM (2 * STG_EL * 2)

__global__ __launch_bounds__(256) void gemm_bf3_kernel(
    const __nv_bfloat16* __restrict__ Ah, const __nv_bfloat16* __restrict__ Al,
    const __nv_bfloat16* __restrict__ Bh, const __nv_bfloat16* __restrict__ Bl,
    float* __restrict__ C, int M, int N, int K)
{
    extern __shared__ __nv_bfloat16 smb[];
    const unsigned smB = (unsigned)__cvta_generic_to_shared(smb);
    const int tid = threadIdx.x, wid = tid >> 5, lane = tid & 31;
    const int wm = wid & 3, wn = wid >> 2;
    const int g = lane >> 2, t = lane & 3;
    const int bm0 = blockIdx.y * 128, bn0 = blockIdx.x * 128;

    float acc[2][8][4];
#pragma unroll
    for (int i = 0; i < 2; i++)
#pragma unroll
        for (int j = 0; j < 8; j++)
#pragma unroll
            for (int c = 0; c < 4; c++) acc[i][j][c] = 0.f;

    auto load_stage = [&](int kt, int stg) {
        const int k0 = kt * 32;
        const unsigned sb = smB + stg * (STG_EL * 2);
#pragma unroll
        for (int q = 0; q < 4; q++) {
            int fi = tid + q * 256;
            int u = fi >> 9, idx = fi & 511;
            int r = idx >> 2, c = (idx & 3) * 8;
            cp16(sb + ((u ? O_AL : O_AH) + r * GA_ST + c) * 2,
                 (u ? Al : Ah) + (size_t)(bm0 + r) * K + k0 + c);
        }
#pragma unroll
        for (int q = 0; q < 4; q++) {
            int fi = tid + q * 256;
            int u = fi >> 9, idx = fi & 511;
            int r = idx >> 4, c = (idx & 15) * 8;
            cp16(sb + ((u ? O_BL : O_BH) + r * GB_ST + c) * 2,
                 (u ? Bl : Bh) + (size_t)(k0 + r) * N + bn0 + c);
        }
    };
    load_stage(0, 0);
    cpcommit();

    const unsigned aoff = ((lane & 15) * GA_ST + (lane >> 4) * 8) * 2;
    const unsigned boff = (((((lane >> 3) & 1) * 8) + (lane & 7)) * GB_ST + (lane >> 4) * 8) * 2;
    const int NT = K >> 5;

    for (int kt = 0; kt < NT; kt++) {
        if (kt + 1 < NT) { load_stage(kt + 1, (kt + 1) & 1); cpcommit();
            asm volatile("cp.async.wait_group 1;"); }
        else { asm volatile("cp.async.wait_group 0;"); }
        __syncthreads();
        const unsigned sb = smB + (kt & 1) * (STG_EL * 2);

#pragma unroll
        for (int ks = 0; ks < 2; ks++) {
            unsigned AH[2][4], AL[2][4];
#pragma unroll
            for (int mf = 0; mf < 2; mf++) {
                unsigned a = sb + (wm * 32 + mf * 16) * GA_ST * 2 + aoff + ks * 32;
                ldsm4(AH[mf][0], AH[mf][1], AH[mf][2], AH[mf][3], a + O_AH * 2);
                ldsm4(AL[mf][0], AL[mf][1], AL[mf][2], AL[mf][3], a + O_AL * 2);
            }
#pragma unroll
            for (int np = 0; np < 4; np++) {
                unsigned bofs = sb + boff + ks * 16 * GB_ST * 2 + (wn * 64 + np * 16) * 2;
                unsigned TH[4], TL[4];
                ldsmT4(TH[0], TH[1], TH[2], TH[3], bofs + O_BH * 2);
                ldsmT4(TL[0], TL[1], TL[2], TL[3], bofs + O_BL * 2);
#pragma unroll
                for (int hh = 0; hh < 2; hh++) {
                    int nf = np * 2 + hh;
#pragma unroll
                    for (int mf = 0; mf < 2; mf++) {
                        mma16bf(acc[mf][nf], AH[mf], TH[2 * hh], TH[2 * hh + 1]);
                        mma16bf(acc[mf][nf], AH[mf], TL[2 * hh], TL[2 * hh + 1]);
                        mma16bf(acc[mf][nf], AL[mf], TH[2 * hh], TH[2 * hh + 1]);
                    }
                }
            }
        }
        __syncthreads();
    }

#pragma unroll
    for (int mf = 0; mf < 2; mf++) {
        size_t r0 = (size_t)(bm0 + wm * 32 + mf * 16 + g);
#pragma unroll
        for (int nf = 0; nf < 8; nf++) {
            int c = bn0 + wn * 64 + nf * 8 + 2 * t;
            *(float2*)&C[r0 * N + c]       = make_float2(acc[mf][nf][0], acc[mf][nf][1]);
            *(float2*)&C[(r0 + 8) * N + c] = make_float2(acc[mf][nf][2], acc[mf][nf][3]);
        }
    }
}

// ---------------- fp16 differential flash attention v4 ----------------
// 128-row q tile, 8 warps: warps 0-3 branch1, 4-7 branch2.
// m16n8k16 fp16 MMA; P C-frag == PV A-frag (no shuffles); 2-stage cp.async.
#define HROW 144                       // bytes per smem row (72 halves)
#define QTILE 9216                     // 64 rows x 144 B
#define ST_STRIDE 27648                // 3 tiles (K1,K2,V) per stage
#define ATT_SMEM (4 * QTILE + 2 * ST_STRIDE)   // 92160 bytes  (Q=4 tiles + 2 stages)
#define NKT (SEQ / 64)

__global__ __launch_bounds__(256) void attn_v4_kernel(
    const __half* __restrict__ Q, const __half* __restrict__ K, const __half* __restrict__ Vt,
    const float* __restrict__ lq1, const float* __restrict__ lk1,
    const float* __restrict__ lq2, const float* __restrict__ lk2,
    const float* __restrict__ lam_init_p,
    const float* __restrict__ gnw, const float* __restrict__ gnb,
    __nv_bfloat16* __restrict__ OutH, __nv_bfloat16* __restrict__ OutL)
{
    extern __shared__ char smv[];
    const unsigned smBase = (unsigned)__cvta_generic_to_shared(smv);
    const int tid = threadIdx.x, wid = tid >> 5, lane = tid & 31;
    const int br = wid >> 2, mblk = wid & 3;
    const int g = lane >> 2, t = lane & 3;
    const int bh = blockIdx.y, b = bh >> 4, h = bh & 15;
    const int q0 = blockIdx.x * 128;
    const int rowg0 = b * SEQ;
    const float scale = 0.125f;
    const int c1base = h * HDIM;

    // prologue: Q1 (128x64 halves) at 0, Q2 at 2*QTILE
#pragma unroll
    for (int q = 0; q < 4; q++) {
        int fi = tid + q * 256;                 // 0..1023
        int r = fi >> 3, c = fi & 7;            // 128 rows x 8 chunks
        const __half* gq = &Q[(size_t)(rowg0 + q0 + r) * QK_COLS + c1base + c * 8];
        cp16(smBase + r * HROW + c * 16, gq);
        cp16(smBase + 2 * QTILE + r * HROW + c * 16, gq + THD);
    }
    auto load_stage = [&](int kt, int stg) {
        const int k0 = kt * 64;
        const unsigned base = smBase + 4 * QTILE + stg * ST_STRIDE;
#pragma unroll
        for (int q = 0; q < 2; q++) {
            int fi = tid + q * 256;             // 0..511
            int r = fi >> 3, c = fi & 7;        // 64 rows x 8 chunks
            const __half* gk = &K[(size_t)(rowg0 + k0 + r) * QK_COLS + c1base + c * 8];
            cp16(base + r * HROW + c * 16, gk);
            cp16(base + QTILE + r * HROW + c * 16, gk + THD);
            cp16(base + 2 * QTILE + r * HROW + c * 16,
                 &Vt[(size_t)(bh * HDIM + r) * SEQ + k0 + c * 8]);
        }
    };
    load_stage(0, 0);
    cpcommit();

    const unsigned aoff = (lane & 15) * HROW + (lane >> 4) * 16;
    const unsigned boff = ((lane & 7) + ((lane >> 4) << 3)) * HROW + ((lane >> 3) & 1) * 16;
    const unsigned aQw = smBase + br * (2 * QTILE) + mblk * 32 * HROW + aoff;

    float O[2][8][4];
#pragma unroll
    for (int mf = 0; mf < 2; mf++)
#pragma unroll
        for (int df = 0; df < 8; df++)
#pragma unroll
            for (int c = 0; c < 4; c++) O[mf][df][c] = 0.f;
    float mmx[2][2] = {{-1e30f, -1e30f}, {-1e30f, -1e30f}};
    float lsum[2][2] = {{0.f, 0.f}, {0.f, 0.f}};

    for (int kt = 0; kt < NKT; kt++) {
        if (kt + 1 < NKT) { load_stage(kt + 1, (kt + 1) & 1); cpcommit();
            asm volatile("cp.async.wait_group 1;"); }
        else { asm volatile("cp.async.wait_group 0;"); }
        __syncthreads();

        const unsigned stb = smBase + 4 * QTILE + (kt & 1) * ST_STRIDE;
        const unsigned kB = stb + br * QTILE + boff;
        const unsigned vB = stb + 2 * QTILE + boff;

        float S[2][8][4];
#pragma unroll
        for (int mf = 0; mf < 2; mf++)
#pragma unroll
            for (int nf = 0; nf < 8; nf++)
#pragma unroll
                for (int c = 0; c < 4; c++) S[mf][nf][c] = 0.f;

        // S = Q (32x64) @ K^T
#pragma unroll
        for (int p = 0; p < 4; p++) {
            unsigned A[2][4];
#pragma unroll
            for (int mf = 0; mf < 2; mf++)
                ldsm4(A[mf][0], A[mf][1], A[mf][2], A[mf][3],
                      aQw + mf * 16 * HROW + p * 32);
#pragma unroll
            for (int nb = 0; nb < 4; nb++) {
                unsigned Bf[4];
                ldsm4(Bf[0], Bf[1], Bf[2], Bf[3], kB + nb * 16 * HROW + p * 32);
#pragma unroll
                for (int mf = 0; mf < 2; mf++) {
                    mma16h(S[mf][2 * nb],     A[mf], Bf[0], Bf[1]);
                    mma16h(S[mf][2 * nb + 1], A[mf], Bf[2], Bf[3]);
                }
            }
        }

        // online softmax
#pragma unroll
        for (int mf = 0; mf < 2; mf++) {
            float mx0 = -1e30f, mx1 = -1e30f;
#pragma unroll
            for (int nf = 0; nf < 8; nf++) {
                mx0 = fmaxf(mx0, fmaxf(S[mf][nf][0], S[mf][nf][1]));
                mx1 = fmaxf(mx1, fmaxf(S[mf][nf][2], S[mf][nf][3]));
            }
            mx0 = fmaxf(mx0, __shfl_xor_sync(0xffffffffu, mx0, 1));
            mx0 = fmaxf(mx0, __shfl_xor_sync(0xffffffffu, mx0, 2));
            mx1 = fmaxf(mx1, __shfl_xor_sync(0xffffffffu, mx1, 1));
            mx1 = fmaxf(mx1, __shfl_xor_sync(0xffffffffu, mx1, 2));
            float mn0 = fmaxf(mmx[mf][0], mx0 * scale);
            float mn1 = fmaxf(mmx[mf][1], mx1 * scale);
            float c0 = __expf(mmx[mf][0] - mn0);
            float c1 = __expf(mmx[mf][1] - mn1);
            float s0 = 0.f, s1 = 0.f;
#pragma unroll
            for (int nf = 0; nf < 8; nf++) {
                float p00 = __expf(S[mf][nf][0] * scale - mn0);
                float p01 = __expf(S[mf][nf][1] * scale - mn0);
                float p10 = __expf(S[mf][nf][2] * scale - mn1);
                float p11 = __expf(S[mf][nf][3] * scale - mn1);
                S[mf][nf][0] = p00; S[mf][nf][1] = p01;
                S[mf][nf][2] = p10; S[mf][nf][3] = p11;
                s0 += p00 + p01; s1 += p10 + p11;
            }
            s0 += __shfl_xor_sync(0xffffffffu, s0, 1);
            s0 += __shfl_xor_sync(0xffffffffu, s0, 2);
            s1 += __shfl_xor_sync(0xffffffffu, s1, 1);
            s1 += __shfl_xor_sync(0xffffffffu, s1, 2);
            lsum[mf][0] = lsum[mf][0] * c0 + s0;
            lsum[mf][1] = lsum[mf][1] * c1 + s1;
            mmx[mf][0] = mn0; mmx[mf][1] = mn1;
#pragma unroll
            for (int df = 0; df < 8; df++) {
                O[mf][df][0] *= c0; O[mf][df][1] *= c0;
                O[mf][df][2] *= c1; O[mf][df][3] *= c1;
            }
        }

        // O += P @ V : P A-frags are identity-remapped C-frags (fp16)
#pragma unroll
        for (int p = 0; p < 4; p++) {
            unsigned PA[2][4];
#pragma unroll
            for (int mf = 0; mf < 2; mf++) {
                PA[mf][0] = pack2(S[mf][2 * p][0],     S[mf][2 * p][1]);
                PA[mf][1] = pack2(S[mf][2 * p][2],     S[mf][2 * p][3]);
                PA[mf][2] = pack2(S[mf][2 * p + 1][0], S[mf][2 * p + 1][1]);
                PA[mf][3] = pack2(S[mf][2 * p + 1][2], S[mf][2 * p + 1][3]);
            }
#pragma unroll
            for (int nb = 0; nb < 4; nb++) {
                unsigned Bf[4];
                ldsm4(Bf[0], Bf[1], Bf[2], Bf[3], vB + nb * 16 * HROW + p * 32);
#pragma unroll
                for (int mf = 0; mf < 2; mf++) {
                    mma16h(O[mf][2 * nb],     PA[mf], Bf[0], Bf[1]);
                    mma16h(O[mf][2 * nb + 1], PA[mf], Bf[2], Bf[3]);
                }
            }
        }
        __syncthreads();
    }

    // epilogue: branch exchange + diff + GN + bf16 hi/lo out
    const float lam_init = lam_init_p[0];
    const float lam = __expf(lq1[h] * lk1[h]) - __expf(lq2[h] * lk2[h]) + lam_init;
    const float osc = 1.0f - lam_init;
    float* Ex = (float*)(smv + 4 * QTILE);   // 128 x 68 f32 = 34816 B, fits stage area

    if (br == 1) {
#pragma unroll
        for (int mf = 0; mf < 2; mf++) {
            float inv0 = lam / lsum[mf][0];
            float inv1 = lam / lsum[mf][1];
            int row0 = mblk * 32 + mf * 16 + g;
#pragma unroll
            for (int df = 0; df < 8; df++) {
                int col = df * 8 + 2 * t;
                *(float2*)&Ex[row0 * 68 + col] = make_float2(O[mf][df][0] * inv0, O[mf][df][1] * inv0);
                *(float2*)&Ex[(row0 + 8) * 68 + col] = make_float2(O[mf][df][2] * inv1, O[mf][df][3] * inv1);
            }
        }
    }
    __syncthreads();
    if (br == 0) {
#pragma unroll
        for (int mf = 0; mf < 2; mf++) {
#pragma unroll
            for (int half = 0; half < 2; half++) {
                float inv1 = 1.0f / lsum[mf][half];
                int lrow = mblk * 32 + mf * 16 + g + 8 * half;
                float v[16];
                float s = 0.f, sq = 0.f;
#pragma unroll
                for (int df = 0; df < 8; df++) {
                    float2 e = *(float2*)&Ex[lrow * 68 + df * 8 + 2 * t];
                    float a0 = O[mf][df][half * 2 + 0] * inv1 - e.x;
                    float a1 = O[mf][df][half * 2 + 1] * inv1 - e.y;
                    v[2 * df] = a0; v[2 * df + 1] = a1;
                    s += a0 + a1; sq += a0 * a0 + a1 * a1;
                }
                s  += __shfl_xor_sync(0xffffffffu, s, 1);
                s  += __shfl_xor_sync(0xffffffffu, s, 2);
                sq += __shfl_xor_sync(0xffffffffu, sq, 1);
                sq += __shfl_xor_sync(0xffffffffu, sq, 2);
                float mean = s * (1.0f / 64.0f);
                float var = sq * (1.0f / 64.0f) - mean * mean;
                float istd = rsqrtf(var + GN_EPS);
                size_t grow = (size_t)(rowg0 + q0 + lrow);
#pragma unroll
                for (int df = 0; df < 8; df++) {
                    int col = h * HDIM + df * 8 + 2 * t;
                    float2 gw = *(const float2*)&gnw[col];
                    float2 gb = *(const float2*)&gnb[col];
                    float o0 = ((v[2 * df]     - mean) * istd * gw.x + gb.x) * osc;
                    float o1 = ((v[2 * df + 1] - mean) * istd * gw.y + gb.y) * osc;
                    __nv_bfloat16 h0 = __float2bfloat16_rn(o0);
                    __nv_bfloat16 h1 = __float2bfloat16_rn(o1);
                    __nv_bfloat162 ph; ph.x = h0; ph.y = h1;
                    __nv_bfloat162 pl;
                    pl.x = __float2bfloat16_rn(o0 - __bfloat162float(h0));
                    pl.y = __float2bfloat16_rn(o1 - __bfloat162float(h1));
                    *(__nv_bfloat162*)&OutH[grow * THD + col] = ph;
                    *(__nv_bfloat162*)&OutL[grow * THD + col] = pl;
                }
            }
        }
    }
}

// ---------------- kernel_launch ----------------
extern "C" void kernel_launch(void* const* d_in, const int* in_sizes, int n_in,
                              void* d_out, int out_size)
{
    const float* x   = (const float*)d_in[0];
    const float* Wq  = (const float*)d_in[1];
    const float* Wk  = (const float*)d_in[2];
    const float* Wv  = (const float*)d_in[3];
    const float* Wo  = (const float*)d_in[4];
    const float* lq1 = (const float*)d_in[5];
    const float* lk1 = (const float*)d_in[6];
    const float* lq2 = (const float*)d_in[7];
    const float* lk2 = (const float*)d_in[8];
    const float* lam = (const float*)d_in[9];
    const float* gnw = (const float*)d_in[10];
    const float* gnb = (const float*)d_in[11];
    float* out = (float*)d_out;

    float *Q, *K, *V, *cosT, *sinT;
    __half *Qh, *Kh, *Vth;
    __nv_bfloat16 *xh, *xl, *Wqh, *Wql, *Wkh, *Wkl, *Wvh, *Wvl, *Woh, *Wol, *Ah, *Al;
    cudaGetSymbolAddress((void**)&Q, g_Q);
    cudaGetSymbolAddress((void**)&K, g_K);
    cudaGetSymbolAddress((void**)&V, g_V);
    cudaGetSymbolAddress((void**)&Qh, g_Qh);
    cudaGetSymbolAddress((void**)&Kh, g_Kh);
    cudaGetSymbolAddress((void**)&Vth, g_Vth);
    cudaGetSymbolAddress((void**)&cosT, g_cosT);
    cudaGetSymbolAddress((void**)&sinT, g_sinT);
    cudaGetSymbolAddress((void**)&xh, g_xh);
    cudaGetSymbolAddress((void**)&xl, g_xl);
    cudaGetSymbolAddress((void**)&Wqh, g_Wqh);
    cudaGetSymbolAddress((void**)&Wql, g_Wql);
    cudaGetSymbolAddress((void**)&Wkh, g_Wkh);
    cudaGetSymbolAddress((void**)&Wkl, g_Wkl);
    cudaGetSymbolAddress((void**)&Wvh, g_Wvh);
    cudaGetSymbolAddress((void**)&Wvl, g_Wvl);
    cudaGetSymbolAddress((void**)&Woh, g_Woh);
    cudaGetSymbolAddress((void**)&Wol, g_Wol);
    cudaGetSymbolAddress((void**)&Ah, g_Ah);
    cudaGetSymbolAddress((void**)&Al, g_Al);

    cudaFuncSetAttribute(attn_v4_kernel, cudaFuncAttributeMaxDynamicSharedMemorySize, ATT_SMEM);
    cudaFuncSetAttribute(gemm_bf3_kernel, cudaFuncAttributeMaxDynamicSharedMemorySize, GEMM_SMEM);

    rope_tables_kernel<<<(SEQ * 32 + 255) / 256, 256>>>(cosT, sinT);

    conv_split_kernel<<<(MROWS * DMODEL + 255) / 256, 256>>>(x, xh, xl, MROWS * DMODEL);
    conv_split_kernel<<<(DMODEL * QK_COLS + 255) / 256, 256>>>(Wq, Wqh, Wql, DMODEL * QK_COLS);
    conv_split_kernel<<<(DMODEL * QK_COLS + 255) / 256, 256>>>(Wk, Wkh, Wkl, DMODEL * QK_COLS);
    conv_split_kernel<<<(DMODEL * THD + 255) / 256, 256>>>(Wv, Wvh, Wvl, DMODEL * THD);
    conv_split_kernel<<<(THD * DMODEL + 255) / 256, 256>>>(Wo, Woh, Wol, THD * DMODEL);

    gemm_bf3_kernel<<<dim3(QK_COLS / 128, MROWS / 128), 256, GEMM_SMEM>>>(
        xh, xl, Wqh, Wql, Q, MROWS, QK_COLS, DMODEL);
    gemm_bf3_kernel<<<dim3(QK_COLS / 128, MROWS / 128), 256, GEMM_SMEM>>>(
        xh, xl, Wkh, Wkl, K, MROWS, QK_COLS, DMODEL);
    gemm_bf3_kernel<<<dim3(THD / 128, MROWS / 128), 256, GEMM_SMEM>>>(
        xh, xl, Wvh, Wvl, V, MROWS, THD, DMODEL);

    rope_kernel<<<(MROWS * 1024) / 256, 256>>>(Q, K, Qh, Kh, cosT, sinT);
    vtrans_kernel<<<dim3(SEQ / 32, HDIM / 32, BATCH * NHEAD), dim3(32, 8)>>>(V, Vth);

    attn_v4_kernel<<<dim3(SEQ / 128, BATCH * NHEAD), 256, ATT_SMEM>>>(
        Qh, Kh, Vth, lq1, lk1, lq2, lk2, lam, gnw, gnb, Ah, Al);

    gemm_bf3_kernel<<<dim3(DMODEL / 128, MROWS / 128), 256, GEMM_SMEM>>>(
        Ah, Al, Woh, Wol, out, MROWS, DMODEL, THD);
}

// round 9
// speedup vs baseline: 2.8006x; 1.1717x over previous
#include <cuda_runtime.h>
#include <cuda_fp16.h>
#include <cstdint>
#include <math.h>

#define BATCH 2
#define SEQ   2048
#define DMODEL 1024
#define NHEAD 16
#define HDIM  64
#define THD   (NHEAD * HDIM)
#define MROWS (BATCH * SEQ)
#define QK_COLS (2 * THD)
#define GN_EPS 1e-5f

// ---------------- scratch (all fp16 dataflow) ----------------
__device__ __half g_Qpre[MROWS * QK_COLS];
__device__ __half g_Kpre[MROWS * QK_COLS];
__device__ __half g_Vpre[MROWS * THD];
__device__ __half g_Qh[MROWS * QK_COLS];
__device__ __half g_Kh[MROWS * QK_COLS];
__device__ __half g_Vth[BATCH * NHEAD * HDIM * SEQ];   // [bh][d][s]
__device__ float g_cosT[SEQ * 32];
__device__ float g_sinT[SEQ * 32];
__device__ __half g_xh[MROWS * DMODEL],  g_xl[MROWS * DMODEL];
__device__ __half g_Wq16[DMODEL * QK_COLS];
__device__ __half g_Wk16[DMODEL * QK_COLS];
__device__ __half g_Wv16[DMODEL * THD];
__device__ __half g_Wo16[THD * DMODEL];
__device__ __half g_Ah[MROWS * THD], g_Al[MROWS * THD];

// ---------------- helpers ----------------
__device__ __forceinline__ void ldsm4(unsigned &r0, unsigned &r1, unsigned &r2, unsigned &r3, unsigned a) {
    asm volatile("ldmatrix.sync.aligned.m8n8.x4.shared.b16 {%0,%1,%2,%3}, [%4];"
        : "=r"(r0), "=r"(r1), "=r"(r2), "=r"(r3) : "r"(a));
}
__device__ __forceinline__ void ldsmT4(unsigned &r0, unsigned &r1, unsigned &r2, unsigned &r3, unsigned a) {
    asm volatile("ldmatrix.sync.aligned.m8n8.x4.trans.shared.b16 {%0,%1,%2,%3}, [%4];"
        : "=r"(r0), "=r"(r1), "=r"(r2), "=r"(r3) : "r"(a));
}
__device__ __forceinline__ void mma16h(float* c, const unsigned* a, unsigned b0, unsigned b1) {
    asm volatile("mma.sync.aligned.m16n8k16.row.col.f32.f16.f16.f32 "
        "{%0,%1,%2,%3},{%4,%5,%6,%7},{%8,%9},{%0,%1,%2,%3};"
        : "+f"(c[0]), "+f"(c[1]), "+f"(c[2]), "+f"(c[3])
        : "r"(a[0]), "r"(a[1]), "r"(a[2]), "r"(a[3]), "r"(b0), "r"(b1));
}
__device__ __forceinline__ void cp16(unsigned s, const void* g) {
    asm volatile("cp.async.cg.shared.global [%0], [%1], 16;" :: "r"(s), "l"(g));
}
__device__ __forceinline__ void cpcommit() { asm volatile("cp.async.commit_group;"); }
__device__ __forceinline__ unsigned pack2(float a, float b) {
    __half2 h = __floats2half2_rn(a, b);
    return *(unsigned*)&h;
}

// ---------------- small kernels ----------------
__global__ void split_h_kernel(const float* __restrict__ s, __half* __restrict__ h,
                               __half* __restrict__ l, int n) {
    int i = blockIdx.x * blockDim.x + threadIdx.x;
    if (i >= n) return;
    float v = s[i];
    __half hv = __float2half_rn(v);
    h[i] = hv;
    l[i] = __float2half_rn(v - __half2float(hv));
}
__global__ void conv_h_kernel(const float* __restrict__ s, __half* __restrict__ d, int n) {
    int i = blockIdx.x * blockDim.x + threadIdx.x;
    if (i < n) d[i] = __float2half_rn(s[i]);
}

__global__ void rope_tables_kernel(float* __restrict__ cosT, float* __restrict__ sinT) {
    int i = blockIdx.x * blockDim.x + threadIdx.x;
    if (i >= SEQ * 32) return;
    int t = i >> 5, j = i & 31;
    double invf = pow(10000.0, -(double)(2 * j) / 64.0);
    float f = (float)t * (float)invf;
    cosT[i] = (float)cos((double)f);
    sinT[i] = (float)sin((double)f);
}

// fp16 Q,K pre-rope -> RoPE -> fp16
__global__ void rope_kernel(const __half* __restrict__ Qp, const __half* __restrict__ Kp,
                            __half* __restrict__ Qh, __half* __restrict__ Kh,
                            const float* __restrict__ cosT, const float* __restrict__ sinT) {
    int idx = blockIdx.x * blockDim.x + threadIdx.x;
    if (idx >= MROWS * 1024) return;
    int m = idx >> 10, p = idx & 1023;
    int ch = p >> 5, dl = p & 31;
    int s = m & (SEQ - 1);
    float c = cosT[s * 32 + dl], sn = sinT[s * 32 + dl];
    int base = m * QK_COLS + ch * HDIM + dl;
    float qlo = __half2float(Qp[base]), qhi = __half2float(Qp[base + 32]);
    Qh[base]      = __float2half_rn(qlo * c - qhi * sn);
    Qh[base + 32] = __float2half_rn(qhi * c + qlo * sn);
    float klo = __half2float(Kp[base]), khi = __half2float(Kp[base + 32]);
    Kh[base]      = __float2half_rn(klo * c - khi * sn);
    Kh[base + 32] = __float2half_rn(khi * c + klo * sn);
}

// fp16 V -> fp16 Vt [bh][d][s]
__global__ void vtrans_kernel(const __half* __restrict__ V, __half* __restrict__ Vt) {
    __shared__ float t[32][33];
    int bh = blockIdx.z, b = bh >> 4, h = bh & 15;
    int s0 = blockIdx.x * 32, d0 = blockIdx.y * 32;
    int tx = threadIdx.x, ty = threadIdx.y;
#pragma unroll
    for (int j = 0; j < 32; j += 8)
        t[ty + j][tx] = __half2float(V[(size_t)(b * SEQ + s0 + ty + j) * THD + h * HDIM + d0 + tx]);
    __syncthreads();
#pragma unroll
    for (int j = 0; j < 32; j += 8)
        Vt[(size_t)(bh * HDIM + d0 + ty + j) * SEQ + s0 + tx] = __float2half_rn(t[tx][ty + j]);
}

// ---------------- fp16 2-term mma.sync GEMM ----------------
// C[M,N] = (Ah+Al)[M,K] @ B[K,N]  (split-A; B single fp16)
// BM=128 BN=128 BK=32, 256 threads, 2-stage cp.async.
#define GA_ST 40
#define GB_ST 136
#define O_AH 0
#define O_AL (128 * GA_ST)
#define O_B  (2 * 128 * GA_ST)
#define STG_EL (O_B + 32 * GB_ST)     // 14592 halves
#define GEMM_SMEM (2 * STG_EL * 2)    // 58368 bytes

template <typename TOut>
__global__ __launch_bounds__(256) void gemm_h2_kernel(
    const __half* __restrict__ Ah, const __half* __restrict__ Al,
    const __half* __restrict__ B, TOut* __restrict__ C, int M, int N, int K)
{
    extern __shared__ __half smb[];
    const unsigned smB = (unsigned)__cvta_generic_to_shared(smb);
    const int tid = threadIdx.x, wid = tid >> 5, lane = tid & 31;
    const int wm = wid & 3, wn = wid >> 2;
    const int g = lane >> 2, t = lane & 3;
    const int bm0 = blockIdx.y * 128, bn0 = blockIdx.x * 128;

    float acc[2][8][4];
#pragma unroll
    for (int i = 0; i < 2; i++)
#pragma unroll
        for (int j = 0; j < 8; j++)
#pragma unroll
            for (int c = 0; c < 4; c++) acc[i][j][c] = 0.f;

    auto load_stage = [&](int kt, int stg) {
        const int k0 = kt * 32;
        const unsigned sb = smB + stg * (STG_EL * 2);
#pragma unroll
        for (int q = 0; q < 4; q++) {
            int fi = tid + q * 256;            // 0..1023
            int u = fi >> 9, idx = fi & 511;
            int r = idx >> 2, c = (idx & 3) * 8;
            cp16(sb + ((u ? O_AL : O_AH) + r * GA_ST + c) * 2,
                 (u ? Al : Ah) + (size_t)(bm0 + r) * K + k0 + c);
        }
#pragma unroll
        for (int q = 0; q < 2; q++) {
            int fi = tid + q * 256;            // 0..511
            int r = fi >> 4, c = (fi & 15) * 8;
            cp16(sb + (O_B + r * GB_ST + c) * 2,
                 B + (size_t)(k0 + r) * N + bn0 + c);
        }
    };
    load_stage(0, 0);
    cpcommit();

    const unsigned aoff = ((lane & 15) * GA_ST + (lane >> 4) * 8) * 2;
    const unsigned boff = (((((lane >> 3) & 1) * 8) + (lane & 7)) * GB_ST + (lane >> 4) * 8) * 2;
    const int NT = K >> 5;

    for (int kt = 0; kt < NT; kt++) {
        if (kt + 1 < NT) { load_stage(kt + 1, (kt + 1) & 1); cpcommit();
            asm volatile("cp.async.wait_group 1;"); }
        else { asm volatile("cp.async.wait_group 0;"); }
        __syncthreads();
        const unsigned sb = smB + (kt & 1) * (STG_EL * 2);

#pragma unroll
        for (int ks = 0; ks < 2; ks++) {
            unsigned AH[2][4], AL[2][4];
#pragma unroll
            for (int mf = 0; mf < 2; mf++) {
                unsigned a = sb + (wm * 32 + mf * 16) * GA_ST * 2 + aoff + ks * 32;
                ldsm4(AH[mf][0], AH[mf][1], AH[mf][2], AH[mf][3], a + O_AH * 2);
                ldsm4(AL[mf][0], AL[mf][1], AL[mf][2], AL[mf][3], a + O_AL * 2);
            }
#pragma unroll
            for (int np = 0; np < 4; np++) {
                unsigned bofs = sb + boff + ks * 16 * GB_ST * 2 + O_B * 2 + (wn * 64 + np * 16) * 2;
                unsigned TB[4];
                ldsmT4(TB[0], TB[1], TB[2], TB[3], bofs);
#pragma unroll
                for (int hh = 0; hh < 2; hh++) {
                    int nf = np * 2 + hh;
#pragma unroll
                    for (int mf = 0; mf < 2; mf++) {
                        mma16h(acc[mf][nf], AH[mf], TB[2 * hh], TB[2 * hh + 1]);
                        mma16h(acc[mf][nf], AL[mf], TB[2 * hh], TB[2 * hh + 1]);
                    }
                }
            }
        }
        __syncthreads();
    }

#pragma unroll
    for (int mf = 0; mf < 2; mf++) {
        size_t r0 = (size_t)(bm0 + wm * 32 + mf * 16 + g);
#pragma unroll
        for (int nf = 0; nf < 8; nf++) {
            int c = bn0 + wn * 64 + nf * 8 + 2 * t;
            if (sizeof(TOut) == 4) {
                float* Cf = (float*)C;
                *(float2*)&Cf[r0 * N + c]       = make_float2(acc[mf][nf][0], acc[mf][nf][1]);
                *(float2*)&Cf[(r0 + 8) * N + c] = make_float2(acc[mf][nf][2], acc[mf][nf][3]);
            } else {
                __half* Ch = (__half*)C;
                *(__half2*)&Ch[r0 * N + c]       = __floats2half2_rn(acc[mf][nf][0], acc[mf][nf][1]);
                *(__half2*)&Ch[(r0 + 8) * N + c] = __floats2half2_rn(acc[mf][nf][2], acc[mf][nf][3]);
            }
        }
    }
}

// ---------------- fp16 differential flash attention v4 ----------------
#define HROW 144                       // bytes per smem row (72 halves)
#define QTILE 9216                     // 64 rows x 144 B
#define ST_STRIDE 27648                // 3 tiles (K1,K2,V) per stage
#define ATT_SMEM (4 * QTILE + 2 * ST_STRIDE)   // 92160 bytes
#define NKT (SEQ / 64)

__global__ __launch_bounds__(256) void attn_v4_kernel(
    const __half* __restrict__ Q, const __half* __restrict__ K, const __half* __restrict__ Vt,
    const float* __restrict__ lq1, const float* __restrict__ lk1,
    const float* __restrict__ lq2, const float* __restrict__ lk2,
    const float* __restrict__ lam_init_p,
    const float* __restrict__ gnw, const float* __restrict__ gnb,
    __half* __restrict__ OutH, __half* __restrict__ OutL)
{
    extern __shared__ char smv[];
    const unsigned smBase = (unsigned)__cvta_generic_to_shared(smv);
    const int tid = threadIdx.x, wid = tid >> 5, lane = tid & 31;
    const int br = wid >> 2, mblk = wid & 3;
    const int g = lane >> 2, t = lane & 3;
    const int bh = blockIdx.y, b = bh >> 4, h = bh & 15;
    const int q0 = blockIdx.x * 128;
    const int rowg0 = b * SEQ;
    const float scale = 0.125f;
    const int c1base = h * HDIM;

#pragma unroll
    for (int q = 0; q < 4; q++) {
        int fi = tid + q * 256;
        int r = fi >> 3, c = fi & 7;
        const __half* gq = &Q[(size_t)(rowg0 + q0 + r) * QK_COLS + c1base + c * 8];
        cp16(smBase + r * HROW + c * 16, gq);
        cp16(smBase + 2 * QTILE + r * HROW + c * 16, gq + THD);
    }
    auto load_stage = [&](int kt, int stg) {
        const int k0 = kt * 64;
        const unsigned base = smBase + 4 * QTILE + stg * ST_STRIDE;
#pragma unroll
        for (int q = 0; q < 2; q++) {
            int fi = tid + q * 256;
            int r = fi >> 3, c = fi & 7;
            const __half* gk = &K[(size_t)(rowg0 + k0 + r) * QK_COLS + c1base + c * 8];
            cp16(base + r * HROW + c * 16, gk);
            cp16(base + QTILE + r * HROW + c * 16, gk + THD);
            cp16(base + 2 * QTILE + r * HROW + c * 16,
                 &Vt[(size_t)(bh * HDIM + r) * SEQ + k0 + c * 8]);
        }
    };
    load_stage(0, 0);
    cpcommit();

    const unsigned aoff = (lane & 15) * HROW + (lane >> 4) * 16;
    const unsigned boff = ((lane & 7) + ((lane >> 4) << 3)) * HROW + ((lane >> 3) & 1) * 16;
    const unsigned aQw = smBase + br * (2 * QTILE) + mblk * 32 * HROW + aoff;

    float O[2][8][4];
#pragma unroll
    for (int mf = 0; mf < 2; mf++)
#pragma unroll
        for (int df = 0; df < 8; df++)
#pragma unroll
            for (int c = 0; c < 4; c++) O[mf][df][c] = 0.f;
    float mmx[2][2] = {{-1e30f, -1e30f}, {-1e30f, -1e30f}};
    float lsum[2][2] = {{0.f, 0.f}, {0.f, 0.f}};

    for (int kt = 0; kt < NKT; kt++) {
        if (kt + 1 < NKT) { load_stage(kt + 1, (kt + 1) & 1); cpcommit();
            asm volatile("cp.async.wait_group 1;"); }
        else { asm volatile("cp.async.wait_group 0;"); }
        __syncthreads();

        const unsigned stb = smBase + 4 * QTILE + (kt & 1) * ST_STRIDE;
        const unsigned kB = stb + br * QTILE + boff;
        const unsigned vB = stb + 2 * QTILE + boff;

        float S[2][8][4];
#pragma unroll
        for (int mf = 0; mf < 2; mf++)
#pragma unroll
            for (int nf = 0; nf < 8; nf++)
#pragma unroll
                for (int c = 0; c < 4; c++) S[mf][nf][c] = 0.f;

#pragma unroll
        for (int p = 0; p < 4; p++) {
            unsigned A[2][4];
#pragma unroll
            for (int mf = 0; mf < 2; mf++)
                ldsm4(A[mf][0], A[mf][1], A[mf][2], A[mf][3],
                      aQw + mf * 16 * HROW + p * 32);
#pragma unroll
            for (int nb = 0; nb < 4; nb++) {
                unsigned Bf[4];
                ldsm4(Bf[0], Bf[1], Bf[2], Bf[3], kB + nb * 16 * HROW + p * 32);
#pragma unroll
                for (int mf = 0; mf < 2; mf++) {
                    mma16h(S[mf][2 * nb],     A[mf], Bf[0], Bf[1]);
                    mma16h(S[mf][2 * nb + 1], A[mf], Bf[2], Bf[3]);
                }
            }
        }

#pragma unroll
        for (int mf = 0; mf < 2; mf++) {
            float mx0 = -1e30f, mx1 = -1e30f;
#pragma unroll
            for (int nf = 0; nf < 8; nf++) {
                mx0 = fmaxf(mx0, fmaxf(S[mf][nf][0], S[mf][nf][1]));
                mx1 = fmaxf(mx1, fmaxf(S[mf][nf][2], S[mf][nf][3]));
            }
            mx0 = fmaxf(mx0, __shfl_xor_sync(0xffffffffu, mx0, 1));
            mx0 = fmaxf(mx0, __shfl_xor_sync(0xffffffffu, mx0, 2));
            mx1 = fmaxf(mx1, __shfl_xor_sync(0xffffffffu, mx1, 1));
            mx1 = fmaxf(mx1, __shfl_xor_sync(0xffffffffu, mx1, 2));
            float mn0 = fmaxf(mmx[mf][0], mx0 * scale);
            float mn1 = fmaxf(mmx[mf][1], mx1 * scale);
            float c0 = __expf(mmx[mf][0] - mn0);
            float c1 = __expf(mmx[mf][1] - mn1);
            float s0 = 0.f, s1 = 0.f;
#pragma unroll
            for (int nf = 0; nf < 8; nf++) {
                float p00 = __expf(S[mf][nf][0] * scale - mn0);
                float p01 = __expf(S[mf][nf][1] * scale - mn0);
                float p10 = __expf(S[mf][nf][2] * scale - mn1);
                float p11 = __expf(S[mf][nf][3] * scale - mn1);
                S[mf][nf][0] = p00; S[mf][nf][1] = p01;
                S[mf][nf][2] = p10; S[mf][nf][3] = p11;
                s0 += p00 + p01; s1 += p10 + p11;
            }
            s0 += __shfl_xor_sync(0xffffffffu, s0, 1);
            s0 += __shfl_xor_sync(0xffffffffu, s0, 2);
            s1 += __shfl_xor_sync(0xffffffffu, s1, 1);
            s1 += __shfl_xor_sync(0xffffffffu, s1, 2);
            lsum[mf][0] = lsum[mf][0] * c0 + s0;
            lsum[mf][1] = lsum[mf][1] * c1 + s1;
            mmx[mf][0] = mn0; mmx[mf][1] = mn1;
#pragma unroll
            for (int df = 0; df < 8; df++) {
                O[mf][df][0] *= c0; O[mf][df][1] *= c0;
                O[mf][df][2] *= c1; O[mf][df][3] *= c1;
            }
        }

#pragma unroll
        for (int p = 0; p < 4; p++) {
            unsigned PA[2][4];
#pragma unroll
            for (int mf = 0; mf < 2; mf++) {
                PA[mf][0] = pack2(S[mf][2 * p][0],     S[mf][2 * p][1]);
                PA[mf][1] = pack2(S[mf][2 * p][2],     S[mf][2 * p][3]);
                PA[mf][2] = pack2(S[mf][2 * p + 1][0], S[mf][2 * p + 1][1]);
                PA[mf][3] = pack2(S[mf][2 * p + 1][2], S[mf][2 * p + 1][3]);
            }
#pragma unroll
            for (int nb = 0; nb < 4; nb++) {
                unsigned Bf[4];
                ldsm4(Bf[0], Bf[1], Bf[2], Bf[3], vB + nb * 16 * HROW + p * 32);
#pragma unroll
                for (int mf = 0; mf < 2; mf++) {
                    mma16h(O[mf][2 * nb],     PA[mf], Bf[0], Bf[1]);
                    mma16h(O[mf][2 * nb + 1], PA[mf], Bf[2], Bf[3]);
                }
            }
        }
        __syncthreads();
    }

    const float lam_init = lam_init_p[0];
    const float lam = __expf(lq1[h] * lk1[h]) - __expf(lq2[h] * lk2[h]) + lam_init;
    const float osc = 1.0f - lam_init;
    float* Ex = (float*)(smv + 4 * QTILE);

    if (br == 1) {
#pragma unroll
        for (int mf = 0; mf < 2; mf++) {
            float inv0 = lam / lsum[mf][0];
            float inv1 = lam / lsum[mf][1];
            int row0 = mblk * 32 + mf * 16 + g;
#pragma unroll
            for (int df = 0; df < 8; df++) {
                int col = df * 8 + 2 * t;
                *(float2*)&Ex[row0 * 68 + col] = make_float2(O[mf][df][0] * inv0, O[mf][df][1] * inv0);
                *(float2*)&Ex[(row0 + 8) * 68 + col] = make_float2(O[mf][df][2] * inv1, O[mf][df][3] * inv1);
            }
        }
    }
    __syncthreads();
    if (br == 0) {
#pragma unroll
        for (int mf = 0; mf < 2; mf++) {
#pragma unroll
            for (int half = 0; half < 2; half++) {
                float inv1 = 1.0f / lsum[mf][half];
                int lrow = mblk * 32 + mf * 16 + g + 8 * half;
                float v[16];
                float s = 0.f, sq = 0.f;
#pragma unroll
                for (int df = 0; df < 8; df++) {
                    float2 e = *(float2*)&Ex[lrow * 68 + df * 8 + 2 * t];
                    float a0 = O[mf][df][half * 2 + 0] * inv1 - e.x;
                    float a1 = O[mf][df][half * 2 + 1] * inv1 - e.y;
                    v[2 * df] = a0; v[2 * df + 1] = a1;
                    s += a0 + a1; sq += a0 * a0 + a1 * a1;
                }
                s  += __shfl_xor_sync(0xffffffffu, s, 1);
                s  += __shfl_xor_sync(0xffffffffu, s, 2);
                sq += __shfl_xor_sync(0xffffffffu, sq, 1);
                sq += __shfl_xor_sync(0xffffffffu, sq, 2);
                float mean = s * (1.0f / 64.0f);
                float var = sq * (1.0f / 64.0f) - mean * mean;
                float istd = rsqrtf(var + GN_EPS);
                size_t grow = (size_t)(rowg0 + q0 + lrow);
#pragma unroll
                for (int df = 0; df < 8; df++) {
                    int col = h * HDIM + df * 8 + 2 * t;
                    float2 gw = *(const float2*)&gnw[col];
                    float2 gb = *(const float2*)&gnb[col];
                    float o0 = ((v[2 * df]     - mean) * istd * gw.x + gb.x) * osc;
                    float o1 = ((v[2 * df + 1] - mean) * istd * gw.y + gb.y) * osc;
                    __half h0 = __float2half_rn(o0);
                    __half h1 = __float2half_rn(o1);
                    __half2 ph; ph.x = h0; ph.y = h1;
                    __half2 pl;
                    pl.x = __float2half_rn(o0 - __half2float(h0));
                    pl.y = __float2half_rn(o1 - __half2float(h1));
                    *(__half2*)&OutH[grow * THD + col] = ph;
                    *(__half2*)&OutL[grow * THD + col] = pl;
                }
            }
        }
    }
}

// ---------------- kernel_launch ----------------
extern "C" void kernel_launch(void* const* d_in, const int* in_sizes, int n_in,
                              void* d_out, int out_size)
{
    const float* x   = (const float*)d_in[0];
    const float* Wq  = (const float*)d_in[1];
    const float* Wk  = (const float*)d_in[2];
    const float* Wv  = (const float*)d_in[3];
    const float* Wo  = (const float*)d_in[4];
    const float* lq1 = (const float*)d_in[5];
    const float* lk1 = (const float*)d_in[6];
    const float* lq2 = (const float*)d_in[7];
    const float* lk2 = (const float*)d_in[8];
    const float* lam = (const float*)d_in[9];
    const float* gnw = (const float*)d_in[10];
    const float* gnb = (const float*)d_in[11];
    float* out = (float*)d_out;

    float *cosT, *sinT;
    __half *Qp, *Kp, *Vp, *Qh, *Kh, *Vth, *xh, *xl, *Wq16, *Wk16, *Wv16, *Wo16, *Ah, *Al;
    cudaGetSymbolAddress((void**)&Qp, g_Qpre);
    cudaGetSymbolAddress((void**)&Kp, g_Kpre);
    cudaGetSymbolAddress((void**)&Vp, g_Vpre);
    cudaGetSymbolAddress((void**)&Qh, g_Qh);
    cudaGetSymbolAddress((void**)&Kh, g_Kh);
    cudaGetSymbolAddress((void**)&Vth, g_Vth);
    cudaGetSymbolAddress((void**)&cosT, g_cosT);
    cudaGetSymbolAddress((void**)&sinT, g_sinT);
    cudaGetSymbolAddress((void**)&xh, g_xh);
    cudaGetSymbolAddress((void**)&xl, g_xl);
    cudaGetSymbolAddress((void**)&Wq16, g_Wq16);
    cudaGetSymbolAddress((void**)&Wk16, g_Wk16);
    cudaGetSymbolAddress((void**)&Wv16, g_Wv16);
    cudaGetSymbolAddress((void**)&Wo16, g_Wo16);
    cudaGetSymbolAddress((void**)&Ah, g_Ah);
    cudaGetSymbolAddress((void**)&Al, g_Al);

    cudaFuncSetAttribute(attn_v4_kernel, cudaFuncAttributeMaxDynamicSharedMemorySize, ATT_SMEM);
    cudaFuncSetAttribute(gemm_h2_kernel<__half>, cudaFuncAttributeMaxDynamicSharedMemorySize, GEMM_SMEM);
    cudaFuncSetAttribute(gemm_h2_kernel<float>, cudaFuncAttributeMaxDynamicSharedMemorySize, GEMM_SMEM);

    rope_tables_kernel<<<(SEQ * 32 + 255) / 256, 256>>>(cosT, sinT);

    split_h_kernel<<<(MROWS * DMODEL + 255) / 256, 256>>>(x, xh, xl, MROWS * DMODEL);
    conv_h_kernel<<<(DMODEL * QK_COLS + 255) / 256, 256>>>(Wq, Wq16, DMODEL * QK_COLS);
    conv_h_kernel<<<(DMODEL * QK_COLS + 255) / 256, 256>>>(Wk, Wk16, DMODEL * QK_COLS);
    conv_h_kernel<<<(DMODEL * THD + 255) / 256, 256>>>(Wv, Wv16, DMODEL * THD);
    conv_h_kernel<<<(THD * DMODEL + 255) / 256, 256>>>(Wo, Wo16, THD * DMODEL);

    gemm_h2_kernel<__half><<<dim3(QK_COLS / 128, MROWS / 128), 256, GEMM_SMEM>>>(
        xh, xl, Wq16, Qp, MROWS, QK_COLS, DMODEL);
    gemm_h2_kernel<__half><<<dim3(QK_COLS / 128, MROWS / 128), 256, GEMM_SMEM>>>(
        xh, xl, Wk16, Kp, MROWS, QK_COLS, DMODEL);
    gemm_h2_kernel<__half><<<dim3(THD / 128, MROWS / 128), 256, GEMM_SMEM>>>(
        xh, xl, Wv16, Vp, MROWS, THD, DMODEL);

    rope_kernel<<<(MROWS * 1024) / 256, 256>>>(Qp, Kp, Qh, Kh, cosT, sinT);
    vtrans_kernel<<<dim3(SEQ / 32, HDIM / 32, BATCH * NHEAD), dim3(32, 8)>>>(Vp, Vth);

    attn_v4_kernel<<<dim3(SEQ / 128, BATCH * NHEAD), 256, ATT_SMEM>>>(
        Qh, Kh, Vth, lq1, lk1, lq2, lk2, lam, gnw, gnb, Ah, Al);

    gemm_h2_kernel<float><<<dim3(DMODEL / 128, MROWS / 128), 256, GEMM_SMEM>>>(
        Ah, Al, Wo16, out, MROWS, DMODEL, THD);
}

// round 10
// speedup vs baseline: 2.8882x; 1.0313x over previous
#include <cuda_runtime.h>
#include <cuda_fp16.h>
#include <cstdint>
#include <math.h>

#define BATCH 2
#define SEQ   2048
#define DMODEL 1024
#define NHEAD 16
#define HDIM  64
#define THD   (NHEAD * HDIM)
#define MROWS (BATCH * SEQ)
#define QK_COLS (2 * THD)
#define GN_EPS 1e-5f

// ---------------- scratch ----------------
__device__ __half g_Qh[MROWS * QK_COLS];      // post-RoPE Q (fp16)
__device__ __half g_Kh[MROWS * QK_COLS];      // post-RoPE K (fp16)
__device__ __half g_V16[MROWS * THD];         // V (fp16, row-major)
__device__ float g_cosT[SEQ * 32];
__device__ float g_sinT[SEQ * 32];
__device__ __half g_xh[MROWS * DMODEL],  g_xl[MROWS * DMODEL];
__device__ __half g_Wq16[DMODEL * QK_COLS];
__device__ __half g_Wk16[DMODEL * QK_COLS];
__device__ __half g_Wv16[DMODEL * THD];
__device__ __half g_Wo16[THD * DMODEL];
__device__ __half g_Ah[MROWS * THD], g_Al[MROWS * THD];

// ---------------- helpers ----------------
__device__ __forceinline__ void ldsm4(unsigned &r0, unsigned &r1, unsigned &r2, unsigned &r3, unsigned a) {
    asm volatile("ldmatrix.sync.aligned.m8n8.x4.shared.b16 {%0,%1,%2,%3}, [%4];"
        : "=r"(r0), "=r"(r1), "=r"(r2), "=r"(r3) : "r"(a));
}
__device__ __forceinline__ void ldsmT4(unsigned &r0, unsigned &r1, unsigned &r2, unsigned &r3, unsigned a) {
    asm volatile("ldmatrix.sync.aligned.m8n8.x4.trans.shared.b16 {%0,%1,%2,%3}, [%4];"
        : "=r"(r0), "=r"(r1), "=r"(r2), "=r"(r3) : "r"(a));
}
__device__ __forceinline__ void mma16h(float* c, const unsigned* a, unsigned b0, unsigned b1) {
    asm volatile("mma.sync.aligned.m16n8k16.row.col.f32.f16.f16.f32 "
        "{%0,%1,%2,%3},{%4,%5,%6,%7},{%8,%9},{%0,%1,%2,%3};"
        : "+f"(c[0]), "+f"(c[1]), "+f"(c[2]), "+f"(c[3])
        : "r"(a[0]), "r"(a[1]), "r"(a[2]), "r"(a[3]), "r"(b0), "r"(b1));
}
__device__ __forceinline__ void cp16(unsigned s, const void* g) {
    asm volatile("cp.async.cg.shared.global [%0], [%1], 16;" :: "r"(s), "l"(g));
}
__device__ __forceinline__ void cpcommit() { asm volatile("cp.async.commit_group;"); }
__device__ __forceinline__ unsigned pack2(float a, float b) {
    __half2 h = __floats2half2_rn(a, b);
    return *(unsigned*)&h;
}

// ---------------- small kernels ----------------
__global__ void split_h_kernel(const float* __restrict__ s, __half* __restrict__ h,
                               __half* __restrict__ l, int n) {
    int i = blockIdx.x * blockDim.x + threadIdx.x;
    if (i >= n) return;
    float v = s[i];
    __half hv = __float2half_rn(v);
    h[i] = hv;
    l[i] = __float2half_rn(v - __half2float(hv));
}

// fused conversion of all 4 weight matrices (grid.y selects tensor)
__global__ void conv_w_kernel(const float* __restrict__ Wq, const float* __restrict__ Wk,
                              const float* __restrict__ Wv, const float* __restrict__ Wo,
                              __half* __restrict__ q16, __half* __restrict__ k16,
                              __half* __restrict__ v16, __half* __restrict__ o16) {
    int which = blockIdx.y;
    const float* s;
    __half* d;
    int n;
    if (which == 0)      { s = Wq; d = q16; n = DMODEL * QK_COLS; }
    else if (which == 1) { s = Wk; d = k16; n = DMODEL * QK_COLS; }
    else if (which == 2) { s = Wv; d = v16; n = DMODEL * THD; }
    else                 { s = Wo; d = o16; n = THD * DMODEL; }
    int i = blockIdx.x * blockDim.x + threadIdx.x;
    if (i < n) d[i] = __float2half_rn(s[i]);
}

__global__ void rope_tables_kernel(float* __restrict__ cosT, float* __restrict__ sinT) {
    int i = blockIdx.x * blockDim.x + threadIdx.x;
    if (i >= SEQ * 32) return;
    int t = i >> 5, j = i & 31;
    double invf = pow(10000.0, -(double)(2 * j) / 64.0);
    float f = (float)t * (float)invf;
    cosT[i] = (float)cos((double)f);
    sinT[i] = (float)sin((double)f);
}

// ---------------- fp16 2-term GEMM with optional fused RoPE epilogue ----------------
// C[M,N] = (Ah+Al)[M,K] @ B[K,N]; if ROPE, rotate (d, d+32) pairs within each
// 64-wide head block using cos/sin(s = row mod SEQ) before fp16 store.
#define GA_ST 40
#define GB_ST 136
#define O_AH 0
#define O_AL (128 * GA_ST)
#define O_B  (2 * 128 * GA_ST)
#define STG_EL (O_B + 32 * GB_ST)
#define GEMM_SMEM (2 * STG_EL * 2)

template <typename TOut, bool ROPE>
__global__ __launch_bounds__(256) void gemm_h2_kernel(
    const __half* __restrict__ Ah, const __half* __restrict__ Al,
    const __half* __restrict__ B, TOut* __restrict__ C, int M, int N, int K,
    const float* __restrict__ cosT, const float* __restrict__ sinT)
{
    extern __shared__ __half smb[];
    const unsigned smB = (unsigned)__cvta_generic_to_shared(smb);
    const int tid = threadIdx.x, wid = tid >> 5, lane = tid & 31;
    const int wm = wid & 3, wn = wid >> 2;
    const int g = lane >> 2, t = lane & 3;
    const int bm0 = blockIdx.y * 128, bn0 = blockIdx.x * 128;

    float acc[2][8][4];
#pragma unroll
    for (int i = 0; i < 2; i++)
#pragma unroll
        for (int j = 0; j < 8; j++)
#pragma unroll
            for (int c = 0; c < 4; c++) acc[i][j][c] = 0.f;

    auto load_stage = [&](int kt, int stg) {
        const int k0 = kt * 32;
        const unsigned sb = smB + stg * (STG_EL * 2);
#pragma unroll
        for (int q = 0; q < 4; q++) {
            int fi = tid + q * 256;
            int u = fi >> 9, idx = fi & 511;
            int r = idx >> 2, c = (idx & 3) * 8;
            cp16(sb + ((u ? O_AL : O_AH) + r * GA_ST + c) * 2,
                 (u ? Al : Ah) + (size_t)(bm0 + r) * K + k0 + c);
        }
#pragma unroll
        for (int q = 0; q < 2; q++) {
            int fi = tid + q * 256;
            int r = fi >> 4, c = (fi & 15) * 8;
            cp16(sb + (O_B + r * GB_ST + c) * 2,
                 B + (size_t)(k0 + r) * N + bn0 + c);
        }
    };
    load_stage(0, 0);
    cpcommit();

    const unsigned aoff = ((lane & 15) * GA_ST + (lane >> 4) * 8) * 2;
    const unsigned boff = (((((lane >> 3) & 1) * 8) + (lane & 7)) * GB_ST + (lane >> 4) * 8) * 2;
    const int NT = K >> 5;

    for (int kt = 0; kt < NT; kt++) {
        if (kt + 1 < NT) { load_stage(kt + 1, (kt + 1) & 1); cpcommit();
            asm volatile("cp.async.wait_group 1;"); }
        else { asm volatile("cp.async.wait_group 0;"); }
        __syncthreads();
        const unsigned sb = smB + (kt & 1) * (STG_EL * 2);

#pragma unroll
        for (int ks = 0; ks < 2; ks++) {
            unsigned AH[2][4], AL[2][4];
#pragma unroll
            for (int mf = 0; mf < 2; mf++) {
                unsigned a = sb + (wm * 32 + mf * 16) * GA_ST * 2 + aoff + ks * 32;
                ldsm4(AH[mf][0], AH[mf][1], AH[mf][2], AH[mf][3], a + O_AH * 2);
                ldsm4(AL[mf][0], AL[mf][1], AL[mf][2], AL[mf][3], a + O_AL * 2);
            }
#pragma unroll
            for (int np = 0; np < 4; np++) {
                unsigned bofs = sb + boff + ks * 16 * GB_ST * 2 + O_B * 2 + (wn * 64 + np * 16) * 2;
                unsigned TB[4];
                ldsmT4(TB[0], TB[1], TB[2], TB[3], bofs);
#pragma unroll
                for (int hh = 0; hh < 2; hh++) {
                    int nf = np * 2 + hh;
#pragma unroll
                    for (int mf = 0; mf < 2; mf++) {
                        mma16h(acc[mf][nf], AH[mf], TB[2 * hh], TB[2 * hh + 1]);
                        mma16h(acc[mf][nf], AL[mf], TB[2 * hh], TB[2 * hh + 1]);
                    }
                }
            }
        }
        __syncthreads();
    }

#pragma unroll
    for (int mf = 0; mf < 2; mf++) {
#pragma unroll
        for (int half = 0; half < 2; half++) {
            size_t row = (size_t)(bm0 + wm * 32 + mf * 16 + g + 8 * half);
            if (ROPE) {
                int s = (int)(row & (SEQ - 1));
#pragma unroll
                for (int nf = 0; nf < 4; nf++) {
                    int d = nf * 8 + 2 * t;
                    float2 cc = *(const float2*)&cosT[s * 32 + d];
                    float2 ss = *(const float2*)&sinT[s * 32 + d];
                    float lo0 = acc[mf][nf][2 * half], lo1 = acc[mf][nf][2 * half + 1];
                    float hi0 = acc[mf][nf + 4][2 * half], hi1 = acc[mf][nf + 4][2 * half + 1];
                    __half* Ch = (__half*)C;
                    int c0 = bn0 + wn * 64 + d;
                    *(__half2*)&Ch[row * N + c0] =
                        __floats2half2_rn(lo0 * cc.x - hi0 * ss.x, lo1 * cc.y - hi1 * ss.y);
                    *(__half2*)&Ch[row * N + c0 + 32] =
                        __floats2half2_rn(hi0 * cc.x + lo0 * ss.x, hi1 * cc.y + lo1 * ss.y);
                }
            } else {
#pragma unroll
                for (int nf = 0; nf < 8; nf++) {
                    int c = bn0 + wn * 64 + nf * 8 + 2 * t;
                    if (sizeof(TOut) == 4) {
                        float* Cf = (float*)C;
                        *(float2*)&Cf[row * N + c] =
                            make_float2(acc[mf][nf][2 * half], acc[mf][nf][2 * half + 1]);
                    } else {
                        __half* Ch = (__half*)C;
                        *(__half2*)&Ch[row * N + c] =
                            __floats2half2_rn(acc[mf][nf][2 * half], acc[mf][nf][2 * half + 1]);
                    }
                }
            }
        }
    }
}

// ---------------- fp16 differential flash attention v5 ----------------
// Same as v4 but V is loaded row-major [s][d] and B-fragments come via
// ldmatrix.trans (no pre-transposed Vt buffer).
#define HROW 144
#define QTILE 9216
#define ST_STRIDE 27648
#define ATT_SMEM (4 * QTILE + 2 * ST_STRIDE)   // 92160
#define NKT (SEQ / 64)

__global__ __launch_bounds__(256) void attn_v5_kernel(
    const __half* __restrict__ Q, const __half* __restrict__ K, const __half* __restrict__ V,
    const float* __restrict__ lq1, const float* __restrict__ lk1,
    const float* __restrict__ lq2, const float* __restrict__ lk2,
    const float* __restrict__ lam_init_p,
    const float* __restrict__ gnw, const float* __restrict__ gnb,
    __half* __restrict__ OutH, __half* __restrict__ OutL)
{
    extern __shared__ char smv[];
    const unsigned smBase = (unsigned)__cvta_generic_to_shared(smv);
    const int tid = threadIdx.x, wid = tid >> 5, lane = tid & 31;
    const int br = wid >> 2, mblk = wid & 3;
    const int g = lane >> 2, t = lane & 3;
    const int bh = blockIdx.y, b = bh >> 4, h = bh & 15;
    const int q0 = blockIdx.x * 128;
    const int rowg0 = b * SEQ;
    const float scale = 0.125f;
    const int c1base = h * HDIM;

#pragma unroll
    for (int q = 0; q < 4; q++) {
        int fi = tid + q * 256;
        int r = fi >> 3, c = fi & 7;
        const __half* gq = &Q[(size_t)(rowg0 + q0 + r) * QK_COLS + c1base + c * 8];
        cp16(smBase + r * HROW + c * 16, gq);
        cp16(smBase + 2 * QTILE + r * HROW + c * 16, gq + THD);
    }
    auto load_stage = [&](int kt, int stg) {
        const int k0 = kt * 64;
        const unsigned base = smBase + 4 * QTILE + stg * ST_STRIDE;
#pragma unroll
        for (int q = 0; q < 2; q++) {
            int fi = tid + q * 256;
            int r = fi >> 3, c = fi & 7;
            const __half* gk = &K[(size_t)(rowg0 + k0 + r) * QK_COLS + c1base + c * 8];
            cp16(base + r * HROW + c * 16, gk);
            cp16(base + QTILE + r * HROW + c * 16, gk + THD);
            cp16(base + 2 * QTILE + r * HROW + c * 16,
                 &V[(size_t)(rowg0 + k0 + r) * THD + c1base + c * 8]);
        }
    };
    load_stage(0, 0);
    cpcommit();

    const unsigned aoff = (lane & 15) * HROW + (lane >> 4) * 16;
    const unsigned boff = ((lane & 7) + ((lane >> 4) << 3)) * HROW + ((lane >> 3) & 1) * 16;
    // trans-B mapping for V (rows = k(s), cols = n(d)): lanes 0-15 -> k rows, lane>>4 -> n chunk
    const unsigned boffT = (((lane & 7) + (((lane >> 3) & 1) << 3)) * HROW) + (lane >> 4) * 16;
    const unsigned aQw = smBase + br * (2 * QTILE) + mblk * 32 * HROW + aoff;

    float O[2][8][4];
#pragma unroll
    for (int mf = 0; mf < 2; mf++)
#pragma unroll
        for (int df = 0; df < 8; df++)
#pragma unroll
            for (int c = 0; c < 4; c++) O[mf][df][c] = 0.f;
    float mmx[2][2] = {{-1e30f, -1e30f}, {-1e30f, -1e30f}};
    float lsum[2][2] = {{0.f, 0.f}, {0.f, 0.f}};

    for (int kt = 0; kt < NKT; kt++) {
        if (kt + 1 < NKT) { load_stage(kt + 1, (kt + 1) & 1); cpcommit();
            asm volatile("cp.async.wait_group 1;"); }
        else { asm volatile("cp.async.wait_group 0;"); }
        __syncthreads();

        const unsigned stb = smBase + 4 * QTILE + (kt & 1) * ST_STRIDE;
        const unsigned kB = stb + br * QTILE + boff;
        const unsigned vB = stb + 2 * QTILE + boffT;

        float S[2][8][4];
#pragma unroll
        for (int mf = 0; mf < 2; mf++)
#pragma unroll
            for (int nf = 0; nf < 8; nf++)
#pragma unroll
                for (int c = 0; c < 4; c++) S[mf][nf][c] = 0.f;

#pragma unroll
        for (int p = 0; p < 4; p++) {
            unsigned A[2][4];
#pragma unroll
            for (int mf = 0; mf < 2; mf++)
                ldsm4(A[mf][0], A[mf][1], A[mf][2], A[mf][3],
                      aQw + mf * 16 * HROW + p * 32);
#pragma unroll
            for (int nb = 0; nb < 4; nb++) {
                unsigned Bf[4];
                ldsm4(Bf[0], Bf[1], Bf[2], Bf[3], kB + nb * 16 * HROW + p * 32);
#pragma unroll
                for (int mf = 0; mf < 2; mf++) {
                    mma16h(S[mf][2 * nb],     A[mf], Bf[0], Bf[1]);
                    mma16h(S[mf][2 * nb + 1], A[mf], Bf[2], Bf[3]);
                }
            }
        }

#pragma unroll
        for (int mf = 0; mf < 2; mf++) {
            float mx0 = -1e30f, mx1 = -1e30f;
#pragma unroll
            for (int nf = 0; nf < 8; nf++) {
                mx0 = fmaxf(mx0, fmaxf(S[mf][nf][0], S[mf][nf][1]));
                mx1 = fmaxf(mx1, fmaxf(S[mf][nf][2], S[mf][nf][3]));
            }
            mx0 = fmaxf(mx0, __shfl_xor_sync(0xffffffffu, mx0, 1));
            mx0 = fmaxf(mx0, __shfl_xor_sync(0xffffffffu, mx0, 2));
            mx1 = fmaxf(mx1, __shfl_xor_sync(0xffffffffu, mx1, 1));
            mx1 = fmaxf(mx1, __shfl_xor_sync(0xffffffffu, mx1, 2));
            float mn0 = fmaxf(mmx[mf][0], mx0 * scale);
            float mn1 = fmaxf(mmx[mf][1], mx1 * scale);
            float c0 = __expf(mmx[mf][0] - mn0);
            float c1 = __expf(mmx[mf][1] - mn1);
            float s0 = 0.f, s1 = 0.f;
#pragma unroll
            for (int nf = 0; nf < 8; nf++) {
                float p00 = __expf(S[mf][nf][0] * scale - mn0);
                float p01 = __expf(S[mf][nf][1] * scale - mn0);
                float p10 = __expf(S[mf][nf][2] * scale - mn1);
                float p11 = __expf(S[mf][nf][3] * scale - mn1);
                S[mf][nf][0] = p00; S[mf][nf][1] = p01;
                S[mf][nf][2] = p10; S[mf][nf][3] = p11;
                s0 += p00 + p01; s1 += p10 + p11;
            }
            s0 += __shfl_xor_sync(0xffffffffu, s0, 1);
            s0 += __shfl_xor_sync(0xffffffffu, s0, 2);
            s1 += __shfl_xor_sync(0xffffffffu, s1, 1);
            s1 += __shfl_xor_sync(0xffffffffu, s1, 2);
            lsum[mf][0] = lsum[mf][0] * c0 + s0;
            lsum[mf][1] = lsum[mf][1] * c1 + s1;
            mmx[mf][0] = mn0; mmx[mf][1] = mn1;
#pragma unroll
            for (int df = 0; df < 8; df++) {
                O[mf][df][0] *= c0; O[mf][df][1] *= c0;
                O[mf][df][2] *= c1; O[mf][df][3] *= c1;
            }
        }

#pragma unroll
        for (int p = 0; p < 4; p++) {
            unsigned PA[2][4];
#pragma unroll
            for (int mf = 0; mf < 2; mf++) {
                PA[mf][0] = pack2(S[mf][2 * p][0],     S[mf][2 * p][1]);
                PA[mf][1] = pack2(S[mf][2 * p][2],     S[mf][2 * p][3]);
                PA[mf][2] = pack2(S[mf][2 * p + 1][0], S[mf][2 * p + 1][1]);
                PA[mf][3] = pack2(S[mf][2 * p + 1][2], S[mf][2 * p + 1][3]);
            }
#pragma unroll
            for (int nb = 0; nb < 4; nb++) {
                unsigned Bf[4];
                ldsmT4(Bf[0], Bf[1], Bf[2], Bf[3], vB + p * 16 * HROW + nb * 32);
#pragma unroll
                for (int mf = 0; mf < 2; mf++) {
                    mma16h(O[mf][2 * nb],     PA[mf], Bf[0], Bf[1]);
                    mma16h(O[mf][2 * nb + 1], PA[mf], Bf[2], Bf[3]);
                }
            }
        }
        __syncthreads();
    }

    const float lam_init = lam_init_p[0];
    const float lam = __expf(lq1[h] * lk1[h]) - __expf(lq2[h] * lk2[h]) + lam_init;
    const float osc = 1.0f - lam_init;
    float* Ex = (float*)(smv + 4 * QTILE);

    if (br == 1) {
#pragma unroll
        for (int mf = 0; mf < 2; mf++) {
            float inv0 = lam / lsum[mf][0];
            float inv1 = lam / lsum[mf][1];
            int row0 = mblk * 32 + mf * 16 + g;
#pragma unroll
            for (int df = 0; df < 8; df++) {
                int col = df * 8 + 2 * t;
                *(float2*)&Ex[row0 * 68 + col] = make_float2(O[mf][df][0] * inv0, O[mf][df][1] * inv0);
                *(float2*)&Ex[(row0 + 8) * 68 + col] = make_float2(O[mf][df][2] * inv1, O[mf][df][3] * inv1);
            }
        }
    }
    __syncthreads();
    if (br == 0) {
#pragma unroll
        for (int mf = 0; mf < 2; mf++) {
#pragma unroll
            for (int half = 0; half < 2; half++) {
                float inv1 = 1.0f / lsum[mf][half];
                int lrow = mblk * 32 + mf * 16 + g + 8 * half;
                float v[16];
                float s = 0.f, sq = 0.f;
#pragma unroll
                for (int df = 0; df < 8; df++) {
                    float2 e = *(float2*)&Ex[lrow * 68 + df * 8 + 2 * t];
                    float a0 = O[mf][df][half * 2 + 0] * inv1 - e.x;
                    float a1 = O[mf][df][half * 2 + 1] * inv1 - e.y;
                    v[2 * df] = a0; v[2 * df + 1] = a1;
                    s += a0 + a1; sq += a0 * a0 + a1 * a1;
                }
                s  += __shfl_xor_sync(0xffffffffu, s, 1);
                s  += __shfl_xor_sync(0xffffffffu, s, 2);
                sq += __shfl_xor_sync(0xffffffffu, sq, 1);
                sq += __shfl_xor_sync(0xffffffffu, sq, 2);
                float mean = s * (1.0f / 64.0f);
                float var = sq * (1.0f / 64.0f) - mean * mean;
                float istd = rsqrtf(var + GN_EPS);
                size_t grow = (size_t)(rowg0 + q0 + lrow);
#pragma unroll
                for (int df = 0; df < 8; df++) {
                    int col = h * HDIM + df * 8 + 2 * t;
                    float2 gw = *(const float2*)&gnw[col];
                    float2 gb = *(const float2*)&gnb[col];
                    float o0 = ((v[2 * df]     - mean) * istd * gw.x + gb.x) * osc;
                    float o1 = ((v[2 * df + 1] - mean) * istd * gw.y + gb.y) * osc;
                    __half h0 = __float2half_rn(o0);
                    __half h1 = __float2half_rn(o1);
                    __half2 ph; ph.x = h0; ph.y = h1;
                    __half2 pl;
                    pl.x = __float2half_rn(o0 - __half2float(h0));
                    pl.y = __float2half_rn(o1 - __half2float(h1));
                    *(__half2*)&OutH[grow * THD + col] = ph;
                    *(__half2*)&OutL[grow * THD + col] = pl;
                }
            }
        }
    }
}

// ---------------- kernel_launch ----------------
extern "C" void kernel_launch(void* const* d_in, const int* in_sizes, int n_in,
                              void* d_out, int out_size)
{
    const float* x   = (const float*)d_in[0];
    const float* Wq  = (const float*)d_in[1];
    const float* Wk  = (const float*)d_in[2];
    const float* Wv  = (const float*)d_in[3];
    const float* Wo  = (const float*)d_in[4];
    const float* lq1 = (const float*)d_in[5];
    const float* lk1 = (const float*)d_in[6];
    const float* lq2 = (const float*)d_in[7];
    const float* lk2 = (const float*)d_in[8];
    const float* lam = (const float*)d_in[9];
    const float* gnw = (const float*)d_in[10];
    const float* gnb = (const float*)d_in[11];
    float* out = (float*)d_out;

    float *cosT, *sinT;
    __half *Qh, *Kh, *V16, *xh, *xl, *Wq16, *Wk16, *Wv16, *Wo16, *Ah, *Al;
    cudaGetSymbolAddress((void**)&Qh, g_Qh);
    cudaGetSymbolAddress((void**)&Kh, g_Kh);
    cudaGetSymbolAddress((void**)&V16, g_V16);
    cudaGetSymbolAddress((void**)&cosT, g_cosT);
    cudaGetSymbolAddress((void**)&sinT, g_sinT);
    cudaGetSymbolAddress((void**)&xh, g_xh);
    cudaGetSymbolAddress((void**)&xl, g_xl);
    cudaGetSymbolAddress((void**)&Wq16, g_Wq16);
    cudaGetSymbolAddress((void**)&Wk16, g_Wk16);
    cudaGetSymbolAddress((void**)&Wv16, g_Wv16);
    cudaGetSymbolAddress((void**)&Wo16, g_Wo16);
    cudaGetSymbolAddress((void**)&Ah, g_Ah);
    cudaGetSymbolAddress((void**)&Al, g_Al);

    cudaFuncSetAttribute(attn_v5_kernel, cudaFuncAttributeMaxDynamicSharedMemorySize, ATT_SMEM);
    cudaFuncSetAttribute(gemm_h2_kernel<__half, true>, cudaFuncAttributeMaxDynamicSharedMemorySize, GEMM_SMEM);
    cudaFuncSetAttribute(gemm_h2_kernel<__half, false>, cudaFuncAttributeMaxDynamicSharedMemorySize, GEMM_SMEM);
    cudaFuncSetAttribute(gemm_h2_kernel<float, false>, cudaFuncAttributeMaxDynamicSharedMemorySize, GEMM_SMEM);

    rope_tables_kernel<<<(SEQ * 32 + 255) / 256, 256>>>(cosT, sinT);
    split_h_kernel<<<(MROWS * DMODEL + 255) / 256, 256>>>(x, xh, xl, MROWS * DMODEL);
    conv_w_kernel<<<dim3((DMODEL * QK_COLS + 255) / 256, 4), 256>>>(
        Wq, Wk, Wv, Wo, Wq16, Wk16, Wv16, Wo16);

    gemm_h2_kernel<__half, true><<<dim3(QK_COLS / 128, MROWS / 128), 256, GEMM_SMEM>>>(
        xh, xl, Wq16, Qh, MROWS, QK_COLS, DMODEL, cosT, sinT);
    gemm_h2_kernel<__half, true><<<dim3(QK_COLS / 128, MROWS / 128), 256, GEMM_SMEM>>>(
        xh, xl, Wk16, Kh, MROWS, QK_COLS, DMODEL, cosT, sinT);
    gemm_h2_kernel<__half, false><<<dim3(THD / 128, MROWS / 128), 256, GEMM_SMEM>>>(
        xh, xl, Wv16, V16, MROWS, THD, DMODEL, cosT, sinT);

    attn_v5_kernel<<<dim3(SEQ / 128, BATCH * NHEAD), 256, ATT_SMEM>>>(
        Qh, Kh, V16, lq1, lk1, lq2, lk2, lam, gnw, gnb, Ah, Al);

    gemm_h2_kernel<float, false><<<dim3(DMODEL / 128, MROWS / 128), 256, GEMM_SMEM>>>(
        Ah, Al, Wo16, out, MROWS, DMODEL, THD, cosT, sinT);
}

// round 11
// speedup vs baseline: 2.9511x; 1.0218x over previous
#include <cuda_runtime.h>
#include <cuda_fp16.h>
#include <cstdint>
#include <math.h>

#define BATCH 2
#define SEQ   2048
#define DMODEL 1024
#define NHEAD 16
#define HDIM  64
#define THD   (NHEAD * HDIM)
#define MROWS (BATCH * SEQ)
#define QK_COLS (2 * THD)
#define GN_EPS 1e-5f

// ---------------- scratch ----------------
__device__ __half g_Qh[MROWS * QK_COLS];
__device__ __half g_Kh[MROWS * QK_COLS];
__device__ __half g_V16[MROWS * THD];
__device__ float g_cosT[SEQ * 32];
__device__ float g_sinT[SEQ * 32];
__device__ __half g_xh[MROWS * DMODEL],  g_xl[MROWS * DMODEL];
__device__ __half g_Wq16[DMODEL * QK_COLS];
__device__ __half g_Wk16[DMODEL * QK_COLS];
__device__ __half g_Wv16[DMODEL * THD];
__device__ __half g_Wo16[THD * DMODEL];
__device__ __half g_Ah[MROWS * THD], g_Al[MROWS * THD];

// ---------------- helpers ----------------
__device__ __forceinline__ void ldsm4(unsigned &r0, unsigned &r1, unsigned &r2, unsigned &r3, unsigned a) {
    asm volatile("ldmatrix.sync.aligned.m8n8.x4.shared.b16 {%0,%1,%2,%3}, [%4];"
        : "=r"(r0), "=r"(r1), "=r"(r2), "=r"(r3) : "r"(a));
}
__device__ __forceinline__ void ldsmT4(unsigned &r0, unsigned &r1, unsigned &r2, unsigned &r3, unsigned a) {
    asm volatile("ldmatrix.sync.aligned.m8n8.x4.trans.shared.b16 {%0,%1,%2,%3}, [%4];"
        : "=r"(r0), "=r"(r1), "=r"(r2), "=r"(r3) : "r"(a));
}
__device__ __forceinline__ void mma16h(float* c, const unsigned* a, unsigned b0, unsigned b1) {
    asm volatile("mma.sync.aligned.m16n8k16.row.col.f32.f16.f16.f32 "
        "{%0,%1,%2,%3},{%4,%5,%6,%7},{%8,%9},{%0,%1,%2,%3};"
        : "+f"(c[0]), "+f"(c[1]), "+f"(c[2]), "+f"(c[3])
        : "r"(a[0]), "r"(a[1]), "r"(a[2]), "r"(a[3]), "r"(b0), "r"(b1));
}
__device__ __forceinline__ void cp16(unsigned s, const void* g) {
    asm volatile("cp.async.cg.shared.global [%0], [%1], 16;" :: "r"(s), "l"(g));
}
__device__ __forceinline__ void cpcommit() { asm volatile("cp.async.commit_group;"); }
__device__ __forceinline__ unsigned pack2(float a, float b) {
    __half2 h = __floats2half2_rn(a, b);
    return *(unsigned*)&h;
}

// ---------------- small kernels ----------------
__global__ void split_h_kernel(const float* __restrict__ s, __half* __restrict__ h,
                               __half* __restrict__ l, int n) {
    int i = blockIdx.x * blockDim.x + threadIdx.x;
    if (i >= n) return;
    float v = s[i];
    __half hv = __float2half_rn(v);
    h[i] = hv;
    l[i] = __float2half_rn(v - __half2float(hv));
}

__global__ void conv_w_kernel(const float* __restrict__ Wq, const float* __restrict__ Wk,
                              const float* __restrict__ Wv, const float* __restrict__ Wo,
                              __half* __restrict__ q16, __half* __restrict__ k16,
                              __half* __restrict__ v16, __half* __restrict__ o16) {
    int which = blockIdx.y;
    const float* s;
    __half* d;
    int n;
    if (which == 0)      { s = Wq; d = q16; n = DMODEL * QK_COLS; }
    else if (which == 1) { s = Wk; d = k16; n = DMODEL * QK_COLS; }
    else if (which == 2) { s = Wv; d = v16; n = DMODEL * THD; }
    else                 { s = Wo; d = o16; n = THD * DMODEL; }
    int i = blockIdx.x * blockDim.x + threadIdx.x;
    if (i < n) d[i] = __float2half_rn(s[i]);
}

__global__ void rope_tables_kernel(float* __restrict__ cosT, float* __restrict__ sinT) {
    int i = blockIdx.x * blockDim.x + threadIdx.x;
    if (i >= SEQ * 32) return;
    int t = i >> 5, j = i & 31;
    double invf = pow(10000.0, -(double)(2 * j) / 64.0);
    float f = (float)t * (float)invf;
    cosT[i] = (float)cos((double)f);
    sinT[i] = (float)sin((double)f);
}

// ---------------- fp16 2-term GEMM, 3-stage pipeline, fused RoPE ----------------
// QKMODE: blockIdx.z selects (Wq->Qh) / (Wk->Kh), both with RoPE epilogue.
#define GA_ST 40
#define GB_ST 136
#define O_AH 0
#define O_AL (128 * GA_ST)
#define O_B  (2 * 128 * GA_ST)
#define STG_EL (O_B + 32 * GB_ST)          // 14592 halves = 29184 B
#define GEMM_SMEM (3 * STG_EL * 2)         // 87552 B

template <typename TOut, bool ROPE, bool QKMODE>
__global__ __launch_bounds__(256) void gemm_h2_kernel(
    const __half* __restrict__ Ah, const __half* __restrict__ Al,
    const __half* __restrict__ B0, const __half* __restrict__ B1,
    TOut* __restrict__ C0, TOut* __restrict__ C1, int M, int N, int K,
    const float* __restrict__ cosT, const float* __restrict__ sinT)
{
    extern __shared__ __half smb[];
    const unsigned smB = (unsigned)__cvta_generic_to_shared(smb);
    const int tid = threadIdx.x, wid = tid >> 5, lane = tid & 31;
    const int wm = wid & 3, wn = wid >> 2;
    const int g = lane >> 2, t = lane & 3;
    const int bm0 = blockIdx.y * 128, bn0 = blockIdx.x * 128;
    const __half* B = (QKMODE && blockIdx.z) ? B1 : B0;
    TOut* C = (QKMODE && blockIdx.z) ? C1 : C0;

    float acc[2][8][4];
#pragma unroll
    for (int i = 0; i < 2; i++)
#pragma unroll
        for (int j = 0; j < 8; j++)
#pragma unroll
            for (int c = 0; c < 4; c++) acc[i][j][c] = 0.f;

    auto load_stage = [&](int kt, int stg) {
        const int k0 = kt * 32;
        const unsigned sb = smB + stg * (STG_EL * 2);
#pragma unroll
        for (int q = 0; q < 4; q++) {
            int fi = tid + q * 256;
            int u = fi >> 9, idx = fi & 511;
            int r = idx >> 2, c = (idx & 3) * 8;
            cp16(sb + ((u ? O_AL : O_AH) + r * GA_ST + c) * 2,
                 (u ? Al : Ah) + (size_t)(bm0 + r) * K + k0 + c);
        }
#pragma unroll
        for (int q = 0; q < 2; q++) {
            int fi = tid + q * 256;
            int r = fi >> 4, c = (fi & 15) * 8;
            cp16(sb + (O_B + r * GB_ST + c) * 2,
                 B + (size_t)(k0 + r) * N + bn0 + c);
        }
        cpcommit();
    };
    const int NT = K >> 5;
    load_stage(0, 0);
    load_stage(1, 1);

    const unsigned aoff = ((lane & 15) * GA_ST + (lane >> 4) * 8) * 2;
    const unsigned boff = (((((lane >> 3) & 1) * 8) + (lane & 7)) * GB_ST + (lane >> 4) * 8) * 2;

    int stg = 0;
    for (int kt = 0; kt < NT; kt++) {
        if (kt < NT - 1) asm volatile("cp.async.wait_group 1;");
        else             asm volatile("cp.async.wait_group 0;");
        __syncthreads();
        if (kt + 2 < NT) load_stage(kt + 2, (stg + 2) % 3);

        const unsigned sb = smB + stg * (STG_EL * 2);
#pragma unroll
        for (int ks = 0; ks < 2; ks++) {
            unsigned AH[2][4], AL[2][4];
#pragma unroll
            for (int mf = 0; mf < 2; mf++) {
                unsigned a = sb + (wm * 32 + mf * 16) * GA_ST * 2 + aoff + ks * 32;
                ldsm4(AH[mf][0], AH[mf][1], AH[mf][2], AH[mf][3], a + O_AH * 2);
                ldsm4(AL[mf][0], AL[mf][1], AL[mf][2], AL[mf][3], a + O_AL * 2);
            }
#pragma unroll
            for (int np = 0; np < 4; np++) {
                unsigned bofs = sb + boff + ks * 16 * GB_ST * 2 + O_B * 2 + (wn * 64 + np * 16) * 2;
                unsigned TB[4];
                ldsmT4(TB[0], TB[1], TB[2], TB[3], bofs);
#pragma unroll
                for (int hh = 0; hh < 2; hh++) {
                    int nf = np * 2 + hh;
#pragma unroll
                    for (int mf = 0; mf < 2; mf++) {
                        mma16h(acc[mf][nf], AH[mf], TB[2 * hh], TB[2 * hh + 1]);
                        mma16h(acc[mf][nf], AL[mf], TB[2 * hh], TB[2 * hh + 1]);
                    }
                }
            }
        }
        stg = (stg + 1) % 3;
    }

#pragma unroll
    for (int mf = 0; mf < 2; mf++) {
#pragma unroll
        for (int half = 0; half < 2; half++) {
            size_t row = (size_t)(bm0 + wm * 32 + mf * 16 + g + 8 * half);
            if (ROPE) {
                int s = (int)(row & (SEQ - 1));
#pragma unroll
                for (int nf = 0; nf < 4; nf++) {
                    int d = nf * 8 + 2 * t;
                    float2 cc = *(const float2*)&cosT[s * 32 + d];
                    float2 ss = *(const float2*)&sinT[s * 32 + d];
                    float lo0 = acc[mf][nf][2 * half], lo1 = acc[mf][nf][2 * half + 1];
                    float hi0 = acc[mf][nf + 4][2 * half], hi1 = acc[mf][nf + 4][2 * half + 1];
                    __half* Ch = (__half*)C;
                    int c0 = bn0 + wn * 64 + d;
                    *(__half2*)&Ch[row * N + c0] =
                        __floats2half2_rn(lo0 * cc.x - hi0 * ss.x, lo1 * cc.y - hi1 * ss.y);
                    *(__half2*)&Ch[row * N + c0 + 32] =
                        __floats2half2_rn(hi0 * cc.x + lo0 * ss.x, hi1 * cc.y + lo1 * ss.y);
                }
            } else {
#pragma unroll
                for (int nf = 0; nf < 8; nf++) {
                    int c = bn0 + wn * 64 + nf * 8 + 2 * t;
                    if (sizeof(TOut) == 4) {
                        float* Cf = (float*)C;
                        *(float2*)&Cf[row * N + c] =
                            make_float2(acc[mf][nf][2 * half], acc[mf][nf][2 * half + 1]);
                    } else {
                        __half* Ch = (__half*)C;
                        *(__half2*)&Ch[row * N + c] =
                            __floats2half2_rn(acc[mf][nf][2 * half], acc[mf][nf][2 * half + 1]);
                    }
                }
            }
        }
    }
}

// ---------------- fp16 differential flash attention v5 (unchanged) ----------------
#define HROW 144
#define QTILE 9216
#define ST_STRIDE 27648
#define ATT_SMEM (4 * QTILE + 2 * ST_STRIDE)   // 92160
#define NKT (SEQ / 64)

__global__ __launch_bounds__(256) void attn_v5_kernel(
    const __half* __restrict__ Q, const __half* __restrict__ K, const __half* __restrict__ V,
    const float* __restrict__ lq1, const float* __restrict__ lk1,
    const float* __restrict__ lq2, const float* __restrict__ lk2,
    const float* __restrict__ lam_init_p,
    const float* __restrict__ gnw, const float* __restrict__ gnb,
    __half* __restrict__ OutH, __half* __restrict__ OutL)
{
    extern __shared__ char smv[];
    const unsigned smBase = (unsigned)__cvta_generic_to_shared(smv);
    const int tid = threadIdx.x, wid = tid >> 5, lane = tid & 31;
    const int br = wid >> 2, mblk = wid & 3;
    const int g = lane >> 2, t = lane & 3;
    const int bh = blockIdx.y, b = bh >> 4, h = bh & 15;
    const int q0 = blockIdx.x * 128;
    const int rowg0 = b * SEQ;
    const float scale = 0.125f;
    const int c1base = h * HDIM;

#pragma unroll
    for (int q = 0; q < 4; q++) {
        int fi = tid + q * 256;
        int r = fi >> 3, c = fi & 7;
        const __half* gq = &Q[(size_t)(rowg0 + q0 + r) * QK_COLS + c1base + c * 8];
        cp16(smBase + r * HROW + c * 16, gq);
        cp16(smBase + 2 * QTILE + r * HROW + c * 16, gq + THD);
    }
    auto load_stage = [&](int kt, int stg) {
        const int k0 = kt * 64;
        const unsigned base = smBase + 4 * QTILE + stg * ST_STRIDE;
#pragma unroll
        for (int q = 0; q < 2; q++) {
            int fi = tid + q * 256;
            int r = fi >> 3, c = fi & 7;
            const __half* gk = &K[(size_t)(rowg0 + k0 + r) * QK_COLS + c1base + c * 8];
            cp16(base + r * HROW + c * 16, gk);
            cp16(base + QTILE + r * HROW + c * 16, gk + THD);
            cp16(base + 2 * QTILE + r * HROW + c * 16,
                 &V[(size_t)(rowg0 + k0 + r) * THD + c1base + c * 8]);
        }
    };
    load_stage(0, 0);
    cpcommit();

    const unsigned aoff = (lane & 15) * HROW + (lane >> 4) * 16;
    const unsigned boff = ((lane & 7) + ((lane >> 4) << 3)) * HROW + ((lane >> 3) & 1) * 16;
    const unsigned boffT = (((lane & 7) + (((lane >> 3) & 1) << 3)) * HROW) + (lane >> 4) * 16;
    const unsigned aQw = smBase + br * (2 * QTILE) + mblk * 32 * HROW + aoff;

    float O[2][8][4];
#pragma unroll
    for (int mf = 0; mf < 2; mf++)
#pragma unroll
        for (int df = 0; df < 8; df++)
#pragma unroll
            for (int c = 0; c < 4; c++) O[mf][df][c] = 0.f;
    float mmx[2][2] = {{-1e30f, -1e30f}, {-1e30f, -1e30f}};
    float lsum[2][2] = {{0.f, 0.f}, {0.f, 0.f}};

    for (int kt = 0; kt < NKT; kt++) {
        if (kt + 1 < NKT) { load_stage(kt + 1, (kt + 1) & 1); cpcommit();
            asm volatile("cp.async.wait_group 1;"); }
        else { asm volatile("cp.async.wait_group 0;"); }
        __syncthreads();

        const unsigned stb = smBase + 4 * QTILE + (kt & 1) * ST_STRIDE;
        const unsigned kB = stb + br * QTILE + boff;
        const unsigned vB = stb + 2 * QTILE + boffT;

        float S[2][8][4];
#pragma unroll
        for (int mf = 0; mf < 2; mf++)
#pragma unroll
            for (int nf = 0; nf < 8; nf++)
#pragma unroll
                for (int c = 0; c < 4; c++) S[mf][nf][c] = 0.f;

#pragma unroll
        for (int p = 0; p < 4; p++) {
            unsigned A[2][4];
#pragma unroll
            for (int mf = 0; mf < 2; mf++)
                ldsm4(A[mf][0], A[mf][1], A[mf][2], A[mf][3],
                      aQw + mf * 16 * HROW + p * 32);
#pragma unroll
            for (int nb = 0; nb < 4; nb++) {
                unsigned Bf[4];
                ldsm4(Bf[0], Bf[1], Bf[2], Bf[3], kB + nb * 16 * HROW + p * 32);
#pragma unroll
                for (int mf = 0; mf < 2; mf++) {
                    mma16h(S[mf][2 * nb],     A[mf], Bf[0], Bf[1]);
                    mma16h(S[mf][2 * nb + 1], A[mf], Bf[2], Bf[3]);
                }
            }
        }

#pragma unroll
        for (int mf = 0; mf < 2; mf++) {
            float mx0 = -1e30f, mx1 = -1e30f;
#pragma unroll
            for (int nf = 0; nf < 8; nf++) {
                mx0 = fmaxf(mx0, fmaxf(S[mf][nf][0], S[mf][nf][1]));
                mx1 = fmaxf(mx1, fmaxf(S[mf][nf][2], S[mf][nf][3]));
            }
            mx0 = fmaxf(mx0, __shfl_xor_sync(0xffffffffu, mx0, 1));
            mx0 = fmaxf(mx0, __shfl_xor_sync(0xffffffffu, mx0, 2));
            mx1 = fmaxf(mx1, __shfl_xor_sync(0xffffffffu, mx1, 1));
            mx1 = fmaxf(mx1, __shfl_xor_sync(0xffffffffu, mx1, 2));
            float mn0 = fmaxf(mmx[mf][0], mx0 * scale);
            float mn1 = fmaxf(mmx[mf][1], mx1 * scale);
            float c0 = __expf(mmx[mf][0] - mn0);
            float c1 = __expf(mmx[mf][1] - mn1);
            float s0 = 0.f, s1 = 0.f;
#pragma unroll
            for (int nf = 0; nf < 8; nf++) {
                float p00 = __expf(S[mf][nf][0] * scale - mn0);
                float p01 = __expf(S[mf][nf][1] * scale - mn0);
                float p10 = __expf(S[mf][nf][2] * scale - mn1);
                float p11 = __expf(S[mf][nf][3] * scale - mn1);
                S[mf][nf][0] = p00; S[mf][nf][1] = p01;
                S[mf][nf][2] = p10; S[mf][nf][3] = p11;
                s0 += p00 + p01; s1 += p10 + p11;
            }
            s0 += __shfl_xor_sync(0xffffffffu, s0, 1);
            s0 += __shfl_xor_sync(0xffffffffu, s0, 2);
            s1 += __shfl_xor_sync(0xffffffffu, s1, 1);
            s1 += __shfl_xor_sync(0xffffffffu, s1, 2);
            lsum[mf][0] = lsum[mf][0] * c0 + s0;
            lsum[mf][1] = lsum[mf][1] * c1 + s1;
            mmx[mf][0] = mn0; mmx[mf][1] = mn1;
#pragma unroll
            for (int df = 0; df < 8; df++) {
                O[mf][df][0] *= c0; O[mf][df][1] *= c0;
                O[mf][df][2] *= c1; O[mf][df][3] *= c1;
            }
        }

#pragma unroll
        for (int p = 0; p < 4; p++) {
            unsigned PA[2][4];
#pragma unroll
            for (int mf = 0; mf < 2; mf++) {
                PA[mf][0] = pack2(S[mf][2 * p][0],     S[mf][2 * p][1]);
                PA[mf][1] = pack2(S[mf][2 * p][2],     S[mf][2 * p][3]);
                PA[mf][2] = pack2(S[mf][2 * p + 1][0], S[mf][2 * p + 1][1]);
                PA[mf][3] = pack2(S[mf][2 * p + 1][2], S[mf][2 * p + 1][3]);
            }
#pragma unroll
            for (int nb = 0; nb < 4; nb++) {
                unsigned Bf[4];
                ldsmT4(Bf[0], Bf[1], Bf[2], Bf[3], vB + p * 16 * HROW + nb * 32);
#pragma unroll
                for (int mf = 0; mf < 2; mf++) {
                    mma16h(O[mf][2 * nb],     PA[mf], Bf[0], Bf[1]);
                    mma16h(O[mf][2 * nb + 1], PA[mf], Bf[2], Bf[3]);
                }
            }
        }
        __syncthreads();
    }

    const float lam_init = lam_init_p[0];
    const float lam = __expf(lq1[h] * lk1[h]) - __expf(lq2[h] * lk2[h]) + lam_init;
    const float osc = 1.0f - lam_init;
    float* Ex = (float*)(smv + 4 * QTILE);

    if (br == 1) {
#pragma unroll
        for (int mf = 0; mf < 2; mf++) {
            float inv0 = lam / lsum[mf][0];
            float inv1 = lam / lsum[mf][1];
            int row0 = mblk * 32 + mf * 16 + g;
#pragma unroll
            for (int df = 0; df < 8; df++) {
                int col = df * 8 + 2 * t;
                *(float2*)&Ex[row0 * 68 + col] = make_float2(O[mf][df][0] * inv0, O[mf][df][1] * inv0);
                *(float2*)&Ex[(row0 + 8) * 68 + col] = make_float2(O[mf][df][2] * inv1, O[mf][df][3] * inv1);
            }
        }
    }
    __syncthreads();
    if (br == 0) {
#pragma unroll
        for (int mf = 0; mf < 2; mf++) {
#pragma unroll
            for (int half = 0; half < 2; half++) {
                float inv1 = 1.0f / lsum[mf][half];
                int lrow = mblk * 32 + mf * 16 + g + 8 * half;
                float v[16];
                float s = 0.f, sq = 0.f;
#pragma unroll
                for (int df = 0; df < 8; df++) {
                    float2 e = *(float2*)&Ex[lrow * 68 + df * 8 + 2 * t];
                    float a0 = O[mf][df][half * 2 + 0] * inv1 - e.x;
                    float a1 = O[mf][df][half * 2 + 1] * inv1 - e.y;
                    v[2 * df] = a0; v[2 * df + 1] = a1;
                    s += a0 + a1; sq += a0 * a0 + a1 * a1;
                }
                s  += __shfl_xor_sync(0xffffffffu, s, 1);
                s  += __shfl_xor_sync(0xffffffffu, s, 2);
                sq += __shfl_xor_sync(0xffffffffu, sq, 1);
                sq += __shfl_xor_sync(0xffffffffu, sq, 2);
                float mean = s * (1.0f / 64.0f);
                float var = sq * (1.0f / 64.0f) - mean * mean;
                float istd = rsqrtf(var + GN_EPS);
                size_t grow = (size_t)(rowg0 + q0 + lrow);
#pragma unroll
                for (int df = 0; df < 8; df++) {
                    int col = h * HDIM + df * 8 + 2 * t;
                    float2 gw = *(const float2*)&gnw[col];
                    float2 gb = *(const float2*)&gnb[col];
                    float o0 = ((v[2 * df]     - mean) * istd * gw.x + gb.x) * osc;
                    float o1 = ((v[2 * df + 1] - mean) * istd * gw.y + gb.y) * osc;
                    __half h0 = __float2half_rn(o0);
                    __half h1 = __float2half_rn(o1);
                    __half2 ph; ph.x = h0; ph.y = h1;
                    __half2 pl;
                    pl.x = __float2half_rn(o0 - __half2float(h0));
                    pl.y = __float2half_rn(o1 - __half2float(h1));
                    *(__half2*)&OutH[grow * THD + col] = ph;
                    *(__half2*)&OutL[grow * THD + col] = pl;
                }
            }
        }
    }
}

// ---------------- kernel_launch ----------------
extern "C" void kernel_launch(void* const* d_in, const int* in_sizes, int n_in,
                              void* d_out, int out_size)
{
    const float* x   = (const float*)d_in[0];
    const float* Wq  = (const float*)d_in[1];
    const float* Wk  = (const float*)d_in[2];
    const float* Wv  = (const float*)d_in[3];
    const float* Wo  = (const float*)d_in[4];
    const float* lq1 = (const float*)d_in[5];
    const float* lk1 = (const float*)d_in[6];
    const float* lq2 = (const float*)d_in[7];
    const float* lk2 = (const float*)d_in[8];
    const float* lam = (const float*)d_in[9];
    const float* gnw = (const float*)d_in[10];
    const float* gnb = (const float*)d_in[11];
    float* out = (float*)d_out;

    float *cosT, *sinT;
    __half *Qh, *Kh, *V16, *xh, *xl, *Wq16, *Wk16, *Wv16, *Wo16, *Ah, *Al;
    cudaGetSymbolAddress((void**)&Qh, g_Qh);
    cudaGetSymbolAddress((void**)&Kh, g_Kh);
    cudaGetSymbolAddress((void**)&V16, g_V16);
    cudaGetSymbolAddress((void**)&cosT, g_cosT);
    cudaGetSymbolAddress((void**)&sinT, g_sinT);
    cudaGetSymbolAddress((void**)&xh, g_xh);
    cudaGetSymbolAddress((void**)&xl, g_xl);
    cudaGetSymbolAddress((void**)&Wq16, g_Wq16);
    cudaGetSymbolAddress((void**)&Wk16, g_Wk16);
    cudaGetSymbolAddress((void**)&Wv16, g_Wv16);
    cudaGetSymbolAddress((void**)&Wo16, g_Wo16);
    cudaGetSymbolAddress((void**)&Ah, g_Ah);
    cudaGetSymbolAddress((void**)&Al, g_Al);

    cudaFuncSetAttribute(attn_v5_kernel, cudaFuncAttributeMaxDynamicSharedMemorySize, ATT_SMEM);
    cudaFuncSetAttribute((const void*)gemm_h2_kernel<__half, true, true>,
                         cudaFuncAttributeMaxDynamicSharedMemorySize, GEMM_SMEM);
    cudaFuncSetAttribute((const void*)gemm_h2_kernel<__half, false, false>,
                         cudaFuncAttributeMaxDynamicSharedMemorySize, GEMM_SMEM);
    cudaFuncSetAttribute((const void*)gemm_h2_kernel<float, false, false>,
                         cudaFuncAttributeMaxDynamicSharedMemorySize, GEMM_SMEM);

    rope_tables_kernel<<<(SEQ * 32 + 255) / 256, 256>>>(cosT, sinT);
    split_h_kernel<<<(MROWS * DMODEL + 255) / 256, 256>>>(x, xh, xl, MROWS * DMODEL);
    conv_w_kernel<<<dim3((DMODEL * QK_COLS + 255) / 256, 4), 256>>>(
        Wq, Wk, Wv, Wo, Wq16, Wk16, Wv16, Wo16);

    // Q + K projections in one launch (grid.z picks weight/output), fused RoPE
    gemm_h2_kernel<__half, true, true>
        <<<dim3(QK_COLS / 128, MROWS / 128, 2), 256, GEMM_SMEM>>>(
        xh, xl, Wq16, Wk16, Qh, Kh, MROWS, QK_COLS, DMODEL, cosT, sinT);
    gemm_h2_kernel<__half, false, false>
        <<<dim3(THD / 128, MROWS / 128), 256, GEMM_SMEM>>>(
        xh, xl, Wv16, Wv16, V16, V16, MROWS, THD, DMODEL, cosT, sinT);

    attn_v5_kernel<<<dim3(SEQ / 128, BATCH * NHEAD), 256, ATT_SMEM>>>(
        Qh, Kh, V16, lq1, lk1, lq2, lk2, lam, gnw, gnb, Ah, Al);

    gemm_h2_kernel<float, false, false>
        <<<dim3(DMODEL / 128, MROWS / 128), 256, GEMM_SMEM>>>(
        Ah, Al, Wo16, Wo16, out, out, MROWS, DMODEL, THD, cosT, sinT);
}

// round 13
// speedup vs baseline: 3.2117x; 1.0883x over previous
#include <cuda_runtime.h>
#include <cuda_fp16.h>
#include <cstdint>
#include <math.h>

#define BATCH 2
#define SEQ   2048
#define DMODEL 1024
#define NHEAD 16
#define HDIM  64
#define THD   (NHEAD * HDIM)
#define MROWS (BATCH * SEQ)
#define QK_COLS (2 * THD)
#define GN_EPS 1e-5f
#define QSCALE_F 0.18033688f   // 0.125 * log2(e)

// ---------------- scratch ----------------
__device__ __half g_Qh[MROWS * QK_COLS];
__device__ __half g_Kh[MROWS * QK_COLS];
__device__ __half g_V16[MROWS * THD];
__device__ float g_cosT[SEQ * 32];
__device__ float g_sinT[SEQ * 32];
__device__ __half g_xh[MROWS * DMODEL],  g_xl[MROWS * DMODEL];
__device__ __half g_Wq16[DMODEL * QK_COLS];
__device__ __half g_Wk16[DMODEL * QK_COLS];
__device__ __half g_Wv16[DMODEL * THD];
__device__ __half g_Wo16[THD * DMODEL];
__device__ __half g_Ah[MROWS * THD], g_Al[MROWS * THD];

// ---------------- helpers ----------------
__device__ __forceinline__ void ldsm4(unsigned &r0, unsigned &r1, unsigned &r2, unsigned &r3, unsigned a) {
    asm volatile("ldmatrix.sync.aligned.m8n8.x4.shared.b16 {%0,%1,%2,%3}, [%4];"
        : "=r"(r0), "=r"(r1), "=r"(r2), "=r"(r3) : "r"(a));
}
__device__ __forceinline__ void ldsmT4(unsigned &r0, unsigned &r1, unsigned &r2, unsigned &r3, unsigned a) {
    asm volatile("ldmatrix.sync.aligned.m8n8.x4.trans.shared.b16 {%0,%1,%2,%3}, [%4];"
        : "=r"(r0), "=r"(r1), "=r"(r2), "=r"(r3) : "r"(a));
}
__device__ __forceinline__ void mma16h(float* c, const unsigned* a, unsigned b0, unsigned b1) {
    asm volatile("mma.sync.aligned.m16n8k16.row.col.f32.f16.f16.f32 "
        "{%0,%1,%2,%3},{%4,%5,%6,%7},{%8,%9},{%0,%1,%2,%3};"
        : "+f"(c[0]), "+f"(c[1]), "+f"(c[2]), "+f"(c[3])
        : "r"(a[0]), "r"(a[1]), "r"(a[2]), "r"(a[3]), "r"(b0), "r"(b1));
}
__device__ __forceinline__ void cp16(unsigned s, const void* g) {
    asm volatile("cp.async.cg.shared.global [%0], [%1], 16;" :: "r"(s), "l"(g));
}
__device__ __forceinline__ void cpcommit() { asm volatile("cp.async.commit_group;"); }
__device__ __forceinline__ unsigned pack2(float a, float b) {
    __half2 h = __floats2half2_rn(a, b);
    return *(unsigned*)&h;
}

// ---------------- small kernels ----------------
__global__ void split_h_kernel(const float* __restrict__ s, __half* __restrict__ h,
                               __half* __restrict__ l, int n) {
    int i = blockIdx.x * blockDim.x + threadIdx.x;
    if (i >= n) return;
    float v = s[i];
    __half hv = __float2half_rn(v);
    h[i] = hv;
    l[i] = __float2half_rn(v - __half2float(hv));
}

__global__ void conv_w_kernel(const float* __restrict__ Wq, const float* __restrict__ Wk,
                              const float* __restrict__ Wv, const float* __restrict__ Wo,
                              __half* __restrict__ q16, __half* __restrict__ k16,
                              __half* __restrict__ v16, __half* __restrict__ o16) {
    int which = blockIdx.y;
    const float* s;
    __half* d;
    int n;
    if (which == 0)      { s = Wq; d = q16; n = DMODEL * QK_COLS; }
    else if (which == 1) { s = Wk; d = k16; n = DMODEL * QK_COLS; }
    else if (which == 2) { s = Wv; d = v16; n = DMODEL * THD; }
    else                 { s = Wo; d = o16; n = THD * DMODEL; }
    int i = blockIdx.x * blockDim.x + threadIdx.x;
    if (i < n) d[i] = __float2half_rn(s[i]);
}

__global__ void rope_tables_kernel(float* __restrict__ cosT, float* __restrict__ sinT) {
    int i = blockIdx.x * blockDim.x + threadIdx.x;
    if (i >= SEQ * 32) return;
    int t = i >> 5, j = i & 31;
    double invf = pow(10000.0, -(double)(2 * j) / 64.0);
    float f = (float)t * (float)invf;
    cosT[i] = (float)cos((double)f);
    sinT[i] = (float)sin((double)f);
}

// ---------------- fp16 2-term GEMM, BK=64, 2-stage, one sync/iter ----------------
// QKMODE: blockIdx.z selects (Wq->Qh, scaled by QSCALE) / (Wk->Kh).
#define GA_ST 72                           // halves per A row (144 B)
#define GB_ST 136
#define O_AH 0
#define O_AL (128 * GA_ST)                 // 9216
#define O_B  (2 * 128 * GA_ST)             // 18432
#define STG_EL (O_B + 64 * GB_ST)          // 27136 halves = 54272 B
#define GEMM_SMEM (2 * STG_EL * 2)         // 108544 B

template <typename TOut, bool ROPE, bool QKMODE>
__global__ __launch_bounds__(256) void gemm_h2_kernel(
    const __half* __restrict__ Ah, const __half* __restrict__ Al,
    const __half* __restrict__ B0, const __half* __restrict__ B1,
    TOut* __restrict__ C0, TOut* __restrict__ C1, int M, int N, int K,
    const float* __restrict__ cosT, const float* __restrict__ sinT)
{
    extern __shared__ __half smb[];
    const unsigned smB = (unsigned)__cvta_generic_to_shared(smb);
    const int tid = threadIdx.x, wid = tid >> 5, lane = tid & 31;
    const int wm = wid & 3, wn = wid >> 2;
    const int g = lane >> 2, t = lane & 3;
    const int bm0 = blockIdx.y * 128, bn0 = blockIdx.x * 128;
    const __half* B = (QKMODE && blockIdx.z) ? B1 : B0;
    TOut* C = (QKMODE && blockIdx.z) ? C1 : C0;
    const float oscale = (QKMODE && blockIdx.z == 0) ? QSCALE_F : 1.0f;

    float acc[2][8][4];
#pragma unroll
    for (int i = 0; i < 2; i++)
#pragma unroll
        for (int j = 0; j < 8; j++)
#pragma unroll
            for (int c = 0; c < 4; c++) acc[i][j][c] = 0.f;

    auto load_stage = [&](int kt, int stg) {
        const int k0 = kt * 64;
        const unsigned sb = smB + stg * (STG_EL * 2);
#pragma unroll
        for (int q = 0; q < 8; q++) {
            int fi = tid + q * 256;                    // 0..2047
            int u = fi >> 10, idx = fi & 1023;
            int r = idx >> 3, c = (idx & 7) * 8;
            cp16(sb + ((u ? O_AL : O_AH) + r * GA_ST + c) * 2,
                 (u ? Al : Ah) + (size_t)(bm0 + r) * K + k0 + c);
        }
#pragma unroll
        for (int q = 0; q < 4; q++) {
            int fi = tid + q * 256;                    // 0..1023
            int r = fi >> 4, c = (fi & 15) * 8;        // 64 rows x 16 chunks
            cp16(sb + (O_B + r * GB_ST + c) * 2,
                 B + (size_t)(k0 + r) * N + bn0 + c);
        }
        cpcommit();
    };
    const int NT = K >> 6;
    load_stage(0, 0);

    const unsigned aoff = ((lane & 15) * GA_ST + (lane >> 4) * 8) * 2;
    const unsigned boff = (((((lane >> 3) & 1) * 8) + (lane & 7)) * GB_ST + (lane >> 4) * 8) * 2;

    for (int kt = 0; kt < NT; kt++) {
        asm volatile("cp.async.wait_group 0;");
        __syncthreads();
        if (kt + 1 < NT) load_stage(kt + 1, (kt + 1) & 1);

        const unsigned sb = smB + (kt & 1) * (STG_EL * 2);
#pragma unroll
        for (int ks = 0; ks < 4; ks++) {
            unsigned AH[2][4], AL[2][4];
#pragma unroll
            for (int mf = 0; mf < 2; mf++) {
                unsigned a = sb + (wm * 32 + mf * 16) * GA_ST * 2 + aoff + ks * 32;
                ldsm4(AH[mf][0], AH[mf][1], AH[mf][2], AH[mf][3], a + O_AH * 2);
                ldsm4(AL[mf][0], AL[mf][1], AL[mf][2], AL[mf][3], a + O_AL * 2);
            }
#pragma unroll
            for (int np = 0; np < 4; np++) {
                unsigned bofs = sb + boff + ks * 16 * GB_ST * 2 + O_B * 2 + (wn * 64 + np * 16) * 2;
                unsigned TB[4];
                ldsmT4(TB[0], TB[1], TB[2], TB[3], bofs);
#pragma unroll
                for (int hh = 0; hh < 2; hh++) {
                    int nf = np * 2 + hh;
#pragma unroll
                    for (int mf = 0; mf < 2; mf++) {
                        mma16h(acc[mf][nf], AH[mf], TB[2 * hh], TB[2 * hh + 1]);
                        mma16h(acc[mf][nf], AL[mf], TB[2 * hh], TB[2 * hh + 1]);
                    }
                }
            }
        }
    }

#pragma unroll
    for (int mf = 0; mf < 2; mf++) {
#pragma unroll
        for (int half = 0; half < 2; half++) {
            size_t row = (size_t)(bm0 + wm * 32 + mf * 16 + g + 8 * half);
            if (ROPE) {
                int s = (int)(row & (SEQ - 1));
#pragma unroll
                for (int nf = 0; nf < 4; nf++) {
                    int d = nf * 8 + 2 * t;
                    float2 cc = *(const float2*)&cosT[s * 32 + d];
                    float2 ss = *(const float2*)&sinT[s * 32 + d];
                    float lo0 = acc[mf][nf][2 * half], lo1 = acc[mf][nf][2 * half + 1];
                    float hi0 = acc[mf][nf + 4][2 * half], hi1 = acc[mf][nf + 4][2 * half + 1];
                    __half* Ch = (__half*)C;
                    int c0 = bn0 + wn * 64 + d;
                    *(__half2*)&Ch[row * N + c0] = __floats2half2_rn(
                        (lo0 * cc.x - hi0 * ss.x) * oscale, (lo1 * cc.y - hi1 * ss.y) * oscale);
                    *(__half2*)&Ch[row * N + c0 + 32] = __floats2half2_rn(
                        (hi0 * cc.x + lo0 * ss.x) * oscale, (hi1 * cc.y + lo1 * ss.y) * oscale);
                }
            } else {
#pragma unroll
                for (int nf = 0; nf < 8; nf++) {
                    int c = bn0 + wn * 64 + nf * 8 + 2 * t;
                    if (sizeof(TOut) == 4) {
                        float* Cf = (float*)C;
                        *(float2*)&Cf[row * N + c] =
                            make_float2(acc[mf][nf][2 * half], acc[mf][nf][2 * half + 1]);
                    } else {
                        __half* Ch = (__half*)C;
                        *(__half2*)&Ch[row * N + c] =
                            __floats2half2_rn(acc[mf][nf][2 * half], acc[mf][nf][2 * half + 1]);
                    }
                }
            }
        }
    }
}

// ---------------- fp16 differential flash attention v6 ----------------
// Q pre-scaled by 0.125*log2(e): logits in exp2 domain, softmax uses exp2f.
#define HROW 144
#define QTILE 9216
#define ST_STRIDE 27648
#define ATT_SMEM (4 * QTILE + 2 * ST_STRIDE)   // 92160
#define NKT (SEQ / 64)

__global__ __launch_bounds__(256) void attn_v6_kernel(
    const __half* __restrict__ Q, const __half* __restrict__ K, const __half* __restrict__ V,
    const float* __restrict__ lq1, const float* __restrict__ lk1,
    const float* __restrict__ lq2, const float* __restrict__ lk2,
    const float* __restrict__ lam_init_p,
    const float* __restrict__ gnw, const float* __restrict__ gnb,
    __half* __restrict__ OutH, __half* __restrict__ OutL)
{
    extern __shared__ char smv[];
    const unsigned smBase = (unsigned)__cvta_generic_to_shared(smv);
    const int tid = threadIdx.x, wid = tid >> 5, lane = tid & 31;
    const int br = wid >> 2, mblk = wid & 3;
    const int g = lane >> 2, t = lane & 3;
    const int bh = blockIdx.y, b = bh >> 4, h = bh & 15;
    const int q0 = blockIdx.x * 128;
    const int rowg0 = b * SEQ;
    const int c1base = h * HDIM;

#pragma unroll
    for (int q = 0; q < 4; q++) {
        int fi = tid + q * 256;
        int r = fi >> 3, c = fi & 7;
        const __half* gq = &Q[(size_t)(rowg0 + q0 + r) * QK_COLS + c1base + c * 8];
        cp16(smBase + r * HROW + c * 16, gq);
        cp16(smBase + 2 * QTILE + r * HROW + c * 16, gq + THD);
    }
    auto load_stage = [&](int kt, int stg) {
        const int k0 = kt * 64;
        const unsigned base = smBase + 4 * QTILE + stg * ST_STRIDE;
#pragma unroll
        for (int q = 0; q < 2; q++) {
            int fi = tid + q * 256;
            int r = fi >> 3, c = fi & 7;
            const __half* gk = &K[(size_t)(rowg0 + k0 + r) * QK_COLS + c1base + c * 8];
            cp16(base + r * HROW + c * 16, gk);
            cp16(base + QTILE + r * HROW + c * 16, gk + THD);
            cp16(base + 2 * QTILE + r * HROW + c * 16,
                 &V[(size_t)(rowg0 + k0 + r) * THD + c1base + c * 8]);
        }
    };
    load_stage(0, 0);
    cpcommit();

    const unsigned aoff = (lane & 15) * HROW + (lane >> 4) * 16;
    const unsigned boff = ((lane & 7) + ((lane >> 4) << 3)) * HROW + ((lane >> 3) & 1) * 16;
    const unsigned boffT = (((lane & 7) + (((lane >> 3) & 1) << 3)) * HROW) + (lane >> 4) * 16;
    const unsigned aQw = smBase + br * (2 * QTILE) + mblk * 32 * HROW + aoff;

    float O[2][8][4];
#pragma unroll
    for (int mf = 0; mf < 2; mf++)
#pragma unroll
        for (int df = 0; df < 8; df++)
#pragma unroll
            for (int c = 0; c < 4; c++) O[mf][df][c] = 0.f;
    float mmx[2][2] = {{-1e30f, -1e30f}, {-1e30f, -1e30f}};
    float lsum[2][2] = {{0.f, 0.f}, {0.f, 0.f}};

    for (int kt = 0; kt < NKT; kt++) {
        if (kt + 1 < NKT) { load_stage(kt + 1, (kt + 1) & 1); cpcommit();
            asm volatile("cp.async.wait_group 1;"); }
        else { asm volatile("cp.async.wait_group 0;"); }
        __syncthreads();

        const unsigned stb = smBase + 4 * QTILE + (kt & 1) * ST_STRIDE;
        const unsigned kB = stb + br * QTILE + boff;
        const unsigned vB = stb + 2 * QTILE + boffT;

        float S[2][8][4];
#pragma unroll
        for (int mf = 0; mf < 2; mf++)
#pragma unroll
            for (int nf = 0; nf < 8; nf++)
#pragma unroll
                for (int c = 0; c < 4; c++) S[mf][nf][c] = 0.f;

#pragma unroll
        for (int p = 0; p < 4; p++) {
            unsigned A[2][4];
#pragma unroll
            for (int mf = 0; mf < 2; mf++)
                ldsm4(A[mf][0], A[mf][1], A[mf][2], A[mf][3],
                      aQw + mf * 16 * HROW + p * 32);
#pragma unroll
            for (int nb = 0; nb < 4; nb++) {
                unsigned Bf[4];
                ldsm4(Bf[0], Bf[1], Bf[2], Bf[3], kB + nb * 16 * HROW + p * 32);
#pragma unroll
                for (int mf = 0; mf < 2; mf++) {
                    mma16h(S[mf][2 * nb],     A[mf], Bf[0], Bf[1]);
                    mma16h(S[mf][2 * nb + 1], A[mf], Bf[2], Bf[3]);
                }
            }
        }

        // softmax in exp2 domain (Q pre-scaled by 0.125*log2e)
#pragma unroll
        for (int mf = 0; mf < 2; mf++) {
            float mx0 = -1e30f, mx1 = -1e30f;
#pragma unroll
            for (int nf = 0; nf < 8; nf++) {
                mx0 = fmaxf(mx0, fmaxf(S[mf][nf][0], S[mf][nf][1]));
                mx1 = fmaxf(mx1, fmaxf(S[mf][nf][2], S[mf][nf][3]));
            }
            mx0 = fmaxf(mx0, __shfl_xor_sync(0xffffffffu, mx0, 1));
            mx0 = fmaxf(mx0, __shfl_xor_sync(0xffffffffu, mx0, 2));
            mx1 = fmaxf(mx1, __shfl_xor_sync(0xffffffffu, mx1, 1));
            mx1 = fmaxf(mx1, __shfl_xor_sync(0xffffffffu, mx1, 2));
            float mn0 = fmaxf(mmx[mf][0], mx0);
            float mn1 = fmaxf(mmx[mf][1], mx1);
            float c0 = exp2f(mmx[mf][0] - mn0);
            float c1 = exp2f(mmx[mf][1] - mn1);
            float s0 = 0.f, s1 = 0.f;
#pragma unroll
            for (int nf = 0; nf < 8; nf++) {
                float p00 = exp2f(S[mf][nf][0] - mn0);
                float p01 = exp2f(S[mf][nf][1] - mn0);
                float p10 = exp2f(S[mf][nf][2] - mn1);
                float p11 = exp2f(S[mf][nf][3] - mn1);
                S[mf][nf][0] = p00; S[mf][nf][1] = p01;
                S[mf][nf][2] = p10; S[mf][nf][3] = p11;
                s0 += p00 + p01; s1 += p10 + p11;
            }
            s0 += __shfl_xor_sync(0xffffffffu, s0, 1);
            s0 += __shfl_xor_sync(0xffffffffu, s0, 2);
            s1 += __shfl_xor_sync(0xffffffffu, s1, 1);
            s1 += __shfl_xor_sync(0xffffffffu, s1, 2);
            lsum[mf][0] = lsum[mf][0] * c0 + s0;
            lsum[mf][1] = lsum[mf][1] * c1 + s1;
            mmx[mf][0] = mn0; mmx[mf][1] = mn1;
#pragma unroll
            for (int df = 0; df < 8; df++) {
                O[mf][df][0] *= c0; O[mf][df][1] *= c0;
                O[mf][df][2] *= c1; O[mf][df][3] *= c1;
            }
        }

#pragma unroll
        for (int p = 0; p < 4; p++) {
            unsigned PA[2][4];
#pragma unroll
            for (int mf = 0; mf < 2; mf++) {
                PA[mf][0] = pack2(S[mf][2 * p][0],     S[mf][2 * p][1]);
                PA[mf][1] = pack2(S[mf][2 * p][2],     S[mf][2 * p][3]);
                PA[mf][2] = pack2(S[mf][2 * p + 1][0], S[mf][2 * p + 1][1]);
                PA[mf][3] = pack2(S[mf][2 * p + 1][2], S[mf][2 * p + 1][3]);
            }
#pragma unroll
            for (int nb = 0; nb < 4; nb++) {
                unsigned Bf[4];
                ldsmT4(Bf[0], Bf[1], Bf[2], Bf[3], vB + p * 16 * HROW + nb * 32);
#pragma unroll
                for (int mf = 0; mf < 2; mf++) {
                    mma16h(O[mf][2 * nb],     PA[mf], Bf[0], Bf[1]);
                    mma16h(O[mf][2 * nb + 1], PA[mf], Bf[2], Bf[3]);
                }
            }
        }
        __syncthreads();
    }

    const float lam_init = lam_init_p[0];
    const float lam = __expf(lq1[h] * lk1[h]) - __expf(lq2[h] * lk2[h]) + lam_init;
    const float osc = 1.0f - lam_init;
    float* Ex = (float*)(smv + 4 * QTILE);

    if (br == 1) {
#pragma unroll
        for (int mf = 0; mf < 2; mf++) {
            float inv0 = lam / lsum[mf][0];
            float inv1 = lam / lsum[mf][1];
            int row0 = mblk * 32 + mf * 16 + g;
#pragma unroll
            for (int df = 0; df < 8; df++) {
                int col = df * 8 + 2 * t;
                *(float2*)&Ex[row0 * 68 + col] = make_float2(O[mf][df][0] * inv0, O[mf][df][1] * inv0);
                *(float2*)&Ex[(row0 + 8) * 68 + col] = make_float2(O[mf][df][2] * inv1, O[mf][df][3] * inv1);
            }
        }
    }
    __syncthreads();
    if (br == 0) {
#pragma unroll
        for (int mf = 0; mf < 2; mf++) {
#pragma unroll
            for (int half = 0; half < 2; half++) {
                float inv1 = 1.0f / lsum[mf][half];
                int lrow = mblk * 32 + mf * 16 + g + 8 * half;
                float v[16];
                float s = 0.f, sq = 0.f;
#pragma unroll
                for (int df = 0; df < 8; df++) {
                    float2 e = *(float2*)&Ex[lrow * 68 + df * 8 + 2 * t];
                    float a0 = O[mf][df][half * 2 + 0] * inv1 - e.x;
                    float a1 = O[mf][df][half * 2 + 1] * inv1 - e.y;
                    v[2 * df] = a0; v[2 * df + 1] = a1;
                    s += a0 + a1; sq += a0 * a0 + a1 * a1;
                }
                s  += __shfl_xor_sync(0xffffffffu, s, 1);
                s  += __shfl_xor_sync(0xffffffffu, s, 2);
                sq += __shfl_xor_sync(0xffffffffu, sq, 1);
                sq += __shfl_xor_sync(0xffffffffu, sq, 2);
                float mean = s * (1.0f / 64.0f);
                float var = sq * (1.0f / 64.0f) - mean * mean;
                float istd = rsqrtf(var + GN_EPS);
                size_t grow = (size_t)(rowg0 + q0 + lrow);
#pragma unroll
                for (int df = 0; df < 8; df++) {
                    int col = h * HDIM + df * 8 + 2 * t;
                    float2 gw = *(const float2*)&gnw[col];
                    float2 gb = *(const float2*)&gnb[col];
                    float o0 = ((v[2 * df]     - mean) * istd * gw.x + gb.x) * osc;
                    float o1 = ((v[2 * df + 1] - mean) * istd * gw.y + gb.y) * osc;
                    __half h0 = __float2half_rn(o0);
                    __half h1 = __float2half_rn(o1);
                    __half2 ph; ph.x = h0; ph.y = h1;
                    __half2 pl;
                    pl.x = __float2half_rn(o0 - __half2float(h0));
                    pl.y = __float2half_rn(o1 - __half2float(h1));
                    *(__half2*)&OutH[grow * THD + col] = ph;
                    *(__half2*)&OutL[grow * THD + col] = pl;
                }
            }
        }
    }
}

// ---------------- kernel_launch ----------------
extern "C" void kernel_launch(void* const* d_in, const int* in_sizes, int n_in,
                              void* d_out, int out_size)
{
    const float* x   = (const float*)d_in[0];
    const float* Wq  = (const float*)d_in[1];
    const float* Wk  = (const float*)d_in[2];
    const float* Wv  = (const float*)d_in[3];
    const float* Wo  = (const float*)d_in[4];
    const float* lq1 = (const float*)d_in[5];
    const float* lk1 = (const float*)d_in[6];
    const float* lq2 = (const float*)d_in[7];
    const float* lk2 = (const float*)d_in[8];
    const float* lam = (const float*)d_in[9];
    const float* gnw = (const float*)d_in[10];
    const float* gnb = (const float*)d_in[11];
    float* out = (float*)d_out;

    float *cosT, *sinT;
    __half *Qh, *Kh, *V16, *xh, *xl, *Wq16, *Wk16, *Wv16, *Wo16, *Ah, *Al;
    cudaGetSymbolAddress((void**)&Qh, g_Qh);
    cudaGetSymbolAddress((void**)&Kh, g_Kh);
    cudaGetSymbolAddress((void**)&V16, g_V16);
    cudaGetSymbolAddress((void**)&cosT, g_cosT);
    cudaGetSymbolAddress((void**)&sinT, g_sinT);
    cudaGetSymbolAddress((void**)&xh, g_xh);
    cudaGetSymbolAddress((void**)&xl, g_xl);
    cudaGetSymbolAddress((void**)&Wq16, g_Wq16);
    cudaGetSymbolAddress((void**)&Wk16, g_Wk16);
    cudaGetSymbolAddress((void**)&Wv16, g_Wv16);
    cudaGetSymbolAddress((void**)&Wo16, g_Wo16);
    cudaGetSymbolAddress((void**)&Ah, g_Ah);
    cudaGetSymbolAddress((void**)&Al, g_Al);

    cudaFuncSetAttribute(attn_v6_kernel, cudaFuncAttributeMaxDynamicSharedMemorySize, ATT_SMEM);
    cudaFuncSetAttribute((const void*)gemm_h2_kernel<__half, true, true>,
                         cudaFuncAttributeMaxDynamicSharedMemorySize, GEMM_SMEM);
    cudaFuncSetAttribute((const void*)gemm_h2_kernel<__half, false, false>,
                         cudaFuncAttributeMaxDynamicSharedMemorySize, GEMM_SMEM);
    cudaFuncSetAttribute((const void*)gemm_h2_kernel<float, false, false>,
                         cudaFuncAttributeMaxDynamicSharedMemorySize, GEMM_SMEM);

    rope_tables_kernel<<<(SEQ * 32 + 255) / 256, 256>>>(cosT, sinT);
    split_h_kernel<<<(MROWS * DMODEL + 255) / 256, 256>>>(x, xh, xl, MROWS * DMODEL);
    conv_w_kernel<<<dim3((DMODEL * QK_COLS + 255) / 256, 4), 256>>>(
        Wq, Wk, Wv, Wo, Wq16, Wk16, Wv16, Wo16);

    gemm_h2_kernel<__half, true, true>
        <<<dim3(QK_COLS / 128, MROWS / 128, 2), 256, GEMM_SMEM>>>(
        xh, xl, Wq16, Wk16, Qh, Kh, MROWS, QK_COLS, DMODEL, cosT, sinT);
    gemm_h2_kernel<__half, false, false>
        <<<dim3(THD / 128, MROWS / 128), 256, GEMM_SMEM>>>(
        xh, xl, Wv16, Wv16, V16, V16, MROWS, THD, DMODEL, cosT, sinT);

    attn_v6_kernel<<<dim3(SEQ / 128, BATCH * NHEAD), 256, ATT_SMEM>>>(
        Qh, Kh, V16, lq1, lk1, lq2, lk2, lam, gnw, gnb, Ah, Al);

    gemm_h2_kernel<float, false, false>
        <<<dim3(DMODEL / 128, MROWS / 128), 256, GEMM_SMEM>>>(
        Ah, Al, Wo16, Wo16, out, out, MROWS, DMODEL, THD, cosT, sinT);
}

// round 14
// speedup vs baseline: 3.3830x; 1.0533x over previous
#include <cuda_runtime.h>
#include <cuda_fp16.h>
#include <cstdint>
#include <math.h>

#define BATCH 2
#define SEQ   2048
#define DMODEL 1024
#define NHEAD 16
#define HDIM  64
#define THD   (NHEAD * HDIM)
#define MROWS (BATCH * SEQ)
#define QK_COLS (2 * THD)
#define GN_EPS 1e-5f
#define QSCALE_F 0.18033688f   // 0.125 * log2(e)
#define ONES16 0x3C003C00u     // half2(1.0, 1.0)

// ---------------- scratch ----------------
__device__ __half g_Qh[MROWS * QK_COLS];
__device__ __half g_Kh[MROWS * QK_COLS];
__device__ __half g_V16[MROWS * THD];
__device__ float g_cosT[SEQ * 32];
__device__ float g_sinT[SEQ * 32];
__device__ __half g_xh[MROWS * DMODEL],  g_xl[MROWS * DMODEL];
__device__ __half g_Wq16[DMODEL * QK_COLS];
__device__ __half g_Wk16[DMODEL * QK_COLS];
__device__ __half g_Wv16[DMODEL * THD];
__device__ __half g_Wo16[THD * DMODEL];
__device__ __half g_Ah[MROWS * THD], g_Al[MROWS * THD];

// ---------------- helpers ----------------
__device__ __forceinline__ void ldsm4(unsigned &r0, unsigned &r1, unsigned &r2, unsigned &r3, unsigned a) {
    asm volatile("ldmatrix.sync.aligned.m8n8.x4.shared.b16 {%0,%1,%2,%3}, [%4];"
        : "=r"(r0), "=r"(r1), "=r"(r2), "=r"(r3) : "r"(a));
}
__device__ __forceinline__ void ldsmT4(unsigned &r0, unsigned &r1, unsigned &r2, unsigned &r3, unsigned a) {
    asm volatile("ldmatrix.sync.aligned.m8n8.x4.trans.shared.b16 {%0,%1,%2,%3}, [%4];"
        : "=r"(r0), "=r"(r1), "=r"(r2), "=r"(r3) : "r"(a));
}
__device__ __forceinline__ void mma16h(float* c, const unsigned* a, unsigned b0, unsigned b1) {
    asm volatile("mma.sync.aligned.m16n8k16.row.col.f32.f16.f16.f32 "
        "{%0,%1,%2,%3},{%4,%5,%6,%7},{%8,%9},{%0,%1,%2,%3};"
        : "+f"(c[0]), "+f"(c[1]), "+f"(c[2]), "+f"(c[3])
        : "r"(a[0]), "r"(a[1]), "r"(a[2]), "r"(a[3]), "r"(b0), "r"(b1));
}
__device__ __forceinline__ void cp16(unsigned s, const void* g) {
    asm volatile("cp.async.cg.shared.global [%0], [%1], 16;" :: "r"(s), "l"(g));
}
__device__ __forceinline__ void cpcommit() { asm volatile("cp.async.commit_group;"); }
__device__ __forceinline__ unsigned h2exp2(unsigned x) {
    unsigned r;
    asm("ex2.approx.f16x2 %0, %1;" : "=r"(r) : "r"(x));
    return r;
}
__device__ __forceinline__ unsigned packsub(float a, float b, float m) {
    __half2 h = __floats2half2_rn(a - m, b - m);
    return *(unsigned*)&h;
}

// ---------------- small kernels ----------------
__global__ void split_h_kernel(const float* __restrict__ s, __half* __restrict__ h,
                               __half* __restrict__ l, int n) {
    int i = blockIdx.x * blockDim.x + threadIdx.x;
    if (i >= n) return;
    float v = s[i];
    __half hv = __float2half_rn(v);
    h[i] = hv;
    l[i] = __float2half_rn(v - __half2float(hv));
}

__global__ void conv_w_kernel(const float* __restrict__ Wq, const float* __restrict__ Wk,
                              const float* __restrict__ Wv, const float* __restrict__ Wo,
                              __half* __restrict__ q16, __half* __restrict__ k16,
                              __half* __restrict__ v16, __half* __restrict__ o16) {
    int which = blockIdx.y;
    const float* s;
    __half* d;
    int n;
    if (which == 0)      { s = Wq; d = q16; n = DMODEL * QK_COLS; }
    else if (which == 1) { s = Wk; d = k16; n = DMODEL * QK_COLS; }
    else if (which == 2) { s = Wv; d = v16; n = DMODEL * THD; }
    else                 { s = Wo; d = o16; n = THD * DMODEL; }
    int i = blockIdx.x * blockDim.x + threadIdx.x;
    if (i < n) d[i] = __float2half_rn(s[i]);
}

__global__ void rope_tables_kernel(float* __restrict__ cosT, float* __restrict__ sinT) {
    int i = blockIdx.x * blockDim.x + threadIdx.x;
    if (i >= SEQ * 32) return;
    int t = i >> 5, j = i & 31;
    double invf = pow(10000.0, -(double)(2 * j) / 64.0);
    float f = (float)t * (float)invf;
    cosT[i] = (float)cos((double)f);
    sinT[i] = (float)sin((double)f);
}

// ---------------- GEMM common tile geometry (BK=64, 2-stage) ----------------
#define GA_ST 72
#define GB_ST 136
#define O_AH 0
#define O_AL (128 * GA_ST)
#define O_B  (2 * 128 * GA_ST)
#define STG_EL (O_B + 64 * GB_ST)          // 27136 halves
#define GEMM_SMEM (2 * STG_EL * 2)         // 108544 B

// ---------------- merged QKV projection GEMM (grid.z: 0=Q,1=K,2=V) ----------------
__global__ __launch_bounds__(256) void gemm_qkv_kernel(
    const __half* __restrict__ Ah, const __half* __restrict__ Al,
    const __half* __restrict__ Wq, const __half* __restrict__ Wk, const __half* __restrict__ Wv,
    __half* __restrict__ Qo, __half* __restrict__ Ko, __half* __restrict__ Vo,
    const float* __restrict__ cosT, const float* __restrict__ sinT)
{
    const int z = blockIdx.z;
    if (z == 2 && blockIdx.x >= THD / 128) return;
    const int N = (z == 2) ? THD : QK_COLS;
    const int K = DMODEL;
    const __half* B = (z == 0) ? Wq : (z == 1) ? Wk : Wv;
    __half* C = (z == 0) ? Qo : (z == 1) ? Ko : Vo;
    const float oscale = (z == 0) ? QSCALE_F : 1.0f;

    extern __shared__ __half smb[];
    const unsigned smB = (unsigned)__cvta_generic_to_shared(smb);
    const int tid = threadIdx.x, wid = tid >> 5, lane = tid & 31;
    const int wm = wid & 3, wn = wid >> 2;
    const int g = lane >> 2, t = lane & 3;
    const int bm0 = blockIdx.y * 128, bn0 = blockIdx.x * 128;

    float acc[2][8][4];
#pragma unroll
    for (int i = 0; i < 2; i++)
#pragma unroll
        for (int j = 0; j < 8; j++)
#pragma unroll
            for (int c = 0; c < 4; c++) acc[i][j][c] = 0.f;

    auto load_stage = [&](int kt, int stg) {
        const int k0 = kt * 64;
        const unsigned sb = smB + stg * (STG_EL * 2);
#pragma unroll
        for (int q = 0; q < 8; q++) {
            int fi = tid + q * 256;
            int u = fi >> 10, idx = fi & 1023;
            int r = idx >> 3, c = (idx & 7) * 8;
            cp16(sb + ((u ? O_AL : O_AH) + r * GA_ST + c) * 2,
                 (u ? Al : Ah) + (size_t)(bm0 + r) * K + k0 + c);
        }
#pragma unroll
        for (int q = 0; q < 4; q++) {
            int fi = tid + q * 256;
            int r = fi >> 4, c = (fi & 15) * 8;
            cp16(sb + (O_B + r * GB_ST + c) * 2,
                 B + (size_t)(k0 + r) * N + bn0 + c);
        }
        cpcommit();
    };
    const int NT = K >> 6;
    load_stage(0, 0);

    const unsigned aoff = ((lane & 15) * GA_ST + (lane >> 4) * 8) * 2;
    const unsigned boff = (((((lane >> 3) & 1) * 8) + (lane & 7)) * GB_ST + (lane >> 4) * 8) * 2;

    for (int kt = 0; kt < NT; kt++) {
        asm volatile("cp.async.wait_group 0;");
        __syncthreads();
        if (kt + 1 < NT) load_stage(kt + 1, (kt + 1) & 1);

        const unsigned sb = smB + (kt & 1) * (STG_EL * 2);
#pragma unroll
        for (int ks = 0; ks < 4; ks++) {
            unsigned AH[2][4], AL[2][4];
#pragma unroll
            for (int mf = 0; mf < 2; mf++) {
                unsigned a = sb + (wm * 32 + mf * 16) * GA_ST * 2 + aoff + ks * 32;
                ldsm4(AH[mf][0], AH[mf][1], AH[mf][2], AH[mf][3], a + O_AH * 2);
                ldsm4(AL[mf][0], AL[mf][1], AL[mf][2], AL[mf][3], a + O_AL * 2);
            }
#pragma unroll
            for (int np = 0; np < 4; np++) {
                unsigned bofs = sb + boff + ks * 16 * GB_ST * 2 + O_B * 2 + (wn * 64 + np * 16) * 2;
                unsigned TB[4];
                ldsmT4(TB[0], TB[1], TB[2], TB[3], bofs);
#pragma unroll
                for (int hh = 0; hh < 2; hh++) {
                    int nf = np * 2 + hh;
#pragma unroll
                    for (int mf = 0; mf < 2; mf++) {
                        mma16h(acc[mf][nf], AH[mf], TB[2 * hh], TB[2 * hh + 1]);
                        mma16h(acc[mf][nf], AL[mf], TB[2 * hh], TB[2 * hh + 1]);
                    }
                }
            }
        }
    }

#pragma unroll
    for (int mf = 0; mf < 2; mf++) {
#pragma unroll
        for (int half = 0; half < 2; half++) {
            size_t row = (size_t)(bm0 + wm * 32 + mf * 16 + g + 8 * half);
            if (z < 2) {
                int s = (int)(row & (SEQ - 1));
#pragma unroll
                for (int nf = 0; nf < 4; nf++) {
                    int d = nf * 8 + 2 * t;
                    float2 cc = *(const float2*)&cosT[s * 32 + d];
                    float2 ss = *(const float2*)&sinT[s * 32 + d];
                    float lo0 = acc[mf][nf][2 * half], lo1 = acc[mf][nf][2 * half + 1];
                    float hi0 = acc[mf][nf + 4][2 * half], hi1 = acc[mf][nf + 4][2 * half + 1];
                    int c0 = bn0 + wn * 64 + d;
                    *(__half2*)&C[row * N + c0] = __floats2half2_rn(
                        (lo0 * cc.x - hi0 * ss.x) * oscale, (lo1 * cc.y - hi1 * ss.y) * oscale);
                    *(__half2*)&C[row * N + c0 + 32] = __floats2half2_rn(
                        (hi0 * cc.x + lo0 * ss.x) * oscale, (hi1 * cc.y + lo1 * ss.y) * oscale);
                }
            } else {
#pragma unroll
                for (int nf = 0; nf < 8; nf++) {
                    int c = bn0 + wn * 64 + nf * 8 + 2 * t;
                    *(__half2*)&C[row * N + c] =
                        __floats2half2_rn(acc[mf][nf][2 * half], acc[mf][nf][2 * half + 1]);
                }
            }
        }
    }
}

// ---------------- Wo GEMM (f32 out) ----------------
__global__ __launch_bounds__(256) void gemm_o_kernel(
    const __half* __restrict__ Ah, const __half* __restrict__ Al,
    const __half* __restrict__ B, float* __restrict__ C, int M, int N, int K)
{
    extern __shared__ __half smb[];
    const unsigned smB = (unsigned)__cvta_generic_to_shared(smb);
    const int tid = threadIdx.x, wid = tid >> 5, lane = tid & 31;
    const int wm = wid & 3, wn = wid >> 2;
    const int g = lane >> 2, t = lane & 3;
    const int bm0 = blockIdx.y * 128, bn0 = blockIdx.x * 128;

    float acc[2][8][4];
#pragma unroll
    for (int i = 0; i < 2; i++)
#pragma unroll
        for (int j = 0; j < 8; j++)
#pragma unroll
            for (int c = 0; c < 4; c++) acc[i][j][c] = 0.f;

    auto load_stage = [&](int kt, int stg) {
        const int k0 = kt * 64;
        const unsigned sb = smB + stg * (STG_EL * 2);
#pragma unroll
        for (int q = 0; q < 8; q++) {
            int fi = tid + q * 256;
            int u = fi >> 10, idx = fi & 1023;
            int r = idx >> 3, c = (idx & 7) * 8;
            cp16(sb + ((u ? O_AL : O_AH) + r * GA_ST + c) * 2,
                 (u ? Al : Ah) + (size_t)(bm0 + r) * K + k0 + c);
        }
#pragma unroll
        for (int q = 0; q < 4; q++) {
            int fi = tid + q * 256;
            int r = fi >> 4, c = (fi & 15) * 8;
            cp16(sb + (O_B + r * GB_ST + c) * 2,
                 B + (size_t)(k0 + r) * N + bn0 + c);
        }
        cpcommit();
    };
    const int NT = K >> 6;
    load_stage(0, 0);

    const unsigned aoff = ((lane & 15) * GA_ST + (lane >> 4) * 8) * 2;
    const unsigned boff = (((((lane >> 3) & 1) * 8) + (lane & 7)) * GB_ST + (lane >> 4) * 8) * 2;

    for (int kt = 0; kt < NT; kt++) {
        asm volatile("cp.async.wait_group 0;");
        __syncthreads();
        if (kt + 1 < NT) load_stage(kt + 1, (kt + 1) & 1);

        const unsigned sb = smB + (kt & 1) * (STG_EL * 2);
#pragma unroll
        for (int ks = 0; ks < 4; ks++) {
            unsigned AH[2][4], AL[2][4];
#pragma unroll
            for (int mf = 0; mf < 2; mf++) {
                unsigned a = sb + (wm * 32 + mf * 16) * GA_ST * 2 + aoff + ks * 32;
                ldsm4(AH[mf][0], AH[mf][1], AH[mf][2], AH[mf][3], a + O_AH * 2);
                ldsm4(AL[mf][0], AL[mf][1], AL[mf][2], AL[mf][3], a + O_AL * 2);
            }
#pragma unroll
            for (int np = 0; np < 4; np++) {
                unsigned bofs = sb + boff + ks * 16 * GB_ST * 2 + O_B * 2 + (wn * 64 + np * 16) * 2;
                unsigned TB[4];
                ldsmT4(TB[0], TB[1], TB[2], TB[3], bofs);
#pragma unroll
                for (int hh = 0; hh < 2; hh++) {
                    int nf = np * 2 + hh;
#pragma unroll
                    for (int mf = 0; mf < 2; mf++) {
                        mma16h(acc[mf][nf], AH[mf], TB[2 * hh], TB[2 * hh + 1]);
                        mma16h(acc[mf][nf], AL[mf], TB[2 * hh], TB[2 * hh + 1]);
                    }
                }
            }
        }
    }

#pragma unroll
    for (int mf = 0; mf < 2; mf++) {
        size_t r0 = (size_t)(bm0 + wm * 32 + mf * 16 + g);
#pragma unroll
        for (int nf = 0; nf < 8; nf++) {
            int c = bn0 + wn * 64 + nf * 8 + 2 * t;
            *(float2*)&C[r0 * N + c]       = make_float2(acc[mf][nf][0], acc[mf][nf][1]);
            *(float2*)&C[(r0 + 8) * N + c] = make_float2(acc[mf][nf][2], acc[mf][nf][3]);
        }
    }
}

// ---------------- fp16 differential flash attention v7 ----------------
// exp2-domain softmax with f16x2 MUFU; lsum via MMA against ones-fragment.
#define HROW 144
#define QTILE 9216
#define ST_STRIDE 27648
#define ATT_SMEM (4 * QTILE + 2 * ST_STRIDE)   // 92160
#define NKT (SEQ / 64)

__global__ __launch_bounds__(256) void attn_v7_kernel(
    const __half* __restrict__ Q, const __half* __restrict__ K, const __half* __restrict__ V,
    const float* __restrict__ lq1, const float* __restrict__ lk1,
    const float* __restrict__ lq2, const float* __restrict__ lk2,
    const float* __restrict__ lam_init_p,
    const float* __restrict__ gnw, const float* __restrict__ gnb,
    __half* __restrict__ OutH, __half* __restrict__ OutL)
{
    extern __shared__ char smv[];
    const unsigned smBase = (unsigned)__cvta_generic_to_shared(smv);
    const int tid = threadIdx.x, wid = tid >> 5, lane = tid & 31;
    const int br = wid >> 2, mblk = wid & 3;
    const int g = lane >> 2, t = lane & 3;
    const int bh = blockIdx.y, b = bh >> 4, h = bh & 15;
    const int q0 = blockIdx.x * 128;
    const int rowg0 = b * SEQ;
    const int c1base = h * HDIM;

#pragma unroll
    for (int q = 0; q < 4; q++) {
        int fi = tid + q * 256;
        int r = fi >> 3, c = fi & 7;
        const __half* gq = &Q[(size_t)(rowg0 + q0 + r) * QK_COLS + c1base + c * 8];
        cp16(smBase + r * HROW + c * 16, gq);
        cp16(smBase + 2 * QTILE + r * HROW + c * 16, gq + THD);
    }
    auto load_stage = [&](int kt, int stg) {
        const int k0 = kt * 64;
        const unsigned base = smBase + 4 * QTILE + stg * ST_STRIDE;
#pragma unroll
        for (int q = 0; q < 2; q++) {
            int fi = tid + q * 256;
            int r = fi >> 3, c = fi & 7;
            const __half* gk = &K[(size_t)(rowg0 + k0 + r) * QK_COLS + c1base + c * 8];
            cp16(base + r * HROW + c * 16, gk);
            cp16(base + QTILE + r * HROW + c * 16, gk + THD);
            cp16(base + 2 * QTILE + r * HROW + c * 16,
                 &V[(size_t)(rowg0 + k0 + r) * THD + c1base + c * 8]);
        }
    };
    load_stage(0, 0);
    cpcommit();

    const unsigned aoff = (lane & 15) * HROW + (lane >> 4) * 16;
    const unsigned boff = ((lane & 7) + ((lane >> 4) << 3)) * HROW + ((lane >> 3) & 1) * 16;
    const unsigned boffT = (((lane & 7) + (((lane >> 3) & 1) << 3)) * HROW) + (lane >> 4) * 16;
    const unsigned aQw = smBase + br * (2 * QTILE) + mblk * 32 * HROW + aoff;

    float O[2][8][4];
#pragma unroll
    for (int mf = 0; mf < 2; mf++)
#pragma unroll
        for (int df = 0; df < 8; df++)
#pragma unroll
            for (int c = 0; c < 4; c++) O[mf][df][c] = 0.f;
    float mmx[2][2] = {{-1e30f, -1e30f}, {-1e30f, -1e30f}};
    float lsA[2][4] = {{0.f, 0.f, 0.f, 0.f}, {0.f, 0.f, 0.f, 0.f}};

    for (int kt = 0; kt < NKT; kt++) {
        if (kt + 1 < NKT) { load_stage(kt + 1, (kt + 1) & 1); cpcommit();
            asm volatile("cp.async.wait_group 1;"); }
        else { asm volatile("cp.async.wait_group 0;"); }
        __syncthreads();

        const unsigned stb = smBase + 4 * QTILE + (kt & 1) * ST_STRIDE;
        const unsigned kB = stb + br * QTILE + boff;
        const unsigned vB = stb + 2 * QTILE + boffT;

        float S[2][8][4];
#pragma unroll
        for (int mf = 0; mf < 2; mf++)
#pragma unroll
            for (int nf = 0; nf < 8; nf++)
#pragma unroll
                for (int c = 0; c < 4; c++) S[mf][nf][c] = 0.f;

#pragma unroll
        for (int p = 0; p < 4; p++) {
            unsigned A[2][4];
#pragma unroll
            for (int mf = 0; mf < 2; mf++)
                ldsm4(A[mf][0], A[mf][1], A[mf][2], A[mf][3],
                      aQw + mf * 16 * HROW + p * 32);
#pragma unroll
            for (int nb = 0; nb < 4; nb++) {
                unsigned Bf[4];
                ldsm4(Bf[0], Bf[1], Bf[2], Bf[3], kB + nb * 16 * HROW + p * 32);
#pragma unroll
                for (int mf = 0; mf < 2; mf++) {
                    mma16h(S[mf][2 * nb],     A[mf], Bf[0], Bf[1]);
                    mma16h(S[mf][2 * nb + 1], A[mf], Bf[2], Bf[3]);
                }
            }
        }

        // exp2-domain softmax: P computed via f16x2 MUFU; lsum via ones-MMA below
        unsigned P2[2][8][2];
#pragma unroll
        for (int mf = 0; mf < 2; mf++) {
            float mx0 = -1e30f, mx1 = -1e30f;
#pragma unroll
            for (int nf = 0; nf < 8; nf++) {
                mx0 = fmaxf(mx0, fmaxf(S[mf][nf][0], S[mf][nf][1]));
                mx1 = fmaxf(mx1, fmaxf(S[mf][nf][2], S[mf][nf][3]));
            }
            mx0 = fmaxf(mx0, __shfl_xor_sync(0xffffffffu, mx0, 1));
            mx0 = fmaxf(mx0, __shfl_xor_sync(0xffffffffu, mx0, 2));
            mx1 = fmaxf(mx1, __shfl_xor_sync(0xffffffffu, mx1, 1));
            mx1 = fmaxf(mx1, __shfl_xor_sync(0xffffffffu, mx1, 2));
            float mn0 = fmaxf(mmx[mf][0], mx0);
            float mn1 = fmaxf(mmx[mf][1], mx1);
            float c0 = exp2f(mmx[mf][0] - mn0);
            float c1 = exp2f(mmx[mf][1] - mn1);
            mmx[mf][0] = mn0; mmx[mf][1] = mn1;
            lsA[mf][0] *= c0; lsA[mf][1] *= c0;
            lsA[mf][2] *= c1; lsA[mf][3] *= c1;
#pragma unroll
            for (int nf = 0; nf < 8; nf++) {
                P2[mf][nf][0] = h2exp2(packsub(S[mf][nf][0], S[mf][nf][1], mn0));
                P2[mf][nf][1] = h2exp2(packsub(S[mf][nf][2], S[mf][nf][3], mn1));
            }
#pragma unroll
            for (int df = 0; df < 8; df++) {
                O[mf][df][0] *= c0; O[mf][df][1] *= c0;
                O[mf][df][2] *= c1; O[mf][df][3] *= c1;
            }
        }

#pragma unroll
        for (int p = 0; p < 4; p++) {
            unsigned PA[2][4];
#pragma unroll
            for (int mf = 0; mf < 2; mf++) {
                PA[mf][0] = P2[mf][2 * p][0];
                PA[mf][1] = P2[mf][2 * p][1];
                PA[mf][2] = P2[mf][2 * p + 1][0];
                PA[mf][3] = P2[mf][2 * p + 1][1];
                mma16h(lsA[mf], PA[mf], ONES16, ONES16);   // row-sums into lsA
            }
#pragma unroll
            for (int nb = 0; nb < 4; nb++) {
                unsigned Bf[4];
                ldsmT4(Bf[0], Bf[1], Bf[2], Bf[3], vB + p * 16 * HROW + nb * 32);
#pragma unroll
                for (int mf = 0; mf < 2; mf++) {
                    mma16h(O[mf][2 * nb],     PA[mf], Bf[0], Bf[1]);
                    mma16h(O[mf][2 * nb + 1], PA[mf], Bf[2], Bf[3]);
                }
            }
        }
        __syncthreads();
    }

    const float lam_init = lam_init_p[0];
    const float lam = __expf(lq1[h] * lk1[h]) - __expf(lq2[h] * lk2[h]) + lam_init;
    const float osc = 1.0f - lam_init;
    float* Ex = (float*)(smv + 4 * QTILE);

    if (br == 1) {
#pragma unroll
        for (int mf = 0; mf < 2; mf++) {
            float inv0 = lam / lsA[mf][0];
            float inv1 = lam / lsA[mf][2];
            int row0 = mblk * 32 + mf * 16 + g;
#pragma unroll
            for (int df = 0; df < 8; df++) {
                int col = df * 8 + 2 * t;
                *(float2*)&Ex[row0 * 68 + col] = make_float2(O[mf][df][0] * inv0, O[mf][df][1] * inv0);
                *(float2*)&Ex[(row0 + 8) * 68 + col] = make_float2(O[mf][df][2] * inv1, O[mf][df][3] * inv1);
            }
        }
    }
    __syncthreads();
    if (br == 0) {
#pragma unroll
        for (int mf = 0; mf < 2; mf++) {
#pragma unroll
            for (int half = 0; half < 2; half++) {
                float inv1 = 1.0f / lsA[mf][2 * half];
                int lrow = mblk * 32 + mf * 16 + g + 8 * half;
                float v[16];
                float s = 0.f, sq = 0.f;
#pragma unroll
                for (int df = 0; df < 8; df++) {
                    float2 e = *(float2*)&Ex[lrow * 68 + df * 8 + 2 * t];
                    float a0 = O[mf][df][half * 2 + 0] * inv1 - e.x;
                    float a1 = O[mf][df][half * 2 + 1] * inv1 - e.y;
                    v[2 * df] = a0; v[2 * df + 1] = a1;
                    s += a0 + a1; sq += a0 * a0 + a1 * a1;
                }
                s  += __shfl_xor_sync(0xffffffffu, s, 1);
                s  += __shfl_xor_sync(0xffffffffu, s, 2);
                sq += __shfl_xor_sync(0xffffffffu, sq, 1);
                sq += __shfl_xor_sync(0xffffffffu, sq, 2);
                float mean = s * (1.0f / 64.0f);
                float var = sq * (1.0f / 64.0f) - mean * mean;
                float istd = rsqrtf(var + GN_EPS);
                size_t grow = (size_t)(rowg0 + q0 + lrow);
#pragma unroll
                for (int df = 0; df < 8; df++) {
                    int col = h * HDIM + df * 8 + 2 * t;
                    float2 gw = *(const float2*)&gnw[col];
                    float2 gb = *(const float2*)&gnb[col];
                    float o0 = ((v[2 * df]     - mean) * istd * gw.x + gb.x) * osc;
                    float o1 = ((v[2 * df + 1] - mean) * istd * gw.y + gb.y) * osc;
                    __half h0 = __float2half_rn(o0);
                    __half h1 = __float2half_rn(o1);
                    __half2 ph; ph.x = h0; ph.y = h1;
                    __half2 pl;
                    pl.x = __float2half_rn(o0 - __half2float(h0));
                    pl.y = __float2half_rn(o1 - __half2float(h1));
                    *(__half2*)&OutH[grow * THD + col] = ph;
                    *(__half2*)&OutL[grow * THD + col] = pl;
                }
            }
        }
    }
}

// ---------------- kernel_launch ----------------
extern "C" void kernel_launch(void* const* d_in, const int* in_sizes, int n_in,
                              void* d_out, int out_size)
{
    const float* x   = (const float*)d_in[0];
    const float* Wq  = (const float*)d_in[1];
    const float* Wk  = (const float*)d_in[2];
    const float* Wv  = (const float*)d_in[3];
    const float* Wo  = (const float*)d_in[4];
    const float* lq1 = (const float*)d_in[5];
    const float* lk1 = (const float*)d_in[6];
    const float* lq2 = (const float*)d_in[7];
    const float* lk2 = (const float*)d_in[8];
    const float* lam = (const float*)d_in[9];
    const float* gnw = (const float*)d_in[10];
    const float* gnb = (const float*)d_in[11];
    float* out = (float*)d_out;

    float *cosT, *sinT;
    __half *Qh, *Kh, *V16, *xh, *xl, *Wq16, *Wk16, *Wv16, *Wo16, *Ah, *Al;
    cudaGetSymbolAddress((void**)&Qh, g_Qh);
    cudaGetSymbolAddress((void**)&Kh, g_Kh);
    cudaGetSymbolAddress((void**)&V16, g_V16);
    cudaGetSymbolAddress((void**)&cosT, g_cosT);
    cudaGetSymbolAddress((void**)&sinT, g_sinT);
    cudaGetSymbolAddress((void**)&xh, g_xh);
    cudaGetSymbolAddress((void**)&xl, g_xl);
    cudaGetSymbolAddress((void**)&Wq16, g_Wq16);
    cudaGetSymbolAddress((void**)&Wk16, g_Wk16);
    cudaGetSymbolAddress((void**)&Wv16, g_Wv16);
    cudaGetSymbolAddress((void**)&Wo16, g_Wo16);
    cudaGetSymbolAddress((void**)&Ah, g_Ah);
    cudaGetSymbolAddress((void**)&Al, g_Al);

    cudaFuncSetAttribute(attn_v7_kernel, cudaFuncAttributeMaxDynamicSharedMemorySize, ATT_SMEM);
    cudaFuncSetAttribute(gemm_qkv_kernel, cudaFuncAttributeMaxDynamicSharedMemorySize, GEMM_SMEM);
    cudaFuncSetAttribute(gemm_o_kernel, cudaFuncAttributeMaxDynamicSharedMemorySize, GEMM_SMEM);

    rope_tables_kernel<<<(SEQ * 32 + 255) / 256, 256>>>(cosT, sinT);
    split_h_kernel<<<(MROWS * DMODEL + 255) / 256, 256>>>(x, xh, xl, MROWS * DMODEL);
    conv_w_kernel<<<dim3((DMODEL * QK_COLS + 255) / 256, 4), 256>>>(
        Wq, Wk, Wv, Wo, Wq16, Wk16, Wv16, Wo16);

    // Q, K, V projections in ONE launch (z selects; RoPE fused for z<2)
    gemm_qkv_kernel<<<dim3(QK_COLS / 128, MROWS / 128, 3), 256, GEMM_SMEM>>>(
        xh, xl, Wq16, Wk16, Wv16, Qh, Kh, V16, cosT, sinT);

    attn_v7_kernel<<<dim3(SEQ / 128, BATCH * NHEAD), 256, ATT_SMEM>>>(
        Qh, Kh, V16, lq1, lk1, lq2, lk2, lam, gnw, gnb, Ah, Al);

    gemm_o_kernel<<<dim3(DMODEL / 128, MROWS / 128), 256, GEMM_SMEM>>>(
        Ah, Al, Wo16, out, MROWS, DMODEL, THD);
}